// round 2
// baseline (speedup 1.0000x reference)
#include <cuda_runtime.h>

#define NNODES 100000
#define NEDGES 1600000
#define NGRAPH 512
#define RDIM   6656
#define RD4    (RDIM/4)

// ---- static device scratch (no allocations allowed) ----
static __device__ __align__(16) float g_aggr[NNODES * 256];
static __device__ __align__(16) float g_tmp [NNODES * 256];   // also reused as [512 x 3328] mid
static __device__ __align__(16) float g_h   [NNODES * 256];
static __device__ __align__(16) float g_pool[NGRAPH * RDIM];

// ---------------------------------------------------------------------------
// pool_init: pool[:, 0:512] = 0 ; pool[:, 512:6656] = fingerprint
// ---------------------------------------------------------------------------
__global__ void pool_init_kernel(const float* __restrict__ fp, float* __restrict__ pool) {
    int col = blockIdx.x * blockDim.x + threadIdx.x;
    int row = blockIdx.y;
    if (col >= RDIM) return;
    float v = 0.0f;
    if (col >= 512) v = fp[row * 6144 + (col - 512)];
    pool[row * RDIM + col] = v;
}

// ---------------------------------------------------------------------------
// copy (float4) : aggr = x   (fuses the "+x" of GINConv, scatter adds on top)
// ---------------------------------------------------------------------------
__global__ void copy_f4_kernel(const float4* __restrict__ src, float4* __restrict__ dst, int n4) {
    int i = blockIdx.x * blockDim.x + threadIdx.x;
    if (i < n4) dst[i] = src[i];
}

// ---------------------------------------------------------------------------
// scatter_add: aggr[dst] += feat[src] over all edges, float4 vector reductions
// F4S = log2(F/4):  F=64 -> 4, F=128 -> 5, F=256 -> 6
// ---------------------------------------------------------------------------
template<int F4S>
__global__ void scatter_add_kernel(const float4* __restrict__ feat,
                                   const int* __restrict__ esrc,
                                   const int* __restrict__ edst,
                                   float4* __restrict__ aggr) {
    int idx = blockIdx.x * blockDim.x + threadIdx.x;
    int e = idx >> F4S;
    if (e >= NEDGES) return;
    int c = idx & ((1 << F4S) - 1);
    int s = __ldg(esrc + e);
    int d = __ldg(edst + e);
    float4 v = __ldg(&feat[(s << F4S) + c]);
    float* p = (float*)(aggr + (d << F4S) + c);
    asm volatile("red.global.add.v4.f32 [%0], {%1, %2, %3, %4};"
                 :: "l"(p), "f"(v.x), "f"(v.y), "f"(v.z), "f"(v.w) : "memory");
}

// ---------------------------------------------------------------------------
// pool_add: pool[batch[i], off + :F] += feat[i, :F]
// ---------------------------------------------------------------------------
__global__ void pool_add_kernel(const float4* __restrict__ feat,
                                const int* __restrict__ batch,
                                float4* __restrict__ pool,
                                int off4, int f4shift) {
    int idx = blockIdx.x * blockDim.x + threadIdx.x;
    int i = idx >> f4shift;
    if (i >= NNODES) return;
    int c = idx & ((1 << f4shift) - 1);
    int g = __ldg(batch + i);
    float4 v = __ldg(&feat[(i << f4shift) + c]);
    float* p = (float*)(pool + g * RD4 + off4 + c);
    asm volatile("red.global.add.v4.f32 [%0], {%1, %2, %3, %4};"
                 :: "l"(p), "f"(v.x), "f"(v.y), "f"(v.z), "f"(v.w) : "memory");
}

// ---------------------------------------------------------------------------
// SGEMM: C[M,Nn] = epi(A[M,K] @ B[K,Nn] + bias)
// BM=BN=128, BK=8, 256 threads, 8x8 per thread.
// Requires: Nn % 128 == 0, K % 8 == 0. M bounds handled.
// EPI: 0 = +bias, 1 = relu(+bias), 2 = relu(bn(+bias))   (eval-mode BN, mean=0 var=1)
// ---------------------------------------------------------------------------
template<int EPI>
__global__ __launch_bounds__(256) void sgemm_kernel(
    int M, int Nn, int K,
    const float* __restrict__ A, const float* __restrict__ B,
    const float* __restrict__ bias,
    const float* __restrict__ bng, const float* __restrict__ bnb,
    float* __restrict__ C)
{
    __shared__ float As[8][128];
    __shared__ float Bs[8][128];

    const int tid = threadIdx.x;
    const int bx = blockIdx.x;
    const int by = blockIdx.y;

    const int trow = (tid >> 4) << 3;       // 0..120 step 8
    const int tcol = (tid & 15) << 3;       // 0..120 step 8

    // A-tile load mapping: 128 rows x 8 cols, one float4 per thread
    const int arow = tid >> 1;              // 0..127
    const int acol = (tid & 1) << 2;        // 0 or 4
    // B-tile load mapping: 8 rows x 128 cols, one float4 per thread
    const int brow = tid >> 5;              // 0..7
    const int bcol = (tid & 31) << 2;       // 0..124 step 4

    const int gArow = by * 128 + arow;
    const bool aok = (gArow < M);
    const float* Aptr = A + (long long)gArow * K + acol;
    const float* Bptr = B + (long long)brow * Nn + bx * 128 + bcol;

    float acc[8][8];
    #pragma unroll
    for (int i = 0; i < 8; i++)
        #pragma unroll
        for (int j = 0; j < 8; j++) acc[i][j] = 0.0f;

    for (int kk = 0; kk < K; kk += 8) {
        float4 av = aok ? *(const float4*)(Aptr + kk) : make_float4(0.f, 0.f, 0.f, 0.f);
        As[acol + 0][arow] = av.x;
        As[acol + 1][arow] = av.y;
        As[acol + 2][arow] = av.z;
        As[acol + 3][arow] = av.w;
        *(float4*)&Bs[brow][bcol] = *(const float4*)(Bptr + (long long)kk * Nn);
        __syncthreads();

        #pragma unroll
        for (int k = 0; k < 8; k++) {
            float a[8], b[8];
            #pragma unroll
            for (int i = 0; i < 8; i++) a[i] = As[k][trow + i];
            #pragma unroll
            for (int j = 0; j < 8; j++) b[j] = Bs[k][tcol + j];
            #pragma unroll
            for (int i = 0; i < 8; i++)
                #pragma unroll
                for (int j = 0; j < 8; j++)
                    acc[i][j] = fmaf(a[i], b[j], acc[i][j]);
        }
        __syncthreads();
    }

    const float bninv = rsqrtf(1.0f + 1e-5f);
    #pragma unroll
    for (int i = 0; i < 8; i++) {
        int grow = by * 128 + trow + i;
        if (grow >= M) continue;
        #pragma unroll
        for (int j = 0; j < 8; j += 4) {
            int gcol = bx * 128 + tcol + j;
            float4 v;
            float* vp = &v.x;
            #pragma unroll
            for (int t = 0; t < 4; t++) {
                float val = acc[i][j + t] + __ldg(bias + gcol + t);
                if (EPI == 2)
                    val = val * (__ldg(bng + gcol + t) * bninv) + __ldg(bnb + gcol + t);
                if (EPI >= 1)
                    val = fmaxf(val, 0.0f);
                vp[t] = val;
            }
            *(float4*)&C[(long long)grow * Nn + gcol] = v;
        }
    }
}

// ---------------------------------------------------------------------------
extern "C" void kernel_launch(void* const* d_in, const int* in_sizes, int n_in,
                              void* d_out, int out_size) {
    const float* x     = (const float*)d_in[0];
    const int*   ei    = (const int*)  d_in[1];
    const int*   src   = ei;
    const int*   dst   = ei + NEDGES;
    const int*   batch = (const int*)  d_in[2];
    const float* fp    = (const float*)d_in[3];
    const float* c1w1 = (const float*)d_in[4],  *c1b1 = (const float*)d_in[5];
    const float* c1w2 = (const float*)d_in[6],  *c1b2 = (const float*)d_in[7];
    const float* c2w1 = (const float*)d_in[8],  *c2b1 = (const float*)d_in[9];
    const float* c2w2 = (const float*)d_in[10], *c2b2 = (const float*)d_in[11];
    const float* c3w1 = (const float*)d_in[12], *c3b1 = (const float*)d_in[13];
    const float* c3w2 = (const float*)d_in[14], *c3b2 = (const float*)d_in[15];
    const float* bn1g = (const float*)d_in[16], *bn1b = (const float*)d_in[17];
    const float* bn2g = (const float*)d_in[18], *bn2b = (const float*)d_in[19];
    const float* bn3g = (const float*)d_in[20], *bn3b = (const float*)d_in[21];
    const float* o1w  = (const float*)d_in[22], *o1b  = (const float*)d_in[23];
    const float* obng = (const float*)d_in[24], *obnb = (const float*)d_in[25];
    const float* o3w  = (const float*)d_in[26], *o3b  = (const float*)d_in[27];
    float* out = (float*)d_out;

    float *aggr, *tmp, *h, *pool;
    cudaGetSymbolAddress((void**)&aggr, g_aggr);
    cudaGetSymbolAddress((void**)&tmp,  g_tmp);
    cudaGetSymbolAddress((void**)&h,    g_h);
    cudaGetSymbolAddress((void**)&pool, g_pool);

    const int T = 256;
    const int gy = (NNODES + 127) / 128;   // 782 row tiles

    // pool = [0 | fingerprint]
    pool_init_kernel<<<dim3((RDIM + T - 1) / T, NGRAPH), T>>>(fp, pool);

    // ---- conv1 (F_IN=64 -> 128 -> 128) ----
    copy_f4_kernel<<<(NNODES * 16 + T - 1) / T, T>>>((const float4*)x, (float4*)aggr, NNODES * 16);
    scatter_add_kernel<4><<<(NEDGES * 16 + T - 1) / T, T>>>((const float4*)x, src, dst, (float4*)aggr);
    sgemm_kernel<1><<<dim3(1, gy), T>>>(NNODES, 128, 64,  aggr, c1w1, c1b1, nullptr, nullptr, tmp);
    sgemm_kernel<2><<<dim3(1, gy), T>>>(NNODES, 128, 128, tmp,  c1w2, c1b2, bn1g, bn1b, h);
    pool_add_kernel<<<(NNODES * 32 + T - 1) / T, T>>>((const float4*)h, batch, (float4*)pool, 0, 5);

    // ---- conv2 (128 -> 128 -> 128) ----
    copy_f4_kernel<<<(NNODES * 32 + T - 1) / T, T>>>((const float4*)h, (float4*)aggr, NNODES * 32);
    scatter_add_kernel<5><<<(NEDGES * 32 + T - 1) / T, T>>>((const float4*)h, src, dst, (float4*)aggr);
    sgemm_kernel<1><<<dim3(1, gy), T>>>(NNODES, 128, 128, aggr, c2w1, c2b1, nullptr, nullptr, tmp);
    sgemm_kernel<2><<<dim3(1, gy), T>>>(NNODES, 128, 128, tmp,  c2w2, c2b2, bn2g, bn2b, h);
    pool_add_kernel<<<(NNODES * 32 + T - 1) / T, T>>>((const float4*)h, batch, (float4*)pool, 32, 5);

    // ---- conv3 (128 -> 256 -> 256) ----
    copy_f4_kernel<<<(NNODES * 32 + T - 1) / T, T>>>((const float4*)h, (float4*)aggr, NNODES * 32);
    scatter_add_kernel<5><<<(NEDGES * 32 + T - 1) / T, T>>>((const float4*)h, src, dst, (float4*)aggr);
    sgemm_kernel<1><<<dim3(2, gy), T>>>(NNODES, 256, 128, aggr, c3w1, c3b1, nullptr, nullptr, tmp);
    sgemm_kernel<2><<<dim3(2, gy), T>>>(NNODES, 256, 256, tmp,  c3w2, c3b2, bn3g, bn3b, h);
    pool_add_kernel<<<(NNODES * 64 + T - 1) / T, T>>>((const float4*)h, batch, (float4*)pool, 64, 6);

    // ---- readout: relu(bn(pool @ o1w + o1b)) @ o3w + o3b ----
    sgemm_kernel<2><<<dim3(3328 / 128, (NGRAPH + 127) / 128), T>>>(NGRAPH, 3328, RDIM, pool, o1w, o1b, obng, obnb, tmp);
    sgemm_kernel<0><<<dim3(128 / 128,  (NGRAPH + 127) / 128), T>>>(NGRAPH, 128, 3328, tmp, o3w, o3b, nullptr, nullptr, out);
}

// round 3
// speedup vs baseline: 2.3991x; 2.3991x over previous
#include <cuda_runtime.h>

#define NNODES 100000
#define NEDGES 1600000
#define NGRAPH 512
#define RDIM   6656
#define RD4    (RDIM/4)

// ---- static device scratch (no allocations allowed) ----
static __device__ __align__(16) float g_aggr[NNODES * 256];
static __device__ __align__(16) float g_tmp [NNODES * 256];   // also reused as [512 x 3328] mid
static __device__ __align__(16) float g_h   [NNODES * 256];
static __device__ __align__(16) float g_pool[NGRAPH * RDIM];

// ---------------------------------------------------------------------------
__global__ void pool_init_kernel(const float* __restrict__ fp, float* __restrict__ pool) {
    int col = blockIdx.x * blockDim.x + threadIdx.x;
    int row = blockIdx.y;
    if (col >= RDIM) return;
    float v = 0.0f;
    if (col >= 512) v = fp[row * 6144 + (col - 512)];
    pool[row * RDIM + col] = v;
}

__global__ void copy_f4_kernel(const float4* __restrict__ src, float4* __restrict__ dst, int n4) {
    int i = blockIdx.x * blockDim.x + threadIdx.x;
    if (i < n4) dst[i] = src[i];
}

// ---------------------------------------------------------------------------
// scatter_add: aggr[dst] += feat[src] over all edges, float4 vector reductions
// ---------------------------------------------------------------------------
template<int F4S>
__global__ void scatter_add_kernel(const float4* __restrict__ feat,
                                   const int* __restrict__ esrc,
                                   const int* __restrict__ edst,
                                   float4* __restrict__ aggr) {
    int idx = blockIdx.x * blockDim.x + threadIdx.x;
    int e = idx >> F4S;
    if (e >= NEDGES) return;
    int c = idx & ((1 << F4S) - 1);
    int s = __ldg(esrc + e);
    int d = __ldg(edst + e);
    float4 v = __ldg(&feat[(s << F4S) + c]);
    float* p = (float*)(aggr + (d << F4S) + c);
    asm volatile("red.global.add.v4.f32 [%0], {%1, %2, %3, %4};"
                 :: "l"(p), "f"(v.x), "f"(v.y), "f"(v.z), "f"(v.w) : "memory");
}

__global__ void pool_add_kernel(const float4* __restrict__ feat,
                                const int* __restrict__ batch,
                                float4* __restrict__ pool,
                                int off4, int f4shift) {
    int idx = blockIdx.x * blockDim.x + threadIdx.x;
    int i = idx >> f4shift;
    if (i >= NNODES) return;
    int c = idx & ((1 << f4shift) - 1);
    int g = __ldg(batch + i);
    float4 v = __ldg(&feat[(i << f4shift) + c]);
    float* p = (float*)(pool + g * RD4 + off4 + c);
    asm volatile("red.global.add.v4.f32 [%0], {%1, %2, %3, %4};"
                 :: "l"(p), "f"(v.x), "f"(v.y), "f"(v.z), "f"(v.w) : "memory");
}

// ---------------------------------------------------------------------------
// TF32 tensor-core GEMM: C[M,Nn] = epi(A[M,K] @ B[K,Nn] + bias)
// BM=BN=128, BK=16, 256 threads (8 warps as 2x4), warp tile 64x32,
// mma.sync.m16n8k8.tf32, fp32 accumulate. Conversion fp32->tf32 at smem store.
// Requires Nn % 128 == 0, K % 16 == 0. M bounds handled.
// EPI: 0 = +bias, 1 = relu(+bias), 2 = relu(bn(+bias))
// ---------------------------------------------------------------------------
#define SKA 20
#define SKB 136

__device__ __forceinline__ unsigned tf32_bits(float x) {
    unsigned y;
    asm("cvt.rna.tf32.f32 %0, %1;" : "=r"(y) : "f"(x));
    return y;
}

template<int EPI>
__global__ __launch_bounds__(256) void mma_gemm_kernel(
    int M, int Nn, int K,
    const float* __restrict__ A, const float* __restrict__ B,
    const float* __restrict__ bias,
    const float* __restrict__ bng, const float* __restrict__ bnb,
    float* __restrict__ C)
{
    __shared__ float As[128 * SKA];
    __shared__ float Bs[16 * SKB];

    const int tid = threadIdx.x, bx = blockIdx.x, by = blockIdx.y;
    const int warp = tid >> 5, lane = tid & 31;
    const int wm = (warp >> 2) * 64;   // warp row base (0 or 64)
    const int wn = (warp & 3) * 32;    // warp col base (0,32,64,96)
    const int lr = lane >> 2;          // 0..7
    const int lc = lane & 3;           // 0..3

    // A staging: rows am, am+64 ; cols ak..ak+3
    const int am = tid >> 2;           // 0..63
    const int ak = (tid & 3) << 2;     // 0,4,8,12
    // B staging: rows bk, bk+8 ; cols bn..bn+3
    const int bk = tid >> 5;           // 0..7
    const int bn = (tid & 31) << 2;    // 0..124

    const int ar0g = by * 128 + am;
    const int ar1g = ar0g + 64;
    const bool a0ok = ar0g < M;
    const bool a1ok = ar1g < M;
    const float* Ap0 = A + (long long)ar0g * K + ak;
    const float* Ap1 = A + (long long)ar1g * K + ak;
    const float* Bp0 = B + (long long)bk * Nn + bx * 128 + bn;
    const float* Bp1 = B + (long long)(bk + 8) * Nn + bx * 128 + bn;

    float acc[4][4][4];
    #pragma unroll
    for (int i = 0; i < 4; i++)
        #pragma unroll
        for (int j = 0; j < 4; j++)
            #pragma unroll
            for (int t = 0; t < 4; t++) acc[i][j][t] = 0.0f;

    const float4 z4 = make_float4(0.f, 0.f, 0.f, 0.f);
    float4 ra0 = a0ok ? *(const float4*)(Ap0) : z4;
    float4 ra1 = a1ok ? *(const float4*)(Ap1) : z4;
    float4 rb0 = *(const float4*)(Bp0);
    float4 rb1 = *(const float4*)(Bp1);

    for (int kk = 0; kk < K; kk += 16) {
        // store staged tile (convert to tf32 bit pattern once here)
        As[am * SKA + ak + 0] = __uint_as_float(tf32_bits(ra0.x));
        As[am * SKA + ak + 1] = __uint_as_float(tf32_bits(ra0.y));
        As[am * SKA + ak + 2] = __uint_as_float(tf32_bits(ra0.z));
        As[am * SKA + ak + 3] = __uint_as_float(tf32_bits(ra0.w));
        As[(am + 64) * SKA + ak + 0] = __uint_as_float(tf32_bits(ra1.x));
        As[(am + 64) * SKA + ak + 1] = __uint_as_float(tf32_bits(ra1.y));
        As[(am + 64) * SKA + ak + 2] = __uint_as_float(tf32_bits(ra1.z));
        As[(am + 64) * SKA + ak + 3] = __uint_as_float(tf32_bits(ra1.w));
        Bs[bk * SKB + bn + 0] = __uint_as_float(tf32_bits(rb0.x));
        Bs[bk * SKB + bn + 1] = __uint_as_float(tf32_bits(rb0.y));
        Bs[bk * SKB + bn + 2] = __uint_as_float(tf32_bits(rb0.z));
        Bs[bk * SKB + bn + 3] = __uint_as_float(tf32_bits(rb0.w));
        Bs[(bk + 8) * SKB + bn + 0] = __uint_as_float(tf32_bits(rb1.x));
        Bs[(bk + 8) * SKB + bn + 1] = __uint_as_float(tf32_bits(rb1.y));
        Bs[(bk + 8) * SKB + bn + 2] = __uint_as_float(tf32_bits(rb1.z));
        Bs[(bk + 8) * SKB + bn + 3] = __uint_as_float(tf32_bits(rb1.w));
        __syncthreads();

        int kn = kk + 16;
        if (kn < K) {
            ra0 = a0ok ? *(const float4*)(Ap0 + kn) : z4;
            ra1 = a1ok ? *(const float4*)(Ap1 + kn) : z4;
            rb0 = *(const float4*)(Bp0 + (long long)kn * Nn);
            rb1 = *(const float4*)(Bp1 + (long long)kn * Nn);
        }

        #pragma unroll
        for (int ks = 0; ks < 16; ks += 8) {
            unsigned af[4][4], bf[4][2];
            #pragma unroll
            for (int mt = 0; mt < 4; mt++) {
                int row = wm + mt * 16 + lr;
                af[mt][0] = __float_as_uint(As[row * SKA + ks + lc]);
                af[mt][1] = __float_as_uint(As[(row + 8) * SKA + ks + lc]);
                af[mt][2] = __float_as_uint(As[row * SKA + ks + lc + 4]);
                af[mt][3] = __float_as_uint(As[(row + 8) * SKA + ks + lc + 4]);
            }
            #pragma unroll
            for (int nt = 0; nt < 4; nt++) {
                int col = wn + nt * 8 + lr;
                bf[nt][0] = __float_as_uint(Bs[(ks + lc) * SKB + col]);
                bf[nt][1] = __float_as_uint(Bs[(ks + lc + 4) * SKB + col]);
            }
            #pragma unroll
            for (int mt = 0; mt < 4; mt++)
                #pragma unroll
                for (int nt = 0; nt < 4; nt++) {
                    asm volatile(
                        "mma.sync.aligned.m16n8k8.row.col.f32.tf32.tf32.f32 "
                        "{%0,%1,%2,%3}, {%4,%5,%6,%7}, {%8,%9}, {%0,%1,%2,%3};"
                        : "+f"(acc[mt][nt][0]), "+f"(acc[mt][nt][1]),
                          "+f"(acc[mt][nt][2]), "+f"(acc[mt][nt][3])
                        : "r"(af[mt][0]), "r"(af[mt][1]), "r"(af[mt][2]), "r"(af[mt][3]),
                          "r"(bf[nt][0]), "r"(bf[nt][1]));
                }
        }
        __syncthreads();
    }

    // epilogue
    const float bninv = rsqrtf(1.0f + 1e-5f);
    #pragma unroll
    for (int mt = 0; mt < 4; mt++) {
        int r0 = by * 128 + wm + mt * 16 + lr;
        int r1 = r0 + 8;
        #pragma unroll
        for (int nt = 0; nt < 4; nt++) {
            int col = bx * 128 + wn + nt * 8 + 2 * lc;
            float b0 = __ldg(bias + col);
            float b1 = __ldg(bias + col + 1);
            float g0 = 1.f, g1 = 1.f, be0 = 0.f, be1 = 0.f;
            if (EPI == 2) {
                g0 = __ldg(bng + col) * bninv;  g1 = __ldg(bng + col + 1) * bninv;
                be0 = __ldg(bnb + col);         be1 = __ldg(bnb + col + 1);
            }
            float v00 = acc[mt][nt][0] + b0, v01 = acc[mt][nt][1] + b1;
            float v10 = acc[mt][nt][2] + b0, v11 = acc[mt][nt][3] + b1;
            if (EPI == 2) {
                v00 = v00 * g0 + be0; v01 = v01 * g1 + be1;
                v10 = v10 * g0 + be0; v11 = v11 * g1 + be1;
            }
            if (EPI >= 1) {
                v00 = fmaxf(v00, 0.f); v01 = fmaxf(v01, 0.f);
                v10 = fmaxf(v10, 0.f); v11 = fmaxf(v11, 0.f);
            }
            if (r0 < M) *(float2*)&C[(long long)r0 * Nn + col] = make_float2(v00, v01);
            if (r1 < M) *(float2*)&C[(long long)r1 * Nn + col] = make_float2(v10, v11);
        }
    }
}

// ---------------------------------------------------------------------------
extern "C" void kernel_launch(void* const* d_in, const int* in_sizes, int n_in,
                              void* d_out, int out_size) {
    const float* x     = (const float*)d_in[0];
    const int*   ei    = (const int*)  d_in[1];
    const int*   src   = ei;
    const int*   dst   = ei + NEDGES;
    const int*   batch = (const int*)  d_in[2];
    const float* fp    = (const float*)d_in[3];
    const float* c1w1 = (const float*)d_in[4],  *c1b1 = (const float*)d_in[5];
    const float* c1w2 = (const float*)d_in[6],  *c1b2 = (const float*)d_in[7];
    const float* c2w1 = (const float*)d_in[8],  *c2b1 = (const float*)d_in[9];
    const float* c2w2 = (const float*)d_in[10], *c2b2 = (const float*)d_in[11];
    const float* c3w1 = (const float*)d_in[12], *c3b1 = (const float*)d_in[13];
    const float* c3w2 = (const float*)d_in[14], *c3b2 = (const float*)d_in[15];
    const float* bn1g = (const float*)d_in[16], *bn1b = (const float*)d_in[17];
    const float* bn2g = (const float*)d_in[18], *bn2b = (const float*)d_in[19];
    const float* bn3g = (const float*)d_in[20], *bn3b = (const float*)d_in[21];
    const float* o1w  = (const float*)d_in[22], *o1b  = (const float*)d_in[23];
    const float* obng = (const float*)d_in[24], *obnb = (const float*)d_in[25];
    const float* o3w  = (const float*)d_in[26], *o3b  = (const float*)d_in[27];
    float* out = (float*)d_out;

    float *aggr, *tmp, *h, *pool;
    cudaGetSymbolAddress((void**)&aggr, g_aggr);
    cudaGetSymbolAddress((void**)&tmp,  g_tmp);
    cudaGetSymbolAddress((void**)&h,    g_h);
    cudaGetSymbolAddress((void**)&pool, g_pool);

    const int T = 256;
    const int gy = (NNODES + 127) / 128;   // 782 row tiles

    // pool = [0 | fingerprint]
    pool_init_kernel<<<dim3((RDIM + T - 1) / T, NGRAPH), T>>>(fp, pool);

    // ---- conv1 (F_IN=64 -> 128 -> 128) ----
    copy_f4_kernel<<<(NNODES * 16 + T - 1) / T, T>>>((const float4*)x, (float4*)aggr, NNODES * 16);
    scatter_add_kernel<4><<<(NEDGES * 16 + T - 1) / T, T>>>((const float4*)x, src, dst, (float4*)aggr);
    mma_gemm_kernel<1><<<dim3(1, gy), T>>>(NNODES, 128, 64,  aggr, c1w1, c1b1, nullptr, nullptr, tmp);
    mma_gemm_kernel<2><<<dim3(1, gy), T>>>(NNODES, 128, 128, tmp,  c1w2, c1b2, bn1g, bn1b, h);
    pool_add_kernel<<<(NNODES * 32 + T - 1) / T, T>>>((const float4*)h, batch, (float4*)pool, 0, 5);

    // ---- conv2 (128 -> 128 -> 128) ----
    copy_f4_kernel<<<(NNODES * 32 + T - 1) / T, T>>>((const float4*)h, (float4*)aggr, NNODES * 32);
    scatter_add_kernel<5><<<(NEDGES * 32 + T - 1) / T, T>>>((const float4*)h, src, dst, (float4*)aggr);
    mma_gemm_kernel<1><<<dim3(1, gy), T>>>(NNODES, 128, 128, aggr, c2w1, c2b1, nullptr, nullptr, tmp);
    mma_gemm_kernel<2><<<dim3(1, gy), T>>>(NNODES, 128, 128, tmp,  c2w2, c2b2, bn2g, bn2b, h);
    pool_add_kernel<<<(NNODES * 32 + T - 1) / T, T>>>((const float4*)h, batch, (float4*)pool, 32, 5);

    // ---- conv3 (128 -> 256 -> 256) ----
    copy_f4_kernel<<<(NNODES * 32 + T - 1) / T, T>>>((const float4*)h, (float4*)aggr, NNODES * 32);
    scatter_add_kernel<5><<<(NEDGES * 32 + T - 1) / T, T>>>((const float4*)h, src, dst, (float4*)aggr);
    mma_gemm_kernel<1><<<dim3(2, gy), T>>>(NNODES, 256, 128, aggr, c3w1, c3b1, nullptr, nullptr, tmp);
    mma_gemm_kernel<2><<<dim3(2, gy), T>>>(NNODES, 256, 256, tmp,  c3w2, c3b2, bn3g, bn3b, h);
    pool_add_kernel<<<(NNODES * 64 + T - 1) / T, T>>>((const float4*)h, batch, (float4*)pool, 64, 6);

    // ---- readout: relu(bn(pool @ o1w + o1b)) @ o3w + o3b ----
    mma_gemm_kernel<2><<<dim3(3328 / 128, (NGRAPH + 127) / 128), T>>>(NGRAPH, 3328, RDIM, pool, o1w, o1b, obng, obnb, tmp);
    mma_gemm_kernel<0><<<dim3(1, (NGRAPH + 127) / 128), T>>>(NGRAPH, 128, 3328, tmp, o3w, o3b, nullptr, nullptr, out);
}

// round 4
// speedup vs baseline: 2.8612x; 1.1926x over previous
#include <cuda_runtime.h>

#define NNODES 100000
#define NEDGES 1600000
#define NGRAPH 512
#define RDIM   6656

// ---- static device scratch (no allocations allowed) ----
static __device__ __align__(16) float g_aggr[NNODES * 256];
static __device__ __align__(16) float g_tmp [NNODES * 256];   // also reused as [512 x 3328] mid
static __device__ __align__(16) float g_h   [NNODES * 256];
static __device__ __align__(16) float g_pool[NGRAPH * RDIM];
static __device__ int g_deg[NNODES];
static __device__ int g_cursor[NNODES];
static __device__ int g_rowptr[NNODES + 1];
static __device__ int g_srclist[NEDGES];
static __device__ int g_gstart[NGRAPH + 1];

// ---------------------------------------------------------------------------
// CSR build: zero degrees -> histogram -> scan -> fill src lists
// ---------------------------------------------------------------------------
__global__ void zero_deg_kernel(int* __restrict__ deg) {
    int i = blockIdx.x * blockDim.x + threadIdx.x;
    if (i < NNODES) deg[i] = 0;
}

__global__ void hist_kernel(const int* __restrict__ edst, int* __restrict__ deg) {
    int e = blockIdx.x * blockDim.x + threadIdx.x;
    if (e < NEDGES) atomicAdd(&deg[__ldg(edst + e)], 1);
}

// single-block exclusive scan over NNODES degrees -> rowptr, cursor
__global__ __launch_bounds__(1024) void scan_kernel(const int* __restrict__ deg,
                                                    int* __restrict__ rowptr,
                                                    int* __restrict__ cursor) {
    __shared__ int sums[1024];
    const int t = threadIdx.x;
    const int chunk = (NNODES + 1023) / 1024;   // 98
    const int beg = t * chunk;
    const int end = min(beg + chunk, NNODES);
    int s = 0;
    for (int k = beg; k < end; k++) s += deg[k];
    sums[t] = s;
    __syncthreads();
    // Hillis-Steele inclusive scan
    for (int off = 1; off < 1024; off <<= 1) {
        int v = (t >= off) ? sums[t - off] : 0;
        __syncthreads();
        sums[t] += v;
        __syncthreads();
    }
    int base = sums[t] - s;   // exclusive
    int run = base;
    for (int k = beg; k < end; k++) {
        rowptr[k] = run;
        cursor[k] = run;
        run += deg[k];
    }
    if (t == 1023) rowptr[NNODES] = sums[1023];
}

__global__ void fill_kernel(const int* __restrict__ esrc, const int* __restrict__ edst,
                            int* __restrict__ cursor, int* __restrict__ srclist) {
    int e = blockIdx.x * blockDim.x + threadIdx.x;
    if (e >= NEDGES) return;
    int d = __ldg(edst + e);
    int pos = atomicAdd(&cursor[d], 1);
    srclist[pos] = __ldg(esrc + e);
}

// graph ranges: gstart[g] = first node index with batch >= g (batch is sorted)
__global__ void gstart_kernel(const int* __restrict__ batch, int* __restrict__ gstart) {
    int g = blockIdx.x * blockDim.x + threadIdx.x;
    if (g > NGRAPH) return;
    if (g == NGRAPH) { gstart[NGRAPH] = NNODES; return; }
    int lo = 0, hi = NNODES;
    while (lo < hi) {
        int mid = (lo + hi) >> 1;
        if (__ldg(batch + mid) < g) lo = mid + 1; else hi = mid;
    }
    gstart[g] = lo;
}

// ---------------------------------------------------------------------------
// gather aggregation: aggr[i] = feat[i] + sum_{s in adj(i)} feat[s]
// F4 = F/4 float4 per row; L lanes per node
// ---------------------------------------------------------------------------
template<int F4S>
__global__ void gather_aggr_kernel(const float4* __restrict__ feat,
                                   const int* __restrict__ rowptr,
                                   const int* __restrict__ srclist,
                                   float4* __restrict__ aggr) {
    constexpr int F4 = 1 << F4S;
    constexpr int L = (F4 < 32) ? F4 : 32;
    constexpr int VPT = F4 / L;
    constexpr int NPB = 256 / L;
    int i = blockIdx.x * NPB + threadIdx.x / L;
    if (i >= NNODES) return;
    int c = threadIdx.x % L;

    float4 acc[VPT];
    #pragma unroll
    for (int v = 0; v < VPT; v++)
        acc[v] = __ldg(&feat[(i << F4S) + c + v * L]);

    int j = __ldg(rowptr + i);
    const int end = __ldg(rowptr + i + 1);
    for (; j + 1 < end; j += 2) {
        int s0 = __ldg(srclist + j);
        int s1 = __ldg(srclist + j + 1);
        #pragma unroll
        for (int v = 0; v < VPT; v++) {
            float4 t0 = __ldg(&feat[(s0 << F4S) + c + v * L]);
            float4 t1 = __ldg(&feat[(s1 << F4S) + c + v * L]);
            acc[v].x += t0.x + t1.x; acc[v].y += t0.y + t1.y;
            acc[v].z += t0.z + t1.z; acc[v].w += t0.w + t1.w;
        }
    }
    if (j < end) {
        int s0 = __ldg(srclist + j);
        #pragma unroll
        for (int v = 0; v < VPT; v++) {
            float4 t0 = __ldg(&feat[(s0 << F4S) + c + v * L]);
            acc[v].x += t0.x; acc[v].y += t0.y; acc[v].z += t0.z; acc[v].w += t0.w;
        }
    }
    #pragma unroll
    for (int v = 0; v < VPT; v++)
        aggr[(i << F4S) + c + v * L] = acc[v];
}

// ---------------------------------------------------------------------------
// segment pool: pool[g, off + tid] = sum over rows of feat in graph g
// launch with F threads per block, NGRAPH blocks
// ---------------------------------------------------------------------------
__global__ void seg_pool_kernel(const float* __restrict__ feat,
                                const int* __restrict__ gstart,
                                float* __restrict__ pool,
                                int F, int off) {
    int g = blockIdx.x;
    int t = threadIdx.x;
    int beg = __ldg(gstart + g), end = __ldg(gstart + g + 1);
    float a0 = 0.f, a1 = 0.f;
    int r = beg;
    for (; r + 1 < end; r += 2) {
        a0 += __ldg(feat + (long long)r * F + t);
        a1 += __ldg(feat + (long long)(r + 1) * F + t);
    }
    if (r < end) a0 += __ldg(feat + (long long)r * F + t);
    pool[(long long)g * RDIM + off + t] = a0 + a1;
}

// fingerprint copy: pool[:, 512:6656] = fp
__global__ void fp_copy_kernel(const float4* __restrict__ fp, float4* __restrict__ pool) {
    int col = blockIdx.x * blockDim.x + threadIdx.x;   // float4 col < 1536
    int row = blockIdx.y;
    if (col >= 1536) return;
    pool[row * (RDIM / 4) + 128 + col] = fp[row * 1536 + col];
}

// ---------------------------------------------------------------------------
// TF32 tensor-core GEMM (unchanged from R3)
// ---------------------------------------------------------------------------
#define SKA 20
#define SKB 136

__device__ __forceinline__ unsigned tf32_bits(float x) {
    unsigned y;
    asm("cvt.rna.tf32.f32 %0, %1;" : "=r"(y) : "f"(x));
    return y;
}

template<int EPI>
__global__ __launch_bounds__(256) void mma_gemm_kernel(
    int M, int Nn, int K,
    const float* __restrict__ A, const float* __restrict__ B,
    const float* __restrict__ bias,
    const float* __restrict__ bng, const float* __restrict__ bnb,
    float* __restrict__ C)
{
    __shared__ float As[128 * SKA];
    __shared__ float Bs[16 * SKB];

    const int tid = threadIdx.x, bx = blockIdx.x, by = blockIdx.y;
    const int warp = tid >> 5, lane = tid & 31;
    const int wm = (warp >> 2) * 64;
    const int wn = (warp & 3) * 32;
    const int lr = lane >> 2;
    const int lc = lane & 3;

    const int am = tid >> 2;
    const int ak = (tid & 3) << 2;
    const int bk = tid >> 5;
    const int bn = (tid & 31) << 2;

    const int ar0g = by * 128 + am;
    const int ar1g = ar0g + 64;
    const bool a0ok = ar0g < M;
    const bool a1ok = ar1g < M;
    const float* Ap0 = A + (long long)ar0g * K + ak;
    const float* Ap1 = A + (long long)ar1g * K + ak;
    const float* Bp0 = B + (long long)bk * Nn + bx * 128 + bn;
    const float* Bp1 = B + (long long)(bk + 8) * Nn + bx * 128 + bn;

    float acc[4][4][4];
    #pragma unroll
    for (int i = 0; i < 4; i++)
        #pragma unroll
        for (int j = 0; j < 4; j++)
            #pragma unroll
            for (int t = 0; t < 4; t++) acc[i][j][t] = 0.0f;

    const float4 z4 = make_float4(0.f, 0.f, 0.f, 0.f);
    float4 ra0 = a0ok ? *(const float4*)(Ap0) : z4;
    float4 ra1 = a1ok ? *(const float4*)(Ap1) : z4;
    float4 rb0 = *(const float4*)(Bp0);
    float4 rb1 = *(const float4*)(Bp1);

    for (int kk = 0; kk < K; kk += 16) {
        As[am * SKA + ak + 0] = __uint_as_float(tf32_bits(ra0.x));
        As[am * SKA + ak + 1] = __uint_as_float(tf32_bits(ra0.y));
        As[am * SKA + ak + 2] = __uint_as_float(tf32_bits(ra0.z));
        As[am * SKA + ak + 3] = __uint_as_float(tf32_bits(ra0.w));
        As[(am + 64) * SKA + ak + 0] = __uint_as_float(tf32_bits(ra1.x));
        As[(am + 64) * SKA + ak + 1] = __uint_as_float(tf32_bits(ra1.y));
        As[(am + 64) * SKA + ak + 2] = __uint_as_float(tf32_bits(ra1.z));
        As[(am + 64) * SKA + ak + 3] = __uint_as_float(tf32_bits(ra1.w));
        Bs[bk * SKB + bn + 0] = __uint_as_float(tf32_bits(rb0.x));
        Bs[bk * SKB + bn + 1] = __uint_as_float(tf32_bits(rb0.y));
        Bs[bk * SKB + bn + 2] = __uint_as_float(tf32_bits(rb0.z));
        Bs[bk * SKB + bn + 3] = __uint_as_float(tf32_bits(rb0.w));
        Bs[(bk + 8) * SKB + bn + 0] = __uint_as_float(tf32_bits(rb1.x));
        Bs[(bk + 8) * SKB + bn + 1] = __uint_as_float(tf32_bits(rb1.y));
        Bs[(bk + 8) * SKB + bn + 2] = __uint_as_float(tf32_bits(rb1.z));
        Bs[(bk + 8) * SKB + bn + 3] = __uint_as_float(tf32_bits(rb1.w));
        __syncthreads();

        int kn = kk + 16;
        if (kn < K) {
            ra0 = a0ok ? *(const float4*)(Ap0 + kn) : z4;
            ra1 = a1ok ? *(const float4*)(Ap1 + kn) : z4;
            rb0 = *(const float4*)(Bp0 + (long long)kn * Nn);
            rb1 = *(const float4*)(Bp1 + (long long)kn * Nn);
        }

        #pragma unroll
        for (int ks = 0; ks < 16; ks += 8) {
            unsigned af[4][4], bf[4][2];
            #pragma unroll
            for (int mt = 0; mt < 4; mt++) {
                int row = wm + mt * 16 + lr;
                af[mt][0] = __float_as_uint(As[row * SKA + ks + lc]);
                af[mt][1] = __float_as_uint(As[(row + 8) * SKA + ks + lc]);
                af[mt][2] = __float_as_uint(As[row * SKA + ks + lc + 4]);
                af[mt][3] = __float_as_uint(As[(row + 8) * SKA + ks + lc + 4]);
            }
            #pragma unroll
            for (int nt = 0; nt < 4; nt++) {
                int col = wn + nt * 8 + lr;
                bf[nt][0] = __float_as_uint(Bs[(ks + lc) * SKB + col]);
                bf[nt][1] = __float_as_uint(Bs[(ks + lc + 4) * SKB + col]);
            }
            #pragma unroll
            for (int mt = 0; mt < 4; mt++)
                #pragma unroll
                for (int nt = 0; nt < 4; nt++) {
                    asm volatile(
                        "mma.sync.aligned.m16n8k8.row.col.f32.tf32.tf32.f32 "
                        "{%0,%1,%2,%3}, {%4,%5,%6,%7}, {%8,%9}, {%0,%1,%2,%3};"
                        : "+f"(acc[mt][nt][0]), "+f"(acc[mt][nt][1]),
                          "+f"(acc[mt][nt][2]), "+f"(acc[mt][nt][3])
                        : "r"(af[mt][0]), "r"(af[mt][1]), "r"(af[mt][2]), "r"(af[mt][3]),
                          "r"(bf[nt][0]), "r"(bf[nt][1]));
                }
        }
        __syncthreads();
    }

    const float bninv = rsqrtf(1.0f + 1e-5f);
    #pragma unroll
    for (int mt = 0; mt < 4; mt++) {
        int r0 = by * 128 + wm + mt * 16 + lr;
        int r1 = r0 + 8;
        #pragma unroll
        for (int nt = 0; nt < 4; nt++) {
            int col = bx * 128 + wn + nt * 8 + 2 * lc;
            float b0 = __ldg(bias + col);
            float b1 = __ldg(bias + col + 1);
            float g0 = 1.f, g1 = 1.f, be0 = 0.f, be1 = 0.f;
            if (EPI == 2) {
                g0 = __ldg(bng + col) * bninv;  g1 = __ldg(bng + col + 1) * bninv;
                be0 = __ldg(bnb + col);         be1 = __ldg(bnb + col + 1);
            }
            float v00 = acc[mt][nt][0] + b0, v01 = acc[mt][nt][1] + b1;
            float v10 = acc[mt][nt][2] + b0, v11 = acc[mt][nt][3] + b1;
            if (EPI == 2) {
                v00 = v00 * g0 + be0; v01 = v01 * g1 + be1;
                v10 = v10 * g0 + be0; v11 = v11 * g1 + be1;
            }
            if (EPI >= 1) {
                v00 = fmaxf(v00, 0.f); v01 = fmaxf(v01, 0.f);
                v10 = fmaxf(v10, 0.f); v11 = fmaxf(v11, 0.f);
            }
            if (r0 < M) *(float2*)&C[(long long)r0 * Nn + col] = make_float2(v00, v01);
            if (r1 < M) *(float2*)&C[(long long)r1 * Nn + col] = make_float2(v10, v11);
        }
    }
}

// ---------------------------------------------------------------------------
extern "C" void kernel_launch(void* const* d_in, const int* in_sizes, int n_in,
                              void* d_out, int out_size) {
    const float* x     = (const float*)d_in[0];
    const int*   ei    = (const int*)  d_in[1];
    const int*   src   = ei;
    const int*   dst   = ei + NEDGES;
    const int*   batch = (const int*)  d_in[2];
    const float* fp    = (const float*)d_in[3];
    const float* c1w1 = (const float*)d_in[4],  *c1b1 = (const float*)d_in[5];
    const float* c1w2 = (const float*)d_in[6],  *c1b2 = (const float*)d_in[7];
    const float* c2w1 = (const float*)d_in[8],  *c2b1 = (const float*)d_in[9];
    const float* c2w2 = (const float*)d_in[10], *c2b2 = (const float*)d_in[11];
    const float* c3w1 = (const float*)d_in[12], *c3b1 = (const float*)d_in[13];
    const float* c3w2 = (const float*)d_in[14], *c3b2 = (const float*)d_in[15];
    const float* bn1g = (const float*)d_in[16], *bn1b = (const float*)d_in[17];
    const float* bn2g = (const float*)d_in[18], *bn2b = (const float*)d_in[19];
    const float* bn3g = (const float*)d_in[20], *bn3b = (const float*)d_in[21];
    const float* o1w  = (const float*)d_in[22], *o1b  = (const float*)d_in[23];
    const float* obng = (const float*)d_in[24], *obnb = (const float*)d_in[25];
    const float* o3w  = (const float*)d_in[26], *o3b  = (const float*)d_in[27];
    float* out = (float*)d_out;

    float *aggr, *tmp, *h, *pool;
    int *deg, *cursor, *rowptr, *srclist, *gstart;
    cudaGetSymbolAddress((void**)&aggr,    g_aggr);
    cudaGetSymbolAddress((void**)&tmp,     g_tmp);
    cudaGetSymbolAddress((void**)&h,       g_h);
    cudaGetSymbolAddress((void**)&pool,    g_pool);
    cudaGetSymbolAddress((void**)&deg,     g_deg);
    cudaGetSymbolAddress((void**)&cursor,  g_cursor);
    cudaGetSymbolAddress((void**)&rowptr,  g_rowptr);
    cudaGetSymbolAddress((void**)&srclist, g_srclist);
    cudaGetSymbolAddress((void**)&gstart,  g_gstart);

    const int T = 256;
    const int gy = (NNODES + 127) / 128;   // 782 row tiles

    // ---- CSR build (once; reused by all 3 convs) ----
    zero_deg_kernel<<<(NNODES + T - 1) / T, T>>>(deg);
    hist_kernel<<<(NEDGES + T - 1) / T, T>>>(dst, deg);
    scan_kernel<<<1, 1024>>>(deg, rowptr, cursor);
    fill_kernel<<<(NEDGES + T - 1) / T, T>>>(src, dst, cursor, srclist);
    gstart_kernel<<<3, 256>>>(batch, gstart);
    fp_copy_kernel<<<dim3((1536 + T - 1) / T, NGRAPH), T>>>((const float4*)fp, (float4*)pool);

    // ---- conv1 (F_IN=64 -> 128 -> 128) ----
    gather_aggr_kernel<4><<<(NNODES * 16 + T - 1) / T, T>>>((const float4*)x, rowptr, srclist, (float4*)aggr);
    mma_gemm_kernel<1><<<dim3(1, gy), T>>>(NNODES, 128, 64,  aggr, c1w1, c1b1, nullptr, nullptr, tmp);
    mma_gemm_kernel<2><<<dim3(1, gy), T>>>(NNODES, 128, 128, tmp,  c1w2, c1b2, bn1g, bn1b, h);
    seg_pool_kernel<<<NGRAPH, 128>>>(h, gstart, pool, 128, 0);

    // ---- conv2 (128 -> 128 -> 128) ----
    gather_aggr_kernel<5><<<(NNODES * 32 + T - 1) / T, T>>>((const float4*)h, rowptr, srclist, (float4*)aggr);
    mma_gemm_kernel<1><<<dim3(1, gy), T>>>(NNODES, 128, 128, aggr, c2w1, c2b1, nullptr, nullptr, tmp);
    mma_gemm_kernel<2><<<dim3(1, gy), T>>>(NNODES, 128, 128, tmp,  c2w2, c2b2, bn2g, bn2b, aggr);
    seg_pool_kernel<<<NGRAPH, 128>>>(aggr, gstart, pool, 128, 128);

    // ---- conv3 (128 -> 256 -> 256) ----   (h2 lives in aggr; gather into h)
    gather_aggr_kernel<5><<<(NNODES * 32 + T - 1) / T, T>>>((const float4*)aggr, rowptr, srclist, (float4*)h);
    mma_gemm_kernel<1><<<dim3(2, gy), T>>>(NNODES, 256, 128, h,   c3w1, c3b1, nullptr, nullptr, tmp);
    mma_gemm_kernel<2><<<dim3(2, gy), T>>>(NNODES, 256, 256, tmp, c3w2, c3b2, bn3g, bn3b, h);
    seg_pool_kernel<<<NGRAPH, 256>>>(h, gstart, pool, 256, 256);

    // ---- readout: relu(bn(pool @ o1w + o1b)) @ o3w + o3b ----
    mma_gemm_kernel<2><<<dim3(3328 / 128, (NGRAPH + 127) / 128), T>>>(NGRAPH, 3328, RDIM, pool, o1w, o1b, obng, obnb, tmp);
    mma_gemm_kernel<0><<<dim3(1, (NGRAPH + 127) / 128), T>>>(NGRAPH, 128, 3328, tmp, o3w, o3b, nullptr, nullptr, out);
}

// round 5
// speedup vs baseline: 3.5300x; 1.2338x over previous
#include <cuda_runtime.h>

#define NNODES 100000
#define NEDGES 1600000
#define NGRAPH 512
#define RDIM   6656

// ---- static device scratch (no allocations allowed) ----
static __device__ __align__(16) float g_aggr[NNODES * 256];
static __device__ __align__(16) float g_tmp [NNODES * 256];
static __device__ __align__(16) float g_h   [NNODES * 256];
static __device__ __align__(16) float g_pool[NGRAPH * RDIM];
static __device__ int g_deg[NNODES];
static __device__ int g_cursor[NNODES];
static __device__ int g_rowptr[NNODES + 1];
static __device__ int g_srclist[NEDGES];
static __device__ int g_gstart[NGRAPH + 1];

// ---------------------------------------------------------------------------
// CSR build
// ---------------------------------------------------------------------------
__global__ void zero_deg_kernel(int* __restrict__ deg) {
    int i = blockIdx.x * blockDim.x + threadIdx.x;
    if (i < NNODES) deg[i] = 0;
}

__global__ void hist_kernel(const int* __restrict__ edst, int* __restrict__ deg) {
    int e = blockIdx.x * blockDim.x + threadIdx.x;
    if (e < NEDGES) atomicAdd(&deg[__ldg(edst + e)], 1);
}

__global__ __launch_bounds__(1024) void scan_kernel(const int* __restrict__ deg,
                                                    int* __restrict__ rowptr,
                                                    int* __restrict__ cursor) {
    __shared__ int sums[1024];
    const int t = threadIdx.x;
    const int chunk = (NNODES + 1023) / 1024;
    const int beg = t * chunk;
    const int end = min(beg + chunk, NNODES);
    int s = 0;
    for (int k = beg; k < end; k++) s += deg[k];
    sums[t] = s;
    __syncthreads();
    for (int off = 1; off < 1024; off <<= 1) {
        int v = (t >= off) ? sums[t - off] : 0;
        __syncthreads();
        sums[t] += v;
        __syncthreads();
    }
    int run = sums[t] - s;
    for (int k = beg; k < end; k++) {
        rowptr[k] = run;
        cursor[k] = run;
        run += deg[k];
    }
    if (t == 1023) rowptr[NNODES] = sums[1023];
}

__global__ void fill_kernel(const int* __restrict__ esrc, const int* __restrict__ edst,
                            int* __restrict__ cursor, int* __restrict__ srclist) {
    int e = blockIdx.x * blockDim.x + threadIdx.x;
    if (e >= NEDGES) return;
    int d = __ldg(edst + e);
    int pos = atomicAdd(&cursor[d], 1);
    srclist[pos] = __ldg(esrc + e);
}

__global__ void gstart_kernel(const int* __restrict__ batch, int* __restrict__ gstart) {
    int g = blockIdx.x * blockDim.x + threadIdx.x;
    if (g > NGRAPH) return;
    if (g == NGRAPH) { gstart[NGRAPH] = NNODES; return; }
    int lo = 0, hi = NNODES;
    while (lo < hi) {
        int mid = (lo + hi) >> 1;
        if (__ldg(batch + mid) < g) lo = mid + 1; else hi = mid;
    }
    gstart[g] = lo;
}

// ---------------------------------------------------------------------------
// gather aggregation: aggr[i] = feat[i] + sum_{s in adj(i)} feat[s]
// ---------------------------------------------------------------------------
template<int F4S>
__global__ void gather_aggr_kernel(const float4* __restrict__ feat,
                                   const int* __restrict__ rowptr,
                                   const int* __restrict__ srclist,
                                   float4* __restrict__ aggr) {
    constexpr int F4 = 1 << F4S;
    constexpr int L = (F4 < 32) ? F4 : 32;
    constexpr int VPT = F4 / L;
    constexpr int NPB = 256 / L;
    int i = blockIdx.x * NPB + threadIdx.x / L;
    if (i >= NNODES) return;
    int c = threadIdx.x % L;

    float4 acc[VPT];
    #pragma unroll
    for (int v = 0; v < VPT; v++)
        acc[v] = __ldg(&feat[(i << F4S) + c + v * L]);

    int j = __ldg(rowptr + i);
    const int end = __ldg(rowptr + i + 1);
    for (; j + 1 < end; j += 2) {
        int s0 = __ldg(srclist + j);
        int s1 = __ldg(srclist + j + 1);
        #pragma unroll
        for (int v = 0; v < VPT; v++) {
            float4 t0 = __ldg(&feat[(s0 << F4S) + c + v * L]);
            float4 t1 = __ldg(&feat[(s1 << F4S) + c + v * L]);
            acc[v].x += t0.x + t1.x; acc[v].y += t0.y + t1.y;
            acc[v].z += t0.z + t1.z; acc[v].w += t0.w + t1.w;
        }
    }
    if (j < end) {
        int s0 = __ldg(srclist + j);
        #pragma unroll
        for (int v = 0; v < VPT; v++) {
            float4 t0 = __ldg(&feat[(s0 << F4S) + c + v * L]);
            acc[v].x += t0.x; acc[v].y += t0.y; acc[v].z += t0.z; acc[v].w += t0.w;
        }
    }
    #pragma unroll
    for (int v = 0; v < VPT; v++)
        aggr[(i << F4S) + c + v * L] = acc[v];
}

// ---------------------------------------------------------------------------
// segment pool
// ---------------------------------------------------------------------------
__global__ void seg_pool_kernel(const float* __restrict__ feat,
                                const int* __restrict__ gstart,
                                float* __restrict__ pool,
                                int F, int off) {
    int g = blockIdx.x;
    int t = threadIdx.x;
    int beg = __ldg(gstart + g), end = __ldg(gstart + g + 1);
    float a0 = 0.f, a1 = 0.f;
    int r = beg;
    for (; r + 1 < end; r += 2) {
        a0 += __ldg(feat + (long long)r * F + t);
        a1 += __ldg(feat + (long long)(r + 1) * F + t);
    }
    if (r < end) a0 += __ldg(feat + (long long)r * F + t);
    pool[(long long)g * RDIM + off + t] = a0 + a1;
}

__global__ void fp_copy_kernel(const float4* __restrict__ fp, float4* __restrict__ pool) {
    int col = blockIdx.x * blockDim.x + threadIdx.x;
    int row = blockIdx.y;
    if (col >= 1536) return;
    pool[row * (RDIM / 4) + 128 + col] = fp[row * 1536 + col];
}

// ---------------------------------------------------------------------------
// TF32 tensor-core GEMM, BM=BN=128, BK=32, double-buffered dynamic smem.
// SPLIT=1: grid.z = splits, K = per-split K, raw partials to C + z*M*Nn.
// EPI: 0 = +bias, 1 = relu(+bias), 2 = relu(bn(+bias))
// ---------------------------------------------------------------------------
#define BKK 32
#define SKA 36
#define SKB 136
#define ASZ (128 * SKA)
#define BSZ (BKK * SKB)
#define GEMM_SMEM ((2 * (ASZ + BSZ)) * 4)

__device__ __forceinline__ float tf32f(float x) {
    unsigned u;
    asm("cvt.rna.tf32.f32 %0, %1;" : "=r"(u) : "f"(x));
    return __uint_as_float(u);
}

template<int EPI, int SPLIT>
__global__ __launch_bounds__(256, 2) void mma_gemm_kernel(
    int M, int Nn, int K, int ldA,
    const float* __restrict__ A, const float* __restrict__ B,
    const float* __restrict__ bias,
    const float* __restrict__ bng, const float* __restrict__ bnb,
    float* __restrict__ C)
{
    extern __shared__ float smem[];
    float* As = smem;
    float* Bs = smem + 2 * ASZ;

    const int tid = threadIdx.x, bx = blockIdx.x, by = blockIdx.y, bz = blockIdx.z;
    const int warp = tid >> 5, lane = tid & 31;
    const int wm = (warp >> 2) * 64;
    const int wn = (warp & 3) * 32;
    const int lr = lane >> 2;
    const int lc = lane & 3;

    // staging maps
    const int arow = tid >> 1;          // 0..127
    const int acol = (tid & 1) * 16;    // 0 or 16
    const int brow = tid >> 3;          // 0..31
    const int bcol = (tid & 7) * 4;     // 0..28

    const int gArow = by * 128 + arow;
    const bool aok = gArow < M;
    const float* Aptr = A + (long long)gArow * ldA + (long long)bz * K + acol;
    const float* Bptr = B + ((long long)bz * K + brow) * Nn + bx * 128 + bcol;

    float4 ra[4], rb[4];
    const float4 z4 = make_float4(0.f, 0.f, 0.f, 0.f);

    auto load_tile = [&](int kk) {
        #pragma unroll
        for (int j = 0; j < 4; j++)
            ra[j] = aok ? __ldg((const float4*)(Aptr + kk + 4 * j)) : z4;
        #pragma unroll
        for (int j = 0; j < 4; j++)
            rb[j] = __ldg((const float4*)(Bptr + (long long)kk * Nn + 32 * j));
    };
    auto store_tile = [&](int buf) {
        float* a_ = As + buf * ASZ + arow * SKA + acol;
        #pragma unroll
        for (int j = 0; j < 4; j++) {
            float4 v = ra[j];
            v.x = tf32f(v.x); v.y = tf32f(v.y); v.z = tf32f(v.z); v.w = tf32f(v.w);
            *(float4*)(a_ + 4 * j) = v;
        }
        float* b_ = Bs + buf * BSZ + brow * SKB + bcol;
        #pragma unroll
        for (int j = 0; j < 4; j++) {
            float4 v = rb[j];
            v.x = tf32f(v.x); v.y = tf32f(v.y); v.z = tf32f(v.z); v.w = tf32f(v.w);
            *(float4*)(b_ + 32 * j) = v;
        }
    };

    float acc[4][4][4];
    #pragma unroll
    for (int i = 0; i < 4; i++)
        #pragma unroll
        for (int j = 0; j < 4; j++)
            #pragma unroll
            for (int t = 0; t < 4; t++) acc[i][j][t] = 0.0f;

    auto compute = [&](int buf) {
        const float* a_ = As + buf * ASZ;
        const float* b_ = Bs + buf * BSZ;
        #pragma unroll
        for (int ks = 0; ks < BKK; ks += 8) {
            unsigned af[4][4], bf[4][2];
            #pragma unroll
            for (int mt = 0; mt < 4; mt++) {
                int row = wm + mt * 16 + lr;
                af[mt][0] = __float_as_uint(a_[row * SKA + ks + lc]);
                af[mt][1] = __float_as_uint(a_[(row + 8) * SKA + ks + lc]);
                af[mt][2] = __float_as_uint(a_[row * SKA + ks + lc + 4]);
                af[mt][3] = __float_as_uint(a_[(row + 8) * SKA + ks + lc + 4]);
            }
            #pragma unroll
            for (int nt = 0; nt < 4; nt++) {
                int col = wn + nt * 8 + lr;
                bf[nt][0] = __float_as_uint(b_[(ks + lc) * SKB + col]);
                bf[nt][1] = __float_as_uint(b_[(ks + lc + 4) * SKB + col]);
            }
            #pragma unroll
            for (int mt = 0; mt < 4; mt++)
                #pragma unroll
                for (int nt = 0; nt < 4; nt++) {
                    asm volatile(
                        "mma.sync.aligned.m16n8k8.row.col.f32.tf32.tf32.f32 "
                        "{%0,%1,%2,%3}, {%4,%5,%6,%7}, {%8,%9}, {%0,%1,%2,%3};"
                        : "+f"(acc[mt][nt][0]), "+f"(acc[mt][nt][1]),
                          "+f"(acc[mt][nt][2]), "+f"(acc[mt][nt][3])
                        : "r"(af[mt][0]), "r"(af[mt][1]), "r"(af[mt][2]), "r"(af[mt][3]),
                          "r"(bf[nt][0]), "r"(bf[nt][1]));
                }
        }
    };

    const int nIter = K / BKK;
    load_tile(0);
    store_tile(0);
    __syncthreads();
    for (int it = 0; it < nIter; it++) {
        int buf = it & 1;
        if (it + 1 < nIter) load_tile((it + 1) * BKK);
        compute(buf);
        if (it + 1 < nIter) store_tile(buf ^ 1);
        __syncthreads();
    }

    if (SPLIT) {
        float* Cz = C + (long long)bz * M * Nn;
        #pragma unroll
        for (int mt = 0; mt < 4; mt++) {
            int r0 = by * 128 + wm + mt * 16 + lr;
            int r1 = r0 + 8;
            #pragma unroll
            for (int nt = 0; nt < 4; nt++) {
                int col = bx * 128 + wn + nt * 8 + 2 * lc;
                if (r0 < M) *(float2*)&Cz[(long long)r0 * Nn + col] = make_float2(acc[mt][nt][0], acc[mt][nt][1]);
                if (r1 < M) *(float2*)&Cz[(long long)r1 * Nn + col] = make_float2(acc[mt][nt][2], acc[mt][nt][3]);
            }
        }
        return;
    }

    const float bninv = rsqrtf(1.0f + 1e-5f);
    #pragma unroll
    for (int mt = 0; mt < 4; mt++) {
        int r0 = by * 128 + wm + mt * 16 + lr;
        int r1 = r0 + 8;
        #pragma unroll
        for (int nt = 0; nt < 4; nt++) {
            int col = bx * 128 + wn + nt * 8 + 2 * lc;
            float b0 = __ldg(bias + col);
            float b1 = __ldg(bias + col + 1);
            float g0 = 1.f, g1 = 1.f, be0 = 0.f, be1 = 0.f;
            if (EPI == 2) {
                g0 = __ldg(bng + col) * bninv;  g1 = __ldg(bng + col + 1) * bninv;
                be0 = __ldg(bnb + col);         be1 = __ldg(bnb + col + 1);
            }
            float v00 = acc[mt][nt][0] + b0, v01 = acc[mt][nt][1] + b1;
            float v10 = acc[mt][nt][2] + b0, v11 = acc[mt][nt][3] + b1;
            if (EPI == 2) {
                v00 = v00 * g0 + be0; v01 = v01 * g1 + be1;
                v10 = v10 * g0 + be0; v11 = v11 * g1 + be1;
            }
            if (EPI >= 1) {
                v00 = fmaxf(v00, 0.f); v01 = fmaxf(v01, 0.f);
                v10 = fmaxf(v10, 0.f); v11 = fmaxf(v11, 0.f);
            }
            if (r0 < M) *(float2*)&C[(long long)r0 * Nn + col] = make_float2(v00, v01);
            if (r1 < M) *(float2*)&C[(long long)r1 * Nn + col] = make_float2(v10, v11);
        }
    }
}

// ---------------------------------------------------------------------------
// split-K reductions (fixed order -> deterministic)
// ---------------------------------------------------------------------------
__global__ void readout_reduce_kernel(const float4* __restrict__ part,
                                      const float* __restrict__ bias,
                                      const float* __restrict__ bng,
                                      const float* __restrict__ bnb,
                                      float4* __restrict__ outbuf) {
    const int N4 = 3328 / 4;
    int idx = blockIdx.x * blockDim.x + threadIdx.x;
    if (idx >= NGRAPH * N4) return;
    const long long SZ4 = (long long)NGRAPH * N4;
    int col = (idx % N4) * 4;
    float4 s = part[idx];
    #pragma unroll
    for (int z = 1; z < 4; z++) {
        float4 t = part[idx + z * SZ4];
        s.x += t.x; s.y += t.y; s.z += t.z; s.w += t.w;
    }
    const float bninv = rsqrtf(1.0f + 1e-5f);
    float* sp = &s.x;
    #pragma unroll
    for (int c = 0; c < 4; c++) {
        float v = (sp[c] + __ldg(bias + col + c)) * (__ldg(bng + col + c) * bninv) + __ldg(bnb + col + c);
        sp[c] = fmaxf(v, 0.0f);
    }
    outbuf[idx] = s;
}

__global__ void final_reduce_kernel(const float* __restrict__ part,
                                    const float* __restrict__ bias,
                                    float* __restrict__ out) {
    int idx = blockIdx.x * blockDim.x + threadIdx.x;
    if (idx >= NGRAPH * 128) return;
    float s = 0.0f;
    #pragma unroll
    for (int z = 0; z < 8; z++) s += part[idx + z * NGRAPH * 128];
    out[idx] = s + __ldg(bias + (idx & 127));
}

// ---------------------------------------------------------------------------
extern "C" void kernel_launch(void* const* d_in, const int* in_sizes, int n_in,
                              void* d_out, int out_size) {
    const float* x     = (const float*)d_in[0];
    const int*   ei    = (const int*)  d_in[1];
    const int*   src   = ei;
    const int*   dst   = ei + NEDGES;
    const int*   batch = (const int*)  d_in[2];
    const float* fp    = (const float*)d_in[3];
    const float* c1w1 = (const float*)d_in[4],  *c1b1 = (const float*)d_in[5];
    const float* c1w2 = (const float*)d_in[6],  *c1b2 = (const float*)d_in[7];
    const float* c2w1 = (const float*)d_in[8],  *c2b1 = (const float*)d_in[9];
    const float* c2w2 = (const float*)d_in[10], *c2b2 = (const float*)d_in[11];
    const float* c3w1 = (const float*)d_in[12], *c3b1 = (const float*)d_in[13];
    const float* c3w2 = (const float*)d_in[14], *c3b2 = (const float*)d_in[15];
    const float* bn1g = (const float*)d_in[16], *bn1b = (const float*)d_in[17];
    const float* bn2g = (const float*)d_in[18], *bn2b = (const float*)d_in[19];
    const float* bn3g = (const float*)d_in[20], *bn3b = (const float*)d_in[21];
    const float* o1w  = (const float*)d_in[22], *o1b  = (const float*)d_in[23];
    const float* obng = (const float*)d_in[24], *obnb = (const float*)d_in[25];
    const float* o3w  = (const float*)d_in[26], *o3b  = (const float*)d_in[27];
    float* out = (float*)d_out;

    float *aggr, *tmp, *h, *pool;
    int *deg, *cursor, *rowptr, *srclist, *gstart;
    cudaGetSymbolAddress((void**)&aggr,    g_aggr);
    cudaGetSymbolAddress((void**)&tmp,     g_tmp);
    cudaGetSymbolAddress((void**)&h,       g_h);
    cudaGetSymbolAddress((void**)&pool,    g_pool);
    cudaGetSymbolAddress((void**)&deg,     g_deg);
    cudaGetSymbolAddress((void**)&cursor,  g_cursor);
    cudaGetSymbolAddress((void**)&rowptr,  g_rowptr);
    cudaGetSymbolAddress((void**)&srclist, g_srclist);
    cudaGetSymbolAddress((void**)&gstart,  g_gstart);

    cudaFuncSetAttribute(mma_gemm_kernel<1,0>, cudaFuncAttributeMaxDynamicSharedMemorySize, GEMM_SMEM);
    cudaFuncSetAttribute(mma_gemm_kernel<2,0>, cudaFuncAttributeMaxDynamicSharedMemorySize, GEMM_SMEM);
    cudaFuncSetAttribute(mma_gemm_kernel<0,1>, cudaFuncAttributeMaxDynamicSharedMemorySize, GEMM_SMEM);

    const int T = 256;
    const int gy = (NNODES + 127) / 128;   // 782 row tiles

    // ---- CSR build (once; reused by all 3 convs) ----
    zero_deg_kernel<<<(NNODES + T - 1) / T, T>>>(deg);
    hist_kernel<<<(NEDGES + T - 1) / T, T>>>(dst, deg);
    scan_kernel<<<1, 1024>>>(deg, rowptr, cursor);
    fill_kernel<<<(NEDGES + T - 1) / T, T>>>(src, dst, cursor, srclist);
    gstart_kernel<<<3, 256>>>(batch, gstart);
    fp_copy_kernel<<<dim3((1536 + T - 1) / T, NGRAPH), T>>>((const float4*)fp, (float4*)pool);

    // ---- conv1 (64 -> 128 -> 128) ----
    gather_aggr_kernel<4><<<(NNODES * 16 + T - 1) / T, T>>>((const float4*)x, rowptr, srclist, (float4*)aggr);
    mma_gemm_kernel<1,0><<<dim3(1, gy), T, GEMM_SMEM>>>(NNODES, 128, 64, 64,  aggr, c1w1, c1b1, nullptr, nullptr, tmp);
    mma_gemm_kernel<2,0><<<dim3(1, gy), T, GEMM_SMEM>>>(NNODES, 128, 128, 128, tmp,  c1w2, c1b2, bn1g, bn1b, h);
    seg_pool_kernel<<<NGRAPH, 128>>>(h, gstart, pool, 128, 0);

    // ---- conv2 (128 -> 128 -> 128) ----
    gather_aggr_kernel<5><<<(NNODES * 32 + T - 1) / T, T>>>((const float4*)h, rowptr, srclist, (float4*)aggr);
    mma_gemm_kernel<1,0><<<dim3(1, gy), T, GEMM_SMEM>>>(NNODES, 128, 128, 128, aggr, c2w1, c2b1, nullptr, nullptr, tmp);
    mma_gemm_kernel<2,0><<<dim3(1, gy), T, GEMM_SMEM>>>(NNODES, 128, 128, 128, tmp,  c2w2, c2b2, bn2g, bn2b, aggr);
    seg_pool_kernel<<<NGRAPH, 128>>>(aggr, gstart, pool, 128, 128);

    // ---- conv3 (128 -> 256 -> 256) ----
    gather_aggr_kernel<5><<<(NNODES * 32 + T - 1) / T, T>>>((const float4*)aggr, rowptr, srclist, (float4*)h);
    mma_gemm_kernel<1,0><<<dim3(2, gy), T, GEMM_SMEM>>>(NNODES, 256, 128, 128, h,   c3w1, c3b1, nullptr, nullptr, tmp);
    mma_gemm_kernel<2,0><<<dim3(2, gy), T, GEMM_SMEM>>>(NNODES, 256, 256, 256, tmp, c3w2, c3b2, bn3g, bn3b, h);
    seg_pool_kernel<<<NGRAPH, 256>>>(h, gstart, pool, 256, 256);

    // ---- readout GEMM1: split-K=4, partials in g_aggr, reduce -> tmp ----
    mma_gemm_kernel<0,1><<<dim3(3328 / 128, 4, 4), T, GEMM_SMEM>>>(NGRAPH, 3328, 1664, RDIM, pool, o1w, nullptr, nullptr, nullptr, aggr);
    readout_reduce_kernel<<<(NGRAPH * 832 + T - 1) / T, T>>>((const float4*)aggr, o1b, obng, obnb, (float4*)tmp);

    // ---- readout GEMM2: split-K=8, partials in g_h, reduce -> out ----
    mma_gemm_kernel<0,1><<<dim3(1, 4, 8), T, GEMM_SMEM>>>(NGRAPH, 128, 416, 3328, tmp, o3w, nullptr, nullptr, nullptr, h);
    final_reduce_kernel<<<(NGRAPH * 128 + T - 1) / T, T>>>(h, o3b, out);
}

// round 7
// speedup vs baseline: 3.9463x; 1.1179x over previous
#include <cuda_runtime.h>
#include <cuda_fp16.h>
#include <cstdint>

#define NNODES 100000
#define NEDGES 1600000
#define NGRAPH 512
#define RDIM   6656

// ---- static device scratch (no allocations allowed) ----
static __device__ __align__(16) float g_aggr[NNODES * 256];
static __device__ __align__(16) float g_tmp [NNODES * 256];
static __device__ __align__(16) float g_h   [NNODES * 256];
static __device__ __align__(16) float g_pool[NGRAPH * RDIM];
static __device__ int g_deg[NNODES];
static __device__ int g_cursor[NNODES];
static __device__ int g_rowptr[NNODES + 1];
static __device__ int g_srclist[NEDGES];
static __device__ int g_gstart[NGRAPH + 1];

// ---------------------------------------------------------------------------
// CSR build
// ---------------------------------------------------------------------------
__global__ void zero_deg_kernel(int* __restrict__ deg) {
    int i = blockIdx.x * blockDim.x + threadIdx.x;
    if (i < NNODES) deg[i] = 0;
}
__global__ void hist_kernel(const int* __restrict__ edst, int* __restrict__ deg) {
    int e = blockIdx.x * blockDim.x + threadIdx.x;
    if (e < NEDGES) atomicAdd(&deg[__ldg(edst + e)], 1);
}
__global__ __launch_bounds__(1024) void scan_kernel(const int* __restrict__ deg,
                                                    int* __restrict__ rowptr,
                                                    int* __restrict__ cursor) {
    __shared__ int sums[1024];
    const int t = threadIdx.x;
    const int chunk = (NNODES + 1023) / 1024;
    const int beg = t * chunk;
    const int end = min(beg + chunk, NNODES);
    int s = 0;
    for (int k = beg; k < end; k++) s += deg[k];
    sums[t] = s;
    __syncthreads();
    for (int off = 1; off < 1024; off <<= 1) {
        int v = (t >= off) ? sums[t - off] : 0;
        __syncthreads();
        sums[t] += v;
        __syncthreads();
    }
    int run = sums[t] - s;
    for (int k = beg; k < end; k++) {
        rowptr[k] = run;
        cursor[k] = run;
        run += deg[k];
    }
    if (t == 1023) rowptr[NNODES] = sums[1023];
}
__global__ void fill_kernel(const int* __restrict__ esrc, const int* __restrict__ edst,
                            int* __restrict__ cursor, int* __restrict__ srclist) {
    int e = blockIdx.x * blockDim.x + threadIdx.x;
    if (e >= NEDGES) return;
    int d = __ldg(edst + e);
    int pos = atomicAdd(&cursor[d], 1);
    srclist[pos] = __ldg(esrc + e);
}
__global__ void gstart_kernel(const int* __restrict__ batch, int* __restrict__ gstart) {
    int g = blockIdx.x * blockDim.x + threadIdx.x;
    if (g > NGRAPH) return;
    if (g == NGRAPH) { gstart[NGRAPH] = NNODES; return; }
    int lo = 0, hi = NNODES;
    while (lo < hi) {
        int mid = (lo + hi) >> 1;
        if (__ldg(batch + mid) < g) lo = mid + 1; else hi = mid;
    }
    gstart[g] = lo;
}

// ---------------------------------------------------------------------------
// gather aggregation: aggr[i] = feat[i] + sum_{s in adj(i)} feat[s]
// ---------------------------------------------------------------------------
template<int F4S>
__global__ void gather_aggr_kernel(const float4* __restrict__ feat,
                                   const int* __restrict__ rowptr,
                                   const int* __restrict__ srclist,
                                   float4* __restrict__ aggr) {
    constexpr int F4 = 1 << F4S;
    constexpr int L = (F4 < 32) ? F4 : 32;
    constexpr int VPT = F4 / L;
    constexpr int NPB = 256 / L;
    int i = blockIdx.x * NPB + threadIdx.x / L;
    if (i >= NNODES) return;
    int c = threadIdx.x % L;

    float4 acc[VPT];
    #pragma unroll
    for (int v = 0; v < VPT; v++)
        acc[v] = __ldg(&feat[(i << F4S) + c + v * L]);

    int j = __ldg(rowptr + i);
    const int end = __ldg(rowptr + i + 1);
    for (; j + 1 < end; j += 2) {
        int s0 = __ldg(srclist + j);
        int s1 = __ldg(srclist + j + 1);
        #pragma unroll
        for (int v = 0; v < VPT; v++) {
            float4 t0 = __ldg(&feat[(s0 << F4S) + c + v * L]);
            float4 t1 = __ldg(&feat[(s1 << F4S) + c + v * L]);
            acc[v].x += t0.x + t1.x; acc[v].y += t0.y + t1.y;
            acc[v].z += t0.z + t1.z; acc[v].w += t0.w + t1.w;
        }
    }
    if (j < end) {
        int s0 = __ldg(srclist + j);
        #pragma unroll
        for (int v = 0; v < VPT; v++) {
            float4 t0 = __ldg(&feat[(s0 << F4S) + c + v * L]);
            acc[v].x += t0.x; acc[v].y += t0.y; acc[v].z += t0.z; acc[v].w += t0.w;
        }
    }
    #pragma unroll
    for (int v = 0; v < VPT; v++)
        aggr[(i << F4S) + c + v * L] = acc[v];
}

// ---------------------------------------------------------------------------
// pools / copies / reductions
// ---------------------------------------------------------------------------
__global__ void seg_pool_kernel(const float* __restrict__ feat,
                                const int* __restrict__ gstart,
                                float* __restrict__ pool,
                                int F, int off) {
    int g = blockIdx.x;
    int t = threadIdx.x;
    int beg = __ldg(gstart + g), end = __ldg(gstart + g + 1);
    float a0 = 0.f, a1 = 0.f;
    int r = beg;
    for (; r + 1 < end; r += 2) {
        a0 += __ldg(feat + (long long)r * F + t);
        a1 += __ldg(feat + (long long)(r + 1) * F + t);
    }
    if (r < end) a0 += __ldg(feat + (long long)r * F + t);
    pool[(long long)g * RDIM + off + t] = a0 + a1;
}
__global__ void fp_copy_kernel(const float4* __restrict__ fp, float4* __restrict__ pool) {
    int col = blockIdx.x * blockDim.x + threadIdx.x;
    int row = blockIdx.y;
    if (col >= 1536) return;
    pool[row * (RDIM / 4) + 128 + col] = fp[row * 1536 + col];
}
__global__ void readout_reduce_kernel(const float4* __restrict__ part,
                                      const float* __restrict__ bias,
                                      const float* __restrict__ bng,
                                      const float* __restrict__ bnb,
                                      float4* __restrict__ outbuf) {
    const int N4 = 3328 / 4;
    int idx = blockIdx.x * blockDim.x + threadIdx.x;
    if (idx >= NGRAPH * N4) return;
    const long long SZ4 = (long long)NGRAPH * N4;
    int col = (idx % N4) * 4;
    float4 s = part[idx];
    #pragma unroll
    for (int z = 1; z < 4; z++) {
        float4 t = part[idx + z * SZ4];
        s.x += t.x; s.y += t.y; s.z += t.z; s.w += t.w;
    }
    const float bninv = rsqrtf(1.0f + 1e-5f);
    float* sp = &s.x;
    #pragma unroll
    for (int c = 0; c < 4; c++) {
        float v = (sp[c] + __ldg(bias + col + c)) * (__ldg(bng + col + c) * bninv) + __ldg(bnb + col + c);
        sp[c] = fmaxf(v, 0.0f);
    }
    outbuf[idx] = s;
}
__global__ void final_reduce_kernel(const float* __restrict__ part,
                                    const float* __restrict__ bias,
                                    float* __restrict__ out) {
    int idx = blockIdx.x * blockDim.x + threadIdx.x;
    if (idx >= NGRAPH * 128) return;
    float s = 0.0f;
    #pragma unroll
    for (int z = 0; z < 8; z++) s += part[idx + z * NGRAPH * 128];
    out[idx] = s + __ldg(bias + (idx & 127));
}

// ---------------------------------------------------------------------------
// FP16 tensor-core GEMM (mma.sync m16n8k16, fp32 accum), ldmatrix fragments.
// BM=BN=128, BK=32, 256 threads (8 warps 2x4), warp tile 64x32, double-buffered.
// SPLIT=1: grid.z splits K; raw partials to C + bz*M*Nn.
// EPI: 0 = +bias, 1 = relu(+bias), 2 = relu(bn(+bias))
// ---------------------------------------------------------------------------
#define SKA2 40    // A row stride in halves (128 rows)
#define SKB2 136   // B row stride in halves (32 rows)

__device__ __forceinline__ uint32_t smem_u32(const void* p) {
    uint32_t a;
    asm("{ .reg .u64 t; cvta.to.shared.u64 t, %1; cvt.u32.u64 %0, t; }" : "=r"(a) : "l"(p));
    return a;
}
#define LDMATRIX_X4(r0, r1, r2, r3, addr) \
    asm volatile("ldmatrix.sync.aligned.m8n8.x4.shared.b16 {%0,%1,%2,%3}, [%4];" \
        : "=r"(r0), "=r"(r1), "=r"(r2), "=r"(r3) : "r"(addr))
#define LDMATRIX_X4_T(r0, r1, r2, r3, addr) \
    asm volatile("ldmatrix.sync.aligned.m8n8.x4.trans.shared.b16 {%0,%1,%2,%3}, [%4];" \
        : "=r"(r0), "=r"(r1), "=r"(r2), "=r"(r3) : "r"(addr))

template<int EPI, int SPLIT>
__global__ __launch_bounds__(256, 2) void hgemm_kernel(
    int M, int Nn, int K, int ldA,
    const float* __restrict__ A, const float* __restrict__ B,
    const float* __restrict__ bias,
    const float* __restrict__ bng, const float* __restrict__ bnb,
    float* __restrict__ C)
{
    __shared__ __align__(16) __half As[2][128 * SKA2];
    __shared__ __align__(16) __half Bs[2][32 * SKB2];

    const int tid = threadIdx.x, bx = blockIdx.x, by = blockIdx.y, bz = blockIdx.z;
    const int warp = tid >> 5, lane = tid & 31;
    const int wm = (warp >> 2) * 64;
    const int wn = (warp & 3) * 32;
    const int lr = lane >> 2;
    const int lc = lane & 3;

    const long long koff = (long long)bz * K;

    // A staging: 128 rows x 32 k; thread -> (row tid>>1, 16 k's)
    const int arow = tid >> 1;
    const int akb = (tid & 1) * 16;
    const int rowg = by * 128 + arow;
    const bool aok = rowg < M;
    const float* Ap = A + (long long)rowg * ldA + koff + akb;

    // B staging: 32 rows x 128 n; thread -> (row tid>>3, 16 n's)
    const int brow = tid >> 3;
    const int bn0 = (tid & 7) * 16;
    const float* Bp = B + (koff + brow) * (long long)Nn + (long long)bx * 128 + bn0;

    float4 ra[4], rb[4];
    const float4 z4 = make_float4(0.f, 0.f, 0.f, 0.f);

    auto loadT = [&](int kk) {
        #pragma unroll
        for (int q = 0; q < 4; q++)
            ra[q] = aok ? __ldg((const float4*)(Ap + kk + 4 * q)) : z4;
        #pragma unroll
        for (int q = 0; q < 4; q++)
            rb[q] = __ldg((const float4*)(Bp + (long long)kk * Nn + 4 * q));
    };
    auto storeT = [&](int buf) {
        __half2 ha[8];
        #pragma unroll
        for (int q = 0; q < 4; q++) {
            ha[2*q]   = __floats2half2_rn(ra[q].x, ra[q].y);
            ha[2*q+1] = __floats2half2_rn(ra[q].z, ra[q].w);
        }
        uint4* da = (uint4*)&As[buf][arow * SKA2 + akb];
        da[0] = *(uint4*)&ha[0];
        da[1] = *(uint4*)&ha[4];
        __half2 hb[8];
        #pragma unroll
        for (int q = 0; q < 4; q++) {
            hb[2*q]   = __floats2half2_rn(rb[q].x, rb[q].y);
            hb[2*q+1] = __floats2half2_rn(rb[q].z, rb[q].w);
        }
        uint4* db = (uint4*)&Bs[buf][brow * SKB2 + bn0];
        db[0] = *(uint4*)&hb[0];
        db[1] = *(uint4*)&hb[4];
    };

    float acc[4][4][4];
    #pragma unroll
    for (int i = 0; i < 4; i++)
        #pragma unroll
        for (int j = 0; j < 4; j++)
            #pragma unroll
            for (int t = 0; t < 4; t++) acc[i][j][t] = 0.0f;

    // ldmatrix lane-address components
    const int a_r = lane & 15, a_s = lane >> 4;          // A: row sel + k-half sel
    const int b_k = lane & 7,  b_s = lane >> 3;          // B: k row + {k-half, n-half} sel

    auto compute = [&](int buf) {
        const uint32_t aB = smem_u32(&As[buf][0]);
        const uint32_t bB = smem_u32(&Bs[buf][0]);
        #pragma unroll
        for (int ks = 0; ks < 32; ks += 16) {
            uint32_t af[4][4], bf[4][2];
            #pragma unroll
            for (int mt = 0; mt < 4; mt++) {
                uint32_t addr = aB + (uint32_t)(((wm + mt * 16 + a_r) * SKA2 + ks + a_s * 8) * 2);
                LDMATRIX_X4(af[mt][0], af[mt][1], af[mt][2], af[mt][3], addr);
            }
            #pragma unroll
            for (int np = 0; np < 2; np++) {
                uint32_t addr = bB + (uint32_t)(((ks + (b_s & 1) * 8 + b_k) * SKB2 + wn + np * 16 + (b_s >> 1) * 8) * 2);
                uint32_t r0, r1, r2, r3;
                LDMATRIX_X4_T(r0, r1, r2, r3, addr);
                bf[2*np][0] = r0; bf[2*np][1] = r1;
                bf[2*np+1][0] = r2; bf[2*np+1][1] = r3;
            }
            #pragma unroll
            for (int mt = 0; mt < 4; mt++)
                #pragma unroll
                for (int nt = 0; nt < 4; nt++) {
                    asm volatile(
                        "mma.sync.aligned.m16n8k16.row.col.f32.f16.f16.f32 "
                        "{%0,%1,%2,%3}, {%4,%5,%6,%7}, {%8,%9}, {%0,%1,%2,%3};"
                        : "+f"(acc[mt][nt][0]), "+f"(acc[mt][nt][1]),
                          "+f"(acc[mt][nt][2]), "+f"(acc[mt][nt][3])
                        : "r"(af[mt][0]), "r"(af[mt][1]), "r"(af[mt][2]), "r"(af[mt][3]),
                          "r"(bf[nt][0]), "r"(bf[nt][1]));
                }
        }
    };

    const int nIter = K / 32;
    loadT(0);
    storeT(0);
    __syncthreads();
    for (int it = 0; it < nIter; it++) {
        int buf = it & 1;
        if (it + 1 < nIter) loadT((it + 1) * 32);
        compute(buf);
        if (it + 1 < nIter) storeT(buf ^ 1);
        __syncthreads();
    }

    if (SPLIT) {
        float* Cz = C + (long long)bz * M * Nn;
        #pragma unroll
        for (int mt = 0; mt < 4; mt++) {
            int r0 = by * 128 + wm + mt * 16 + lr;
            int r1 = r0 + 8;
            #pragma unroll
            for (int nt = 0; nt < 4; nt++) {
                int col = bx * 128 + wn + nt * 8 + 2 * lc;
                if (r0 < M) *(float2*)&Cz[(long long)r0 * Nn + col] = make_float2(acc[mt][nt][0], acc[mt][nt][1]);
                if (r1 < M) *(float2*)&Cz[(long long)r1 * Nn + col] = make_float2(acc[mt][nt][2], acc[mt][nt][3]);
            }
        }
        return;
    }

    const float bninv = rsqrtf(1.0f + 1e-5f);
    #pragma unroll
    for (int mt = 0; mt < 4; mt++) {
        int r0 = by * 128 + wm + mt * 16 + lr;
        int r1 = r0 + 8;
        #pragma unroll
        for (int nt = 0; nt < 4; nt++) {
            int col = bx * 128 + wn + nt * 8 + 2 * lc;
            float b0 = __ldg(bias + col);
            float b1 = __ldg(bias + col + 1);
            float g0 = 1.f, g1 = 1.f, be0 = 0.f, be1 = 0.f;
            if (EPI == 2) {
                g0 = __ldg(bng + col) * bninv;  g1 = __ldg(bng + col + 1) * bninv;
                be0 = __ldg(bnb + col);         be1 = __ldg(bnb + col + 1);
            }
            float v00 = acc[mt][nt][0] + b0, v01 = acc[mt][nt][1] + b1;
            float v10 = acc[mt][nt][2] + b0, v11 = acc[mt][nt][3] + b1;
            if (EPI == 2) {
                v00 = v00 * g0 + be0; v01 = v01 * g1 + be1;
                v10 = v10 * g0 + be0; v11 = v11 * g1 + be1;
            }
            if (EPI >= 1) {
                v00 = fmaxf(v00, 0.f); v01 = fmaxf(v01, 0.f);
                v10 = fmaxf(v10, 0.f); v11 = fmaxf(v11, 0.f);
            }
            if (r0 < M) *(float2*)&C[(long long)r0 * Nn + col] = make_float2(v00, v01);
            if (r1 < M) *(float2*)&C[(long long)r1 * Nn + col] = make_float2(v10, v11);
        }
    }
}

// ---------------------------------------------------------------------------
extern "C" void kernel_launch(void* const* d_in, const int* in_sizes, int n_in,
                              void* d_out, int out_size) {
    const float* x     = (const float*)d_in[0];
    const int*   ei    = (const int*)  d_in[1];
    const int*   src   = ei;
    const int*   dst   = ei + NEDGES;
    const int*   batch = (const int*)  d_in[2];
    const float* fp    = (const float*)d_in[3];
    const float* c1w1 = (const float*)d_in[4],  *c1b1 = (const float*)d_in[5];
    const float* c1w2 = (const float*)d_in[6],  *c1b2 = (const float*)d_in[7];
    const float* c2w1 = (const float*)d_in[8],  *c2b1 = (const float*)d_in[9];
    const float* c2w2 = (const float*)d_in[10], *c2b2 = (const float*)d_in[11];
    const float* c3w1 = (const float*)d_in[12], *c3b1 = (const float*)d_in[13];
    const float* c3w2 = (const float*)d_in[14], *c3b2 = (const float*)d_in[15];
    const float* bn1g = (const float*)d_in[16], *bn1b = (const float*)d_in[17];
    const float* bn2g = (const float*)d_in[18], *bn2b = (const float*)d_in[19];
    const float* bn3g = (const float*)d_in[20], *bn3b = (const float*)d_in[21];
    const float* o1w  = (const float*)d_in[22], *o1b  = (const float*)d_in[23];
    const float* obng = (const float*)d_in[24], *obnb = (const float*)d_in[25];
    const float* o3w  = (const float*)d_in[26], *o3b  = (const float*)d_in[27];
    float* out = (float*)d_out;

    float *aggr, *tmp, *h, *pool;
    int *deg, *cursor, *rowptr, *srclist, *gstart;
    cudaGetSymbolAddress((void**)&aggr,    g_aggr);
    cudaGetSymbolAddress((void**)&tmp,     g_tmp);
    cudaGetSymbolAddress((void**)&h,       g_h);
    cudaGetSymbolAddress((void**)&pool,    g_pool);
    cudaGetSymbolAddress((void**)&deg,     g_deg);
    cudaGetSymbolAddress((void**)&cursor,  g_cursor);
    cudaGetSymbolAddress((void**)&rowptr,  g_rowptr);
    cudaGetSymbolAddress((void**)&srclist, g_srclist);
    cudaGetSymbolAddress((void**)&gstart,  g_gstart);

    const int T = 256;
    const int gy = (NNODES + 127) / 128;   // 782 row tiles

    // ---- CSR build (once; reused by all 3 convs) ----
    zero_deg_kernel<<<(NNODES + T - 1) / T, T>>>(deg);
    hist_kernel<<<(NEDGES + T - 1) / T, T>>>(dst, deg);
    scan_kernel<<<1, 1024>>>(deg, rowptr, cursor);
    fill_kernel<<<(NEDGES + T - 1) / T, T>>>(src, dst, cursor, srclist);
    gstart_kernel<<<3, 256>>>(batch, gstart);
    fp_copy_kernel<<<dim3((1536 + T - 1) / T, NGRAPH), T>>>((const float4*)fp, (float4*)pool);

    // ---- conv1 (64 -> 128 -> 128) ----
    gather_aggr_kernel<4><<<(NNODES * 16 + T - 1) / T, T>>>((const float4*)x, rowptr, srclist, (float4*)aggr);
    hgemm_kernel<1,0><<<dim3(1, gy), T>>>(NNODES, 128, 64, 64,  aggr, c1w1, c1b1, nullptr, nullptr, tmp);
    hgemm_kernel<2,0><<<dim3(1, gy), T>>>(NNODES, 128, 128, 128, tmp,  c1w2, c1b2, bn1g, bn1b, h);
    seg_pool_kernel<<<NGRAPH, 128>>>(h, gstart, pool, 128, 0);

    // ---- conv2 (128 -> 128 -> 128) ----
    gather_aggr_kernel<5><<<(NNODES * 32 + T - 1) / T, T>>>((const float4*)h, rowptr, srclist, (float4*)aggr);
    hgemm_kernel<1,0><<<dim3(1, gy), T>>>(NNODES, 128, 128, 128, aggr, c2w1, c2b1, nullptr, nullptr, tmp);
    hgemm_kernel<2,0><<<dim3(1, gy), T>>>(NNODES, 128, 128, 128, tmp,  c2w2, c2b2, bn2g, bn2b, aggr);
    seg_pool_kernel<<<NGRAPH, 128>>>(aggr, gstart, pool, 128, 128);

    // ---- conv3 (128 -> 256 -> 256) ----
    gather_aggr_kernel<5><<<(NNODES * 32 + T - 1) / T, T>>>((const float4*)aggr, rowptr, srclist, (float4*)h);
    hgemm_kernel<1,0><<<dim3(2, gy), T>>>(NNODES, 256, 128, 128, h,   c3w1, c3b1, nullptr, nullptr, tmp);
    hgemm_kernel<2,0><<<dim3(2, gy), T>>>(NNODES, 256, 256, 256, tmp, c3w2, c3b2, bn3g, bn3b, h);
    seg_pool_kernel<<<NGRAPH, 256>>>(h, gstart, pool, 256, 256);

    // ---- readout GEMM1: split-K=4, partials in g_aggr, reduce -> tmp ----
    hgemm_kernel<0,1><<<dim3(3328 / 128, 4, 4), T>>>(NGRAPH, 3328, 1664, RDIM, pool, o1w, nullptr, nullptr, nullptr, aggr);
    readout_reduce_kernel<<<(NGRAPH * 832 + T - 1) / T, T>>>((const float4*)aggr, o1b, obng, obnb, (float4*)tmp);

    // ---- readout GEMM2: split-K=8, partials in g_h, reduce -> out ----
    hgemm_kernel<0,1><<<dim3(1, 4, 8), T>>>(NGRAPH, 128, 416, 3328, tmp, o3w, nullptr, nullptr, nullptr, h);
    final_reduce_kernel<<<(NGRAPH * 128 + T - 1) / T, T>>>(h, o3b, out);
}

// round 8
// speedup vs baseline: 4.3391x; 1.0995x over previous
#include <cuda_runtime.h>
#include <cuda_fp16.h>
#include <cstdint>

#define NNODES 100000
#define NEDGES 1600000
#define NGRAPH 512
#define RDIM   6656

// ---- static device scratch (no allocations allowed) ----
static __device__ __align__(16) __half g_xh  [NNODES * 64];
static __device__ __align__(16) __half g_aggrh[NNODES * 256];
static __device__ __align__(16) __half g_tmph [NNODES * 256];
static __device__ __align__(16) __half g_hh   [NNODES * 256];
static __device__ __align__(16) float  g_scr  [8 * 1024 * 1024];   // split-K partials
static __device__ __align__(16) float  g_pool [NGRAPH * RDIM];
static __device__ int g_deg[NNODES];
static __device__ int g_cursor[NNODES];
static __device__ int g_rowptr[NNODES + 1];
static __device__ int g_srclist[NEDGES];
static __device__ int g_gstart[NGRAPH + 1];

// ---------------------------------------------------------------------------
// CSR build
// ---------------------------------------------------------------------------
__global__ void zero_deg_kernel(int* __restrict__ deg) {
    int i = blockIdx.x * blockDim.x + threadIdx.x;
    if (i < NNODES) deg[i] = 0;
}
__global__ void hist_kernel(const int* __restrict__ edst, int* __restrict__ deg) {
    int e = blockIdx.x * blockDim.x + threadIdx.x;
    if (e < NEDGES) atomicAdd(&deg[__ldg(edst + e)], 1);
}
__global__ __launch_bounds__(1024) void scan_kernel(const int* __restrict__ deg,
                                                    int* __restrict__ rowptr,
                                                    int* __restrict__ cursor) {
    __shared__ int sums[1024];
    const int t = threadIdx.x;
    const int chunk = (NNODES + 1023) / 1024;
    const int beg = t * chunk;
    const int end = min(beg + chunk, NNODES);
    int s = 0;
    for (int k = beg; k < end; k++) s += deg[k];
    sums[t] = s;
    __syncthreads();
    for (int off = 1; off < 1024; off <<= 1) {
        int v = (t >= off) ? sums[t - off] : 0;
        __syncthreads();
        sums[t] += v;
        __syncthreads();
    }
    int run = sums[t] - s;
    for (int k = beg; k < end; k++) {
        rowptr[k] = run;
        cursor[k] = run;
        run += deg[k];
    }
    if (t == 1023) rowptr[NNODES] = sums[1023];
}
__global__ void fill_kernel(const int* __restrict__ esrc, const int* __restrict__ edst,
                            int* __restrict__ cursor, int* __restrict__ srclist) {
    int e = blockIdx.x * blockDim.x + threadIdx.x;
    if (e >= NEDGES) return;
    int d = __ldg(edst + e);
    int pos = atomicAdd(&cursor[d], 1);
    srclist[pos] = __ldg(esrc + e);
}
__global__ void gstart_kernel(const int* __restrict__ batch, int* __restrict__ gstart) {
    int g = blockIdx.x * blockDim.x + threadIdx.x;
    if (g > NGRAPH) return;
    if (g == NGRAPH) { gstart[NGRAPH] = NNODES; return; }
    int lo = 0, hi = NNODES;
    while (lo < hi) {
        int mid = (lo + hi) >> 1;
        if (__ldg(batch + mid) < g) lo = mid + 1; else hi = mid;
    }
    gstart[g] = lo;
}

// ---------------------------------------------------------------------------
// fp32 -> fp16 convert (x features)
// ---------------------------------------------------------------------------
__global__ void f2h_kernel(const float2* __restrict__ in, __half2* __restrict__ out, int n2) {
    int i = blockIdx.x * blockDim.x + threadIdx.x;
    if (i < n2) {
        float2 v = __ldg(in + i);
        out[i] = __floats2half2_rn(v.x, v.y);
    }
}

// ---------------------------------------------------------------------------
// fp16 gather: aggr[i] = feat[i] + sum_{s in adj(i)} feat[s]; FH halves per row
// Each lane handles one uint2 = 4 halves; L = FH/4 lanes per node.
// ---------------------------------------------------------------------------
__device__ __forceinline__ float2 h2f2(uint32_t h) {
    return __half22float2(*(__half2*)&h);
}
template<int FH>
__global__ void gather_aggr_h_kernel(const uint2* __restrict__ feat,
                                     const int* __restrict__ rowptr,
                                     const int* __restrict__ srclist,
                                     uint2* __restrict__ aggr) {
    constexpr int L = FH / 4;
    constexpr int NPB = 256 / L;
    int i = blockIdx.x * NPB + threadIdx.x / L;
    if (i >= NNODES) return;
    int c = threadIdx.x % L;

    uint2 v0 = __ldg(&feat[i * L + c]);
    float2 ax = h2f2(v0.x), ay = h2f2(v0.y);

    int j = __ldg(rowptr + i);
    const int end = __ldg(rowptr + i + 1);
    for (; j + 1 < end; j += 2) {
        int s0 = __ldg(srclist + j);
        int s1 = __ldg(srclist + j + 1);
        uint2 t0 = __ldg(&feat[s0 * L + c]);
        uint2 t1 = __ldg(&feat[s1 * L + c]);
        float2 a = h2f2(t0.x), b = h2f2(t0.y), cc = h2f2(t1.x), d = h2f2(t1.y);
        ax.x += a.x + cc.x; ax.y += a.y + cc.y;
        ay.x += b.x + d.x;  ay.y += b.y + d.y;
    }
    if (j < end) {
        int s0 = __ldg(srclist + j);
        uint2 t0 = __ldg(&feat[s0 * L + c]);
        float2 a = h2f2(t0.x), b = h2f2(t0.y);
        ax.x += a.x; ax.y += a.y; ay.x += b.x; ay.y += b.y;
    }
    __half2 r0 = __floats2half2_rn(ax.x, ax.y);
    __half2 r1 = __floats2half2_rn(ay.x, ay.y);
    uint2 o;
    o.x = *(uint32_t*)&r0; o.y = *(uint32_t*)&r1;
    aggr[i * L + c] = o;
}

// ---------------------------------------------------------------------------
// segment pool from fp16: pool[g, off + 2t .. 2t+1] = sum over graph rows
// launch F/2 threads per block, NGRAPH blocks
// ---------------------------------------------------------------------------
__global__ void seg_pool_h_kernel(const __half2* __restrict__ feat,
                                  const int* __restrict__ gstart,
                                  float* __restrict__ pool,
                                  int F2, int off) {
    int g = blockIdx.x;
    int t = threadIdx.x;
    int beg = __ldg(gstart + g), end = __ldg(gstart + g + 1);
    float2 a0 = make_float2(0.f, 0.f), a1 = make_float2(0.f, 0.f);
    int r = beg;
    for (; r + 1 < end; r += 2) {
        float2 v0 = __half22float2(__ldg(feat + (long long)r * F2 + t));
        float2 v1 = __half22float2(__ldg(feat + (long long)(r + 1) * F2 + t));
        a0.x += v0.x; a0.y += v0.y; a1.x += v1.x; a1.y += v1.y;
    }
    if (r < end) {
        float2 v0 = __half22float2(__ldg(feat + (long long)r * F2 + t));
        a0.x += v0.x; a0.y += v0.y;
    }
    pool[(long long)g * RDIM + off + 2 * t]     = a0.x + a1.x;
    pool[(long long)g * RDIM + off + 2 * t + 1] = a0.y + a1.y;
}

__global__ void fp_copy_kernel(const float4* __restrict__ fp, float4* __restrict__ pool) {
    int col = blockIdx.x * blockDim.x + threadIdx.x;
    int row = blockIdx.y;
    if (col >= 1536) return;
    pool[row * (RDIM / 4) + 128 + col] = fp[row * 1536 + col];
}

// ---------------------------------------------------------------------------
// split-K reductions (fixed order). readout_reduce outputs fp16 (feeds GEMM2 A)
// ---------------------------------------------------------------------------
__global__ void readout_reduce_kernel(const float4* __restrict__ part,
                                      const float* __restrict__ bias,
                                      const float* __restrict__ bng,
                                      const float* __restrict__ bnb,
                                      uint2* __restrict__ outh) {
    const int N4 = 3328 / 4;
    int idx = blockIdx.x * blockDim.x + threadIdx.x;
    if (idx >= NGRAPH * N4) return;
    const long long SZ4 = (long long)NGRAPH * N4;
    int col = (idx % N4) * 4;
    float4 s = part[idx];
    #pragma unroll
    for (int z = 1; z < 4; z++) {
        float4 t = part[idx + z * SZ4];
        s.x += t.x; s.y += t.y; s.z += t.z; s.w += t.w;
    }
    const float bninv = rsqrtf(1.0f + 1e-5f);
    float* sp = &s.x;
    #pragma unroll
    for (int c = 0; c < 4; c++) {
        float v = (sp[c] + __ldg(bias + col + c)) * (__ldg(bng + col + c) * bninv) + __ldg(bnb + col + c);
        sp[c] = fmaxf(v, 0.0f);
    }
    __half2 h0 = __floats2half2_rn(s.x, s.y);
    __half2 h1 = __floats2half2_rn(s.z, s.w);
    uint2 o;
    o.x = *(uint32_t*)&h0; o.y = *(uint32_t*)&h1;
    outh[idx] = o;
}
__global__ void final_reduce_kernel(const float* __restrict__ part,
                                    const float* __restrict__ bias,
                                    float* __restrict__ out) {
    int idx = blockIdx.x * blockDim.x + threadIdx.x;
    if (idx >= NGRAPH * 128) return;
    float s = 0.0f;
    #pragma unroll
    for (int z = 0; z < 8; z++) s += part[idx + z * NGRAPH * 128];
    out[idx] = s + __ldg(bias + (idx & 127));
}

// ---------------------------------------------------------------------------
// FP16 tensor-core GEMM (mma.sync m16n8k16, fp32 accum), ldmatrix fragments.
// BM=BN=128, BK=32, 256 threads, warp tile 64x32, double-buffered.
// AH: A operand is fp16 (else fp32). CH: C output fp16 (else fp32).
// SPLIT=1: grid.z splits K; raw fp32 partials to C + bz*M*Nn.
// EPI: 0 = +bias, 1 = relu(+bias), 2 = relu(bn(+bias))
// ---------------------------------------------------------------------------
#define SKA2 40
#define SKB2 136

__device__ __forceinline__ uint32_t smem_u32(const void* p) {
    uint32_t a;
    asm("{ .reg .u64 t; cvta.to.shared.u64 t, %1; cvt.u32.u64 %0, t; }" : "=r"(a) : "l"(p));
    return a;
}
#define LDMATRIX_X4(r0, r1, r2, r3, addr) \
    asm volatile("ldmatrix.sync.aligned.m8n8.x4.shared.b16 {%0,%1,%2,%3}, [%4];" \
        : "=r"(r0), "=r"(r1), "=r"(r2), "=r"(r3) : "r"(addr))
#define LDMATRIX_X4_T(r0, r1, r2, r3, addr) \
    asm volatile("ldmatrix.sync.aligned.m8n8.x4.trans.shared.b16 {%0,%1,%2,%3}, [%4];" \
        : "=r"(r0), "=r"(r1), "=r"(r2), "=r"(r3) : "r"(addr))

template<int EPI, int SPLIT, bool AH, bool CH>
__global__ __launch_bounds__(256, 2) void hgemm_kernel(
    int M, int Nn, int K, int ldA,
    const void* __restrict__ Av, const float* __restrict__ B,
    const float* __restrict__ bias,
    const float* __restrict__ bng, const float* __restrict__ bnb,
    void* __restrict__ Cv)
{
    __shared__ __align__(16) __half As[2][128 * SKA2];
    __shared__ __align__(16) __half Bs[2][32 * SKB2];

    const int tid = threadIdx.x, bx = blockIdx.x, by = blockIdx.y, bz = blockIdx.z;
    const int warp = tid >> 5, lane = tid & 31;
    const int wm = (warp >> 2) * 64;
    const int wn = (warp & 3) * 32;
    const int lr = lane >> 2;
    const int lc = lane & 3;

    const long long koff = (long long)bz * K;

    const int arow = tid >> 1;
    const int akb = (tid & 1) * 16;
    const int rowg = by * 128 + arow;
    const bool aok = rowg < M;
    const float* ApF = AH ? nullptr : ((const float*)Av + (long long)rowg * ldA + koff + akb);
    const __half* ApH = AH ? ((const __half*)Av + (long long)rowg * ldA + koff + akb) : nullptr;

    const int brow = tid >> 3;
    const int bn0 = (tid & 7) * 16;
    const float* Bp = B + (koff + brow) * (long long)Nn + (long long)bx * 128 + bn0;

    float4 ra[4], rb[4];
    uint4 raH[2];
    const float4 z4 = make_float4(0.f, 0.f, 0.f, 0.f);

    auto loadT = [&](int kk) {
        if (AH) {
            if (aok) {
                raH[0] = __ldg((const uint4*)(ApH + kk));
                raH[1] = __ldg((const uint4*)(ApH + kk + 8));
            } else {
                raH[0] = make_uint4(0, 0, 0, 0);
                raH[1] = make_uint4(0, 0, 0, 0);
            }
        } else {
            #pragma unroll
            for (int q = 0; q < 4; q++)
                ra[q] = aok ? __ldg((const float4*)(ApF + kk + 4 * q)) : z4;
        }
        #pragma unroll
        for (int q = 0; q < 4; q++)
            rb[q] = __ldg((const float4*)(Bp + (long long)kk * Nn + 4 * q));
    };
    auto storeT = [&](int buf) {
        uint4* da = (uint4*)&As[buf][arow * SKA2 + akb];
        if (AH) {
            da[0] = raH[0];
            da[1] = raH[1];
        } else {
            __half2 ha[8];
            #pragma unroll
            for (int q = 0; q < 4; q++) {
                ha[2*q]   = __floats2half2_rn(ra[q].x, ra[q].y);
                ha[2*q+1] = __floats2half2_rn(ra[q].z, ra[q].w);
            }
            da[0] = *(uint4*)&ha[0];
            da[1] = *(uint4*)&ha[4];
        }
        __half2 hb[8];
        #pragma unroll
        for (int q = 0; q < 4; q++) {
            hb[2*q]   = __floats2half2_rn(rb[q].x, rb[q].y);
            hb[2*q+1] = __floats2half2_rn(rb[q].z, rb[q].w);
        }
        uint4* db = (uint4*)&Bs[buf][brow * SKB2 + bn0];
        db[0] = *(uint4*)&hb[0];
        db[1] = *(uint4*)&hb[4];
    };

    float acc[4][4][4];
    #pragma unroll
    for (int i = 0; i < 4; i++)
        #pragma unroll
        for (int j = 0; j < 4; j++)
            #pragma unroll
            for (int t = 0; t < 4; t++) acc[i][j][t] = 0.0f;

    const int a_r = lane & 15, a_s = lane >> 4;
    const int b_k = lane & 7,  b_s = lane >> 3;

    auto compute = [&](int buf) {
        const uint32_t aB = smem_u32(&As[buf][0]);
        const uint32_t bB = smem_u32(&Bs[buf][0]);
        #pragma unroll
        for (int ks = 0; ks < 32; ks += 16) {
            uint32_t af[4][4], bf[4][2];
            #pragma unroll
            for (int mt = 0; mt < 4; mt++) {
                uint32_t addr = aB + (uint32_t)(((wm + mt * 16 + a_r) * SKA2 + ks + a_s * 8) * 2);
                LDMATRIX_X4(af[mt][0], af[mt][1], af[mt][2], af[mt][3], addr);
            }
            #pragma unroll
            for (int np = 0; np < 2; np++) {
                uint32_t addr = bB + (uint32_t)(((ks + (b_s & 1) * 8 + b_k) * SKB2 + wn + np * 16 + (b_s >> 1) * 8) * 2);
                uint32_t r0, r1, r2, r3;
                LDMATRIX_X4_T(r0, r1, r2, r3, addr);
                bf[2*np][0] = r0; bf[2*np][1] = r1;
                bf[2*np+1][0] = r2; bf[2*np+1][1] = r3;
            }
            #pragma unroll
            for (int mt = 0; mt < 4; mt++)
                #pragma unroll
                for (int nt = 0; nt < 4; nt++) {
                    asm volatile(
                        "mma.sync.aligned.m16n8k16.row.col.f32.f16.f16.f32 "
                        "{%0,%1,%2,%3}, {%4,%5,%6,%7}, {%8,%9}, {%0,%1,%2,%3};"
                        : "+f"(acc[mt][nt][0]), "+f"(acc[mt][nt][1]),
                          "+f"(acc[mt][nt][2]), "+f"(acc[mt][nt][3])
                        : "r"(af[mt][0]), "r"(af[mt][1]), "r"(af[mt][2]), "r"(af[mt][3]),
                          "r"(bf[nt][0]), "r"(bf[nt][1]));
                }
        }
    };

    const int nIter = K / 32;
    loadT(0);
    storeT(0);
    __syncthreads();
    for (int it = 0; it < nIter; it++) {
        int buf = it & 1;
        if (it + 1 < nIter) loadT((it + 1) * 32);
        compute(buf);
        if (it + 1 < nIter) storeT(buf ^ 1);
        __syncthreads();
    }

    if (SPLIT) {
        float* Cz = (float*)Cv + (long long)bz * M * Nn;
        #pragma unroll
        for (int mt = 0; mt < 4; mt++) {
            int r0 = by * 128 + wm + mt * 16 + lr;
            int r1 = r0 + 8;
            #pragma unroll
            for (int nt = 0; nt < 4; nt++) {
                int col = bx * 128 + wn + nt * 8 + 2 * lc;
                if (r0 < M) *(float2*)&Cz[(long long)r0 * Nn + col] = make_float2(acc[mt][nt][0], acc[mt][nt][1]);
                if (r1 < M) *(float2*)&Cz[(long long)r1 * Nn + col] = make_float2(acc[mt][nt][2], acc[mt][nt][3]);
            }
        }
        return;
    }

    const float bninv = rsqrtf(1.0f + 1e-5f);
    #pragma unroll
    for (int mt = 0; mt < 4; mt++) {
        int r0 = by * 128 + wm + mt * 16 + lr;
        int r1 = r0 + 8;
        #pragma unroll
        for (int nt = 0; nt < 4; nt++) {
            int col = bx * 128 + wn + nt * 8 + 2 * lc;
            float b0 = __ldg(bias + col);
            float b1 = __ldg(bias + col + 1);
            float g0 = 1.f, g1 = 1.f, be0 = 0.f, be1 = 0.f;
            if (EPI == 2) {
                g0 = __ldg(bng + col) * bninv;  g1 = __ldg(bng + col + 1) * bninv;
                be0 = __ldg(bnb + col);         be1 = __ldg(bnb + col + 1);
            }
            float v00 = acc[mt][nt][0] + b0, v01 = acc[mt][nt][1] + b1;
            float v10 = acc[mt][nt][2] + b0, v11 = acc[mt][nt][3] + b1;
            if (EPI == 2) {
                v00 = v00 * g0 + be0; v01 = v01 * g1 + be1;
                v10 = v10 * g0 + be0; v11 = v11 * g1 + be1;
            }
            if (EPI >= 1) {
                v00 = fmaxf(v00, 0.f); v01 = fmaxf(v01, 0.f);
                v10 = fmaxf(v10, 0.f); v11 = fmaxf(v11, 0.f);
            }
            if (CH) {
                __half* Ch = (__half*)Cv;
                if (r0 < M) *(__half2*)&Ch[(long long)r0 * Nn + col] = __floats2half2_rn(v00, v01);
                if (r1 < M) *(__half2*)&Ch[(long long)r1 * Nn + col] = __floats2half2_rn(v10, v11);
            } else {
                float* Cf = (float*)Cv;
                if (r0 < M) *(float2*)&Cf[(long long)r0 * Nn + col] = make_float2(v00, v01);
                if (r1 < M) *(float2*)&Cf[(long long)r1 * Nn + col] = make_float2(v10, v11);
            }
        }
    }
}

// ---------------------------------------------------------------------------
extern "C" void kernel_launch(void* const* d_in, const int* in_sizes, int n_in,
                              void* d_out, int out_size) {
    const float* x     = (const float*)d_in[0];
    const int*   ei    = (const int*)  d_in[1];
    const int*   src   = ei;
    const int*   dst   = ei + NEDGES;
    const int*   batch = (const int*)  d_in[2];
    const float* fp    = (const float*)d_in[3];
    const float* c1w1 = (const float*)d_in[4],  *c1b1 = (const float*)d_in[5];
    const float* c1w2 = (const float*)d_in[6],  *c1b2 = (const float*)d_in[7];
    const float* c2w1 = (const float*)d_in[8],  *c2b1 = (const float*)d_in[9];
    const float* c2w2 = (const float*)d_in[10], *c2b2 = (const float*)d_in[11];
    const float* c3w1 = (const float*)d_in[12], *c3b1 = (const float*)d_in[13];
    const float* c3w2 = (const float*)d_in[14], *c3b2 = (const float*)d_in[15];
    const float* bn1g = (const float*)d_in[16], *bn1b = (const float*)d_in[17];
    const float* bn2g = (const float*)d_in[18], *bn2b = (const float*)d_in[19];
    const float* bn3g = (const float*)d_in[20], *bn3b = (const float*)d_in[21];
    const float* o1w  = (const float*)d_in[22], *o1b  = (const float*)d_in[23];
    const float* obng = (const float*)d_in[24], *obnb = (const float*)d_in[25];
    const float* o3w  = (const float*)d_in[26], *o3b  = (const float*)d_in[27];
    float* out = (float*)d_out;

    __half *xh, *aggrh, *tmph, *hh;
    float *scr, *pool;
    int *deg, *cursor, *rowptr, *srclist, *gstart;
    cudaGetSymbolAddress((void**)&xh,      g_xh);
    cudaGetSymbolAddress((void**)&aggrh,   g_aggrh);
    cudaGetSymbolAddress((void**)&tmph,    g_tmph);
    cudaGetSymbolAddress((void**)&hh,      g_hh);
    cudaGetSymbolAddress((void**)&scr,     g_scr);
    cudaGetSymbolAddress((void**)&pool,    g_pool);
    cudaGetSymbolAddress((void**)&deg,     g_deg);
    cudaGetSymbolAddress((void**)&cursor,  g_cursor);
    cudaGetSymbolAddress((void**)&rowptr,  g_rowptr);
    cudaGetSymbolAddress((void**)&srclist, g_srclist);
    cudaGetSymbolAddress((void**)&gstart,  g_gstart);

    const int T = 256;
    const int gy = (NNODES + 127) / 128;

    // ---- CSR build + input convert ----
    zero_deg_kernel<<<(NNODES + T - 1) / T, T>>>(deg);
    hist_kernel<<<(NEDGES + T - 1) / T, T>>>(dst, deg);
    scan_kernel<<<1, 1024>>>(deg, rowptr, cursor);
    fill_kernel<<<(NEDGES + T - 1) / T, T>>>(src, dst, cursor, srclist);
    gstart_kernel<<<3, 256>>>(batch, gstart);
    fp_copy_kernel<<<dim3((1536 + T - 1) / T, NGRAPH), T>>>((const float4*)fp, (float4*)pool);
    f2h_kernel<<<(NNODES * 32 + T - 1) / T, T>>>((const float2*)x, (__half2*)xh, NNODES * 32);

    // ---- conv1 (64 -> 128 -> 128) ----
    gather_aggr_h_kernel<64><<<(NNODES * 16 + T - 1) / T, T>>>((const uint2*)xh, rowptr, srclist, (uint2*)aggrh);
    hgemm_kernel<1,0,true,true><<<dim3(1, gy), T>>>(NNODES, 128, 64, 64,  aggrh, c1w1, c1b1, nullptr, nullptr, tmph);
    hgemm_kernel<2,0,true,true><<<dim3(1, gy), T>>>(NNODES, 128, 128, 128, tmph,  c1w2, c1b2, bn1g, bn1b, hh);
    seg_pool_h_kernel<<<NGRAPH, 64>>>((const __half2*)hh, gstart, pool, 64, 0);

    // ---- conv2 (128 -> 128 -> 128) ----
    gather_aggr_h_kernel<128><<<(NNODES * 32 + T - 1) / T, T>>>((const uint2*)hh, rowptr, srclist, (uint2*)aggrh);
    hgemm_kernel<1,0,true,true><<<dim3(1, gy), T>>>(NNODES, 128, 128, 128, aggrh, c2w1, c2b1, nullptr, nullptr, tmph);
    hgemm_kernel<2,0,true,true><<<dim3(1, gy), T>>>(NNODES, 128, 128, 128, tmph,  c2w2, c2b2, bn2g, bn2b, hh);
    seg_pool_h_kernel<<<NGRAPH, 64>>>((const __half2*)hh, gstart, pool, 64, 128);

    // ---- conv3 (128 -> 256 -> 256) ----
    gather_aggr_h_kernel<128><<<(NNODES * 32 + T - 1) / T, T>>>((const uint2*)hh, rowptr, srclist, (uint2*)aggrh);
    hgemm_kernel<1,0,true,true><<<dim3(2, gy), T>>>(NNODES, 256, 128, 128, aggrh, c3w1, c3b1, nullptr, nullptr, tmph);
    hgemm_kernel<2,0,true,true><<<dim3(2, gy), T>>>(NNODES, 256, 256, 256, tmph, c3w2, c3b2, bn3g, bn3b, hh);
    seg_pool_h_kernel<<<NGRAPH, 128>>>((const __half2*)hh, gstart, pool, 128, 256);

    // ---- readout GEMM1: A=pool fp32, split-K=4, partials -> scr, reduce -> tmph (fp16) ----
    hgemm_kernel<0,1,false,false><<<dim3(3328 / 128, 4, 4), T>>>(NGRAPH, 3328, 1664, RDIM, pool, o1w, nullptr, nullptr, nullptr, scr);
    readout_reduce_kernel<<<(NGRAPH * 832 + T - 1) / T, T>>>((const float4*)scr, o1b, obng, obnb, (uint2*)tmph);

    // ---- readout GEMM2: A=tmph fp16, split-K=8, partials -> scr(offset), reduce -> out ----
    float* scr2 = scr + 4 * NGRAPH * 3328;
    hgemm_kernel<0,1,true,false><<<dim3(1, 4, 8), T>>>(NGRAPH, 128, 416, 3328, tmph, o3w, nullptr, nullptr, nullptr, scr2);
    final_reduce_kernel<<<(NGRAPH * 128 + T - 1) / T, T>>>(scr2, o3b, out);
}

// round 9
// speedup vs baseline: 4.9254x; 1.1351x over previous
#include <cuda_runtime.h>
#include <cuda_fp16.h>
#include <cstdint>

#define NNODES 100000
#define NEDGES 1600000
#define NGRAPH 512
#define RDIM   6656

// fp16 weight buffer offsets (halves)
#define W_C1W1 0
#define W_C1W2 8192
#define W_C2W1 24576
#define W_C2W2 40960
#define W_C3W1 57344
#define W_C3W2 90112
#define W_O1W  155648
#define W_O3W  22306816
#define W_TOTAL 22732800

// ---- static device scratch (no allocations allowed) ----
static __device__ __align__(16) __half g_xh   [NNODES * 64];
static __device__ __align__(16) __half g_aggrh[NNODES * 256];
static __device__ __align__(16) __half g_tmph [NNODES * 256];
static __device__ __align__(16) __half g_hh   [NNODES * 256];
static __device__ __align__(16) __half g_wh   [W_TOTAL];
static __device__ __align__(16) __half g_poolh[NGRAPH * RDIM];
static __device__ __align__(16) float  g_scr  [8 * 1024 * 1024];
static __device__ int g_deg[NNODES];
static __device__ int g_cursor[NNODES];
static __device__ int g_rowptr[NNODES + 1];
static __device__ int g_srclist[NEDGES];
static __device__ int g_gstart[NGRAPH + 1];

// ---------------------------------------------------------------------------
// CSR build
// ---------------------------------------------------------------------------
__global__ void zero_deg_kernel(int* __restrict__ deg) {
    int i = blockIdx.x * blockDim.x + threadIdx.x;
    if (i < NNODES) deg[i] = 0;
}
__global__ void hist_kernel(const int* __restrict__ edst, int* __restrict__ deg) {
    int e = blockIdx.x * blockDim.x + threadIdx.x;
    if (e < NEDGES) atomicAdd(&deg[__ldg(edst + e)], 1);
}
__global__ __launch_bounds__(1024) void scan_kernel(const int* __restrict__ deg,
                                                    int* __restrict__ rowptr,
                                                    int* __restrict__ cursor) {
    __shared__ int sums[1024];
    const int t = threadIdx.x;
    const int chunk = (NNODES + 1023) / 1024;
    const int beg = t * chunk;
    const int end = min(beg + chunk, NNODES);
    int s = 0;
    for (int k = beg; k < end; k++) s += deg[k];
    sums[t] = s;
    __syncthreads();
    for (int off = 1; off < 1024; off <<= 1) {
        int v = (t >= off) ? sums[t - off] : 0;
        __syncthreads();
        sums[t] += v;
        __syncthreads();
    }
    int run = sums[t] - s;
    for (int k = beg; k < end; k++) {
        rowptr[k] = run;
        cursor[k] = run;
        run += deg[k];
    }
    if (t == 1023) rowptr[NNODES] = sums[1023];
}
__global__ void fill_kernel(const int* __restrict__ esrc, const int* __restrict__ edst,
                            int* __restrict__ cursor, int* __restrict__ srclist) {
    int e = blockIdx.x * blockDim.x + threadIdx.x;
    if (e >= NEDGES) return;
    int d = __ldg(edst + e);
    int pos = atomicAdd(&cursor[d], 1);
    srclist[pos] = __ldg(esrc + e);
}
__global__ void gstart_kernel(const int* __restrict__ batch, int* __restrict__ gstart) {
    int g = blockIdx.x * blockDim.x + threadIdx.x;
    if (g > NGRAPH) return;
    if (g == NGRAPH) { gstart[NGRAPH] = NNODES; return; }
    int lo = 0, hi = NNODES;
    while (lo < hi) {
        int mid = (lo + hi) >> 1;
        if (__ldg(batch + mid) < g) lo = mid + 1; else hi = mid;
    }
    gstart[g] = lo;
}

// ---------------------------------------------------------------------------
// fp32 -> fp16 convert
// ---------------------------------------------------------------------------
__global__ void f2h_kernel(const float2* __restrict__ in, __half2* __restrict__ out, int n2) {
    int i = blockIdx.x * blockDim.x + threadIdx.x;
    if (i < n2) {
        float2 v = __ldg(in + i);
        out[i] = __floats2half2_rn(v.x, v.y);
    }
}

// ---------------------------------------------------------------------------
// fp16 gather
// ---------------------------------------------------------------------------
__device__ __forceinline__ float2 h2f2(uint32_t h) {
    return __half22float2(*(__half2*)&h);
}
template<int FH>
__global__ void gather_aggr_h_kernel(const uint2* __restrict__ feat,
                                     const int* __restrict__ rowptr,
                                     const int* __restrict__ srclist,
                                     uint2* __restrict__ aggr) {
    constexpr int L = FH / 4;
    constexpr int NPB = 256 / L;
    int i = blockIdx.x * NPB + threadIdx.x / L;
    if (i >= NNODES) return;
    int c = threadIdx.x % L;

    uint2 v0 = __ldg(&feat[i * L + c]);
    float2 ax = h2f2(v0.x), ay = h2f2(v0.y);

    int j = __ldg(rowptr + i);
    const int end = __ldg(rowptr + i + 1);
    for (; j + 1 < end; j += 2) {
        int s0 = __ldg(srclist + j);
        int s1 = __ldg(srclist + j + 1);
        uint2 t0 = __ldg(&feat[s0 * L + c]);
        uint2 t1 = __ldg(&feat[s1 * L + c]);
        float2 a = h2f2(t0.x), b = h2f2(t0.y), cc = h2f2(t1.x), d = h2f2(t1.y);
        ax.x += a.x + cc.x; ax.y += a.y + cc.y;
        ay.x += b.x + d.x;  ay.y += b.y + d.y;
    }
    if (j < end) {
        int s0 = __ldg(srclist + j);
        uint2 t0 = __ldg(&feat[s0 * L + c]);
        float2 a = h2f2(t0.x), b = h2f2(t0.y);
        ax.x += a.x; ax.y += a.y; ay.x += b.x; ay.y += b.y;
    }
    __half2 r0 = __floats2half2_rn(ax.x, ax.y);
    __half2 r1 = __floats2half2_rn(ay.x, ay.y);
    uint2 o;
    o.x = *(uint32_t*)&r0; o.y = *(uint32_t*)&r1;
    aggr[i * L + c] = o;
}

// ---------------------------------------------------------------------------
// segment pool -> fp16 pool
// ---------------------------------------------------------------------------
__global__ void seg_pool_h_kernel(const __half2* __restrict__ feat,
                                  const int* __restrict__ gstart,
                                  __half2* __restrict__ pool,
                                  int F2, int off2) {
    int g = blockIdx.x;
    int t = threadIdx.x;
    int beg = __ldg(gstart + g), end = __ldg(gstart + g + 1);
    float2 a0 = make_float2(0.f, 0.f), a1 = make_float2(0.f, 0.f);
    int r = beg;
    for (; r + 1 < end; r += 2) {
        float2 v0 = __half22float2(__ldg(feat + (long long)r * F2 + t));
        float2 v1 = __half22float2(__ldg(feat + (long long)(r + 1) * F2 + t));
        a0.x += v0.x; a0.y += v0.y; a1.x += v1.x; a1.y += v1.y;
    }
    if (r < end) {
        float2 v0 = __half22float2(__ldg(feat + (long long)r * F2 + t));
        a0.x += v0.x; a0.y += v0.y;
    }
    pool[(long long)g * (RDIM / 2) + off2 + t] = __floats2half2_rn(a0.x + a1.x, a0.y + a1.y);
}

// fingerprint: pool[:, 512:6656] = fp (fp32 -> fp16)
__global__ void fp_copy_kernel(const float4* __restrict__ fp, uint2* __restrict__ pool) {
    int col = blockIdx.x * blockDim.x + threadIdx.x;   // float4 col < 1536
    int row = blockIdx.y;
    if (col >= 1536) return;
    float4 v = __ldg(fp + row * 1536 + col);
    __half2 h0 = __floats2half2_rn(v.x, v.y);
    __half2 h1 = __floats2half2_rn(v.z, v.w);
    uint2 o;
    o.x = *(uint32_t*)&h0; o.y = *(uint32_t*)&h1;
    pool[row * (RDIM / 4) + 128 + col] = o;
}

// ---------------------------------------------------------------------------
// split-K reductions (fixed order)
// ---------------------------------------------------------------------------
__global__ void readout_reduce_kernel(const float4* __restrict__ part,
                                      const float* __restrict__ bias,
                                      const float* __restrict__ bng,
                                      const float* __restrict__ bnb,
                                      uint2* __restrict__ outh) {
    const int N4 = 3328 / 4;
    int idx = blockIdx.x * blockDim.x + threadIdx.x;
    if (idx >= NGRAPH * N4) return;
    const long long SZ4 = (long long)NGRAPH * N4;
    int col = (idx % N4) * 4;
    float4 s = part[idx];
    #pragma unroll
    for (int z = 1; z < 4; z++) {
        float4 t = part[idx + z * SZ4];
        s.x += t.x; s.y += t.y; s.z += t.z; s.w += t.w;
    }
    const float bninv = rsqrtf(1.0f + 1e-5f);
    float* sp = &s.x;
    #pragma unroll
    for (int c = 0; c < 4; c++) {
        float v = (sp[c] + __ldg(bias + col + c)) * (__ldg(bng + col + c) * bninv) + __ldg(bnb + col + c);
        sp[c] = fmaxf(v, 0.0f);
    }
    __half2 h0 = __floats2half2_rn(s.x, s.y);
    __half2 h1 = __floats2half2_rn(s.z, s.w);
    uint2 o;
    o.x = *(uint32_t*)&h0; o.y = *(uint32_t*)&h1;
    outh[idx] = o;
}
__global__ void final_reduce_kernel(const float* __restrict__ part,
                                    const float* __restrict__ bias,
                                    float* __restrict__ out) {
    int idx = blockIdx.x * blockDim.x + threadIdx.x;
    if (idx >= NGRAPH * 128) return;
    float s = 0.0f;
    #pragma unroll
    for (int z = 0; z < 8; z++) s += part[idx + z * NGRAPH * 128];
    out[idx] = s + __ldg(bias + (idx & 127));
}

// ---------------------------------------------------------------------------
// All-fp16 tensor-core GEMM with cp.async staging.
// A[M,ldA] fp16, B[K,Nn] fp16. BM=BN=128, BK=32, 256 thr, double-buffered.
// SPLIT=1: grid.z splits K, fp32 partials to C + bz*M*Nn.
// EPI: 0 = +bias, 1 = relu(+bias), 2 = relu(bn(+bias)); CH: fp16 C out.
// ---------------------------------------------------------------------------
#define SKA2 40
#define SKB2 136

__device__ __forceinline__ uint32_t smem_u32(const void* p) {
    uint32_t a;
    asm("{ .reg .u64 t; cvta.to.shared.u64 t, %1; cvt.u32.u64 %0, t; }" : "=r"(a) : "l"(p));
    return a;
}
__device__ __forceinline__ void cp16(uint32_t s, const void* g, int sz) {
    asm volatile("cp.async.cg.shared.global [%0], [%1], 16, %2;" :: "r"(s), "l"(g), "r"(sz));
}
#define CP_COMMIT() asm volatile("cp.async.commit_group;")
#define LDMATRIX_X4(r0, r1, r2, r3, addr) \
    asm volatile("ldmatrix.sync.aligned.m8n8.x4.shared.b16 {%0,%1,%2,%3}, [%4];" \
        : "=r"(r0), "=r"(r1), "=r"(r2), "=r"(r3) : "r"(addr))
#define LDMATRIX_X4_T(r0, r1, r2, r3, addr) \
    asm volatile("ldmatrix.sync.aligned.m8n8.x4.trans.shared.b16 {%0,%1,%2,%3}, [%4];" \
        : "=r"(r0), "=r"(r1), "=r"(r2), "=r"(r3) : "r"(addr))

template<int EPI, int SPLIT, bool CH>
__global__ __launch_bounds__(256, 2) void hgemm16_kernel(
    int M, int Nn, int K, int ldA,
    const __half* __restrict__ A, const __half* __restrict__ B,
    const float* __restrict__ bias,
    const float* __restrict__ bng, const float* __restrict__ bnb,
    void* __restrict__ Cv)
{
    __shared__ __align__(16) __half As[2][128 * SKA2];
    __shared__ __align__(16) __half Bs[2][32 * SKB2];

    const int tid = threadIdx.x, bx = blockIdx.x, by = blockIdx.y, bz = blockIdx.z;
    const int warp = tid >> 5, lane = tid & 31;
    const int wm = (warp >> 2) * 64;
    const int wn = (warp & 3) * 32;
    const int lr = lane >> 2;
    const int lc = lane & 3;

    const long long koff = (long long)bz * K;

    // A chunks: c in [0,512): row=c>>2, kc=(c&3)*8 halves. Thread does c=tid, tid+256.
    // B chunks: c in [0,512): row=c>>4, nc=(c&15)*8 halves.
    auto issueT = [&](int kk, int buf) {
        #pragma unroll
        for (int q = 0; q < 2; q++) {
            int c = tid + q * 256;
            int row = c >> 2, kc = (c & 3) * 8;
            int gr = by * 128 + row;
            uint32_t sa = smem_u32(&As[buf][row * SKA2 + kc]);
            const __half* g = A + (long long)gr * ldA + koff + kk + kc;
            cp16(sa, g, gr < M ? 16 : 0);
        }
        #pragma unroll
        for (int q = 0; q < 2; q++) {
            int c = tid + q * 256;
            int row = c >> 4, nc = (c & 15) * 8;
            uint32_t sb = smem_u32(&Bs[buf][row * SKB2 + nc]);
            const __half* g = B + (koff + kk + row) * (long long)Nn + (long long)bx * 128 + nc;
            cp16(sb, g, 16);
        }
        CP_COMMIT();
    };

    float acc[4][4][4];
    #pragma unroll
    for (int i = 0; i < 4; i++)
        #pragma unroll
        for (int j = 0; j < 4; j++)
            #pragma unroll
            for (int t = 0; t < 4; t++) acc[i][j][t] = 0.0f;

    const int a_r = lane & 15, a_s = lane >> 4;
    const int b_k = lane & 7,  b_s = lane >> 3;

    auto compute = [&](int buf) {
        const uint32_t aB = smem_u32(&As[buf][0]);
        const uint32_t bB = smem_u32(&Bs[buf][0]);
        #pragma unroll
        for (int ks = 0; ks < 32; ks += 16) {
            uint32_t af[4][4], bf[4][2];
            #pragma unroll
            for (int mt = 0; mt < 4; mt++) {
                uint32_t addr = aB + (uint32_t)(((wm + mt * 16 + a_r) * SKA2 + ks + a_s * 8) * 2);
                LDMATRIX_X4(af[mt][0], af[mt][1], af[mt][2], af[mt][3], addr);
            }
            #pragma unroll
            for (int np = 0; np < 2; np++) {
                uint32_t addr = bB + (uint32_t)(((ks + (b_s & 1) * 8 + b_k) * SKB2 + wn + np * 16 + (b_s >> 1) * 8) * 2);
                uint32_t r0, r1, r2, r3;
                LDMATRIX_X4_T(r0, r1, r2, r3, addr);
                bf[2*np][0] = r0; bf[2*np][1] = r1;
                bf[2*np+1][0] = r2; bf[2*np+1][1] = r3;
            }
            #pragma unroll
            for (int mt = 0; mt < 4; mt++)
                #pragma unroll
                for (int nt = 0; nt < 4; nt++) {
                    asm volatile(
                        "mma.sync.aligned.m16n8k16.row.col.f32.f16.f16.f32 "
                        "{%0,%1,%2,%3}, {%4,%5,%6,%7}, {%8,%9}, {%0,%1,%2,%3};"
                        : "+f"(acc[mt][nt][0]), "+f"(acc[mt][nt][1]),
                          "+f"(acc[mt][nt][2]), "+f"(acc[mt][nt][3])
                        : "r"(af[mt][0]), "r"(af[mt][1]), "r"(af[mt][2]), "r"(af[mt][3]),
                          "r"(bf[nt][0]), "r"(bf[nt][1]));
                }
        }
    };

    const int nIter = K / 32;
    issueT(0, 0);
    for (int it = 0; it < nIter; it++) {
        if (it + 1 < nIter) {
            issueT((it + 1) * 32, (it + 1) & 1);
            asm volatile("cp.async.wait_group 1;");
        } else {
            asm volatile("cp.async.wait_group 0;");
        }
        __syncthreads();
        compute(it & 1);
        __syncthreads();
    }

    if (SPLIT) {
        float* Cz = (float*)Cv + (long long)bz * M * Nn;
        #pragma unroll
        for (int mt = 0; mt < 4; mt++) {
            int r0 = by * 128 + wm + mt * 16 + lr;
            int r1 = r0 + 8;
            #pragma unroll
            for (int nt = 0; nt < 4; nt++) {
                int col = bx * 128 + wn + nt * 8 + 2 * lc;
                if (r0 < M) *(float2*)&Cz[(long long)r0 * Nn + col] = make_float2(acc[mt][nt][0], acc[mt][nt][1]);
                if (r1 < M) *(float2*)&Cz[(long long)r1 * Nn + col] = make_float2(acc[mt][nt][2], acc[mt][nt][3]);
            }
        }
        return;
    }

    const float bninv = rsqrtf(1.0f + 1e-5f);
    #pragma unroll
    for (int mt = 0; mt < 4; mt++) {
        int r0 = by * 128 + wm + mt * 16 + lr;
        int r1 = r0 + 8;
        #pragma unroll
        for (int nt = 0; nt < 4; nt++) {
            int col = bx * 128 + wn + nt * 8 + 2 * lc;
            float b0 = __ldg(bias + col);
            float b1 = __ldg(bias + col + 1);
            float g0 = 1.f, g1 = 1.f, be0 = 0.f, be1 = 0.f;
            if (EPI == 2) {
                g0 = __ldg(bng + col) * bninv;  g1 = __ldg(bng + col + 1) * bninv;
                be0 = __ldg(bnb + col);         be1 = __ldg(bnb + col + 1);
            }
            float v00 = acc[mt][nt][0] + b0, v01 = acc[mt][nt][1] + b1;
            float v10 = acc[mt][nt][2] + b0, v11 = acc[mt][nt][3] + b1;
            if (EPI == 2) {
                v00 = v00 * g0 + be0; v01 = v01 * g1 + be1;
                v10 = v10 * g0 + be0; v11 = v11 * g1 + be1;
            }
            if (EPI >= 1) {
                v00 = fmaxf(v00, 0.f); v01 = fmaxf(v01, 0.f);
                v10 = fmaxf(v10, 0.f); v11 = fmaxf(v11, 0.f);
            }
            if (CH) {
                __half* Ch = (__half*)Cv;
                if (r0 < M) *(__half2*)&Ch[(long long)r0 * Nn + col] = __floats2half2_rn(v00, v01);
                if (r1 < M) *(__half2*)&Ch[(long long)r1 * Nn + col] = __floats2half2_rn(v10, v11);
            } else {
                float* Cf = (float*)Cv;
                if (r0 < M) *(float2*)&Cf[(long long)r0 * Nn + col] = make_float2(v00, v01);
                if (r1 < M) *(float2*)&Cf[(long long)r1 * Nn + col] = make_float2(v10, v11);
            }
        }
    }
}

// ---------------------------------------------------------------------------
extern "C" void kernel_launch(void* const* d_in, const int* in_sizes, int n_in,
                              void* d_out, int out_size) {
    const float* x     = (const float*)d_in[0];
    const int*   ei    = (const int*)  d_in[1];
    const int*   src   = ei;
    const int*   dst   = ei + NEDGES;
    const int*   batch = (const int*)  d_in[2];
    const float* fp    = (const float*)d_in[3];
    const float* c1w1 = (const float*)d_in[4],  *c1b1 = (const float*)d_in[5];
    const float* c1w2 = (const float*)d_in[6],  *c1b2 = (const float*)d_in[7];
    const float* c2w1 = (const float*)d_in[8],  *c2b1 = (const float*)d_in[9];
    const float* c2w2 = (const float*)d_in[10], *c2b2 = (const float*)d_in[11];
    const float* c3w1 = (const float*)d_in[12], *c3b1 = (const float*)d_in[13];
    const float* c3w2 = (const float*)d_in[14], *c3b2 = (const float*)d_in[15];
    const float* bn1g = (const float*)d_in[16], *bn1b = (const float*)d_in[17];
    const float* bn2g = (const float*)d_in[18], *bn2b = (const float*)d_in[19];
    const float* bn3g = (const float*)d_in[20], *bn3b = (const float*)d_in[21];
    const float* o1w  = (const float*)d_in[22], *o1b  = (const float*)d_in[23];
    const float* obng = (const float*)d_in[24], *obnb = (const float*)d_in[25];
    const float* o3w  = (const float*)d_in[26], *o3b  = (const float*)d_in[27];
    float* out = (float*)d_out;

    __half *xh, *aggrh, *tmph, *hh, *wh, *poolh;
    float *scr;
    int *deg, *cursor, *rowptr, *srclist, *gstart;
    cudaGetSymbolAddress((void**)&xh,      g_xh);
    cudaGetSymbolAddress((void**)&aggrh,   g_aggrh);
    cudaGetSymbolAddress((void**)&tmph,    g_tmph);
    cudaGetSymbolAddress((void**)&hh,      g_hh);
    cudaGetSymbolAddress((void**)&wh,      g_wh);
    cudaGetSymbolAddress((void**)&poolh,   g_poolh);
    cudaGetSymbolAddress((void**)&scr,     g_scr);
    cudaGetSymbolAddress((void**)&deg,     g_deg);
    cudaGetSymbolAddress((void**)&cursor,  g_cursor);
    cudaGetSymbolAddress((void**)&rowptr,  g_rowptr);
    cudaGetSymbolAddress((void**)&srclist, g_srclist);
    cudaGetSymbolAddress((void**)&gstart,  g_gstart);

    const int T = 256;
    const int gy = (NNODES + 127) / 128;

    // ---- CSR build + converts ----
    zero_deg_kernel<<<(NNODES + T - 1) / T, T>>>(deg);
    hist_kernel<<<(NEDGES + T - 1) / T, T>>>(dst, deg);
    scan_kernel<<<1, 1024>>>(deg, rowptr, cursor);
    fill_kernel<<<(NEDGES + T - 1) / T, T>>>(src, dst, cursor, srclist);
    gstart_kernel<<<3, 256>>>(batch, gstart);
    fp_copy_kernel<<<dim3((1536 + T - 1) / T, NGRAPH), T>>>((const float4*)fp, (uint2*)poolh);
    f2h_kernel<<<(NNODES * 32 + T - 1) / T, T>>>((const float2*)x, (__half2*)xh, NNODES * 32);
    f2h_kernel<<<(4096 + T - 1) / T, T>>>((const float2*)c1w1, (__half2*)(wh + W_C1W1), 4096);
    f2h_kernel<<<(8192 + T - 1) / T, T>>>((const float2*)c1w2, (__half2*)(wh + W_C1W2), 8192);
    f2h_kernel<<<(8192 + T - 1) / T, T>>>((const float2*)c2w1, (__half2*)(wh + W_C2W1), 8192);
    f2h_kernel<<<(8192 + T - 1) / T, T>>>((const float2*)c2w2, (__half2*)(wh + W_C2W2), 8192);
    f2h_kernel<<<(16384 + T - 1) / T, T>>>((const float2*)c3w1, (__half2*)(wh + W_C3W1), 16384);
    f2h_kernel<<<(32768 + T - 1) / T, T>>>((const float2*)c3w2, (__half2*)(wh + W_C3W2), 32768);
    f2h_kernel<<<(11075584 + T - 1) / T, T>>>((const float2*)o1w, (__half2*)(wh + W_O1W), 11075584);
    f2h_kernel<<<(212992 + T - 1) / T, T>>>((const float2*)o3w, (__half2*)(wh + W_O3W), 212992);

    // ---- conv1 (64 -> 128 -> 128) ----
    gather_aggr_h_kernel<64><<<(NNODES * 16 + T - 1) / T, T>>>((const uint2*)xh, rowptr, srclist, (uint2*)aggrh);
    hgemm16_kernel<1,0,true><<<dim3(1, gy), T>>>(NNODES, 128, 64, 64,  aggrh, wh + W_C1W1, c1b1, nullptr, nullptr, tmph);
    hgemm16_kernel<2,0,true><<<dim3(1, gy), T>>>(NNODES, 128, 128, 128, tmph, wh + W_C1W2, c1b2, bn1g, bn1b, hh);
    seg_pool_h_kernel<<<NGRAPH, 64>>>((const __half2*)hh, gstart, (__half2*)poolh, 64, 0);

    // ---- conv2 (128 -> 128 -> 128) ----
    gather_aggr_h_kernel<128><<<(NNODES * 32 + T - 1) / T, T>>>((const uint2*)hh, rowptr, srclist, (uint2*)aggrh);
    hgemm16_kernel<1,0,true><<<dim3(1, gy), T>>>(NNODES, 128, 128, 128, aggrh, wh + W_C2W1, c2b1, nullptr, nullptr, tmph);
    hgemm16_kernel<2,0,true><<<dim3(1, gy), T>>>(NNODES, 128, 128, 128, tmph, wh + W_C2W2, c2b2, bn2g, bn2b, hh);
    seg_pool_h_kernel<<<NGRAPH, 64>>>((const __half2*)hh, gstart, (__half2*)poolh, 64, 64);

    // ---- conv3 (128 -> 256 -> 256) ----
    gather_aggr_h_kernel<128><<<(NNODES * 32 + T - 1) / T, T>>>((const uint2*)hh, rowptr, srclist, (uint2*)aggrh);
    hgemm16_kernel<1,0,true><<<dim3(2, gy), T>>>(NNODES, 256, 128, 128, aggrh, wh + W_C3W1, c3b1, nullptr, nullptr, tmph);
    hgemm16_kernel<2,0,true><<<dim3(2, gy), T>>>(NNODES, 256, 256, 256, tmph, wh + W_C3W2, c3b2, bn3g, bn3b, hh);
    seg_pool_h_kernel<<<NGRAPH, 128>>>((const __half2*)hh, gstart, (__half2*)poolh, 128, 128);

    // ---- readout GEMM1: A=poolh fp16, split-K=4, fp32 partials -> scr, reduce -> tmph fp16 ----
    hgemm16_kernel<0,1,false><<<dim3(3328 / 128, 4, 4), T>>>(NGRAPH, 3328, 1664, RDIM, poolh, wh + W_O1W, nullptr, nullptr, nullptr, scr);
    readout_reduce_kernel<<<(NGRAPH * 832 + T - 1) / T, T>>>((const float4*)scr, o1b, obng, obnb, (uint2*)tmph);

    // ---- readout GEMM2: A=tmph fp16, split-K=8, partials -> scr2, reduce -> out ----
    float* scr2 = scr + 4 * NGRAPH * 3328;
    hgemm16_kernel<0,1,false><<<dim3(1, 4, 8), T>>>(NGRAPH, 128, 416, 3328, tmph, wh + W_O3W, nullptr, nullptr, nullptr, scr2);
    final_reduce_kernel<<<(NGRAPH * 128 + T - 1) / T, T>>>(scr2, o3b, out);
}

// round 10
// speedup vs baseline: 5.1442x; 1.0444x over previous
#include <cuda_runtime.h>
#include <cuda_fp16.h>
#include <cstdint>

#define NNODES 100000
#define NEDGES 1600000
#define NGRAPH 512
#define RDIM   6656

// fp16 weight buffer offsets (halves)
#define W_C1W1 0
#define W_C1W2 8192
#define W_C2W1 24576
#define W_C2W2 40960
#define W_C3W1 57344
#define W_C3W2 90112
#define W_O1W  155648
#define W_O3W  22306816
#define W_TOTAL 22732800

// ---- static device scratch (no allocations allowed) ----
static __device__ __align__(16) __half g_xh   [NNODES * 64];
static __device__ __align__(16) __half g_aggrh[NNODES * 256];
static __device__ __align__(16) __half g_tmph [NNODES * 256];
static __device__ __align__(16) __half g_hh   [NNODES * 256];
static __device__ __align__(16) __half g_wh   [W_TOTAL];
static __device__ __align__(16) __half g_poolh[NGRAPH * RDIM];
static __device__ __align__(16) float  g_scr  [8 * 1024 * 1024];
static __device__ int g_deg[NNODES];
static __device__ int g_cursor[NNODES];
static __device__ int g_rowptr[NNODES + 1];
static __device__ int g_srclist[NEDGES];
static __device__ int g_gstart[NGRAPH + 1];

// ---------------------------------------------------------------------------
// CSR build
// ---------------------------------------------------------------------------
__global__ void zero_deg_kernel(int* __restrict__ deg) {
    int i = blockIdx.x * blockDim.x + threadIdx.x;
    if (i < NNODES) deg[i] = 0;
}
__global__ void hist_kernel(const int* __restrict__ edst, int* __restrict__ deg) {
    int e = blockIdx.x * blockDim.x + threadIdx.x;
    if (e < NEDGES) atomicAdd(&deg[__ldg(edst + e)], 1);
}
__global__ __launch_bounds__(1024) void scan_kernel(const int* __restrict__ deg,
                                                    int* __restrict__ rowptr,
                                                    int* __restrict__ cursor) {
    __shared__ int sums[1024];
    const int t = threadIdx.x;
    const int chunk = (NNODES + 1023) / 1024;
    const int beg = t * chunk;
    const int end = min(beg + chunk, NNODES);
    int s = 0;
    for (int k = beg; k < end; k++) s += deg[k];
    sums[t] = s;
    __syncthreads();
    for (int off = 1; off < 1024; off <<= 1) {
        int v = (t >= off) ? sums[t - off] : 0;
        __syncthreads();
        sums[t] += v;
        __syncthreads();
    }
    int run = sums[t] - s;
    for (int k = beg; k < end; k++) {
        rowptr[k] = run;
        cursor[k] = run;
        run += deg[k];
    }
    if (t == 1023) rowptr[NNODES] = sums[1023];
}
__global__ void fill_kernel(const int* __restrict__ esrc, const int* __restrict__ edst,
                            int* __restrict__ cursor, int* __restrict__ srclist) {
    int e = blockIdx.x * blockDim.x + threadIdx.x;
    if (e >= NEDGES) return;
    int d = __ldg(edst + e);
    int pos = atomicAdd(&cursor[d], 1);
    srclist[pos] = __ldg(esrc + e);
}
__global__ void gstart_kernel(const int* __restrict__ batch, int* __restrict__ gstart) {
    int g = blockIdx.x * blockDim.x + threadIdx.x;
    if (g > NGRAPH) return;
    if (g == NGRAPH) { gstart[NGRAPH] = NNODES; return; }
    int lo = 0, hi = NNODES;
    while (lo < hi) {
        int mid = (lo + hi) >> 1;
        if (__ldg(batch + mid) < g) lo = mid + 1; else hi = mid;
    }
    gstart[g] = lo;
}

// ---------------------------------------------------------------------------
// converts
// ---------------------------------------------------------------------------
__global__ void f2h_kernel(const float2* __restrict__ in, __half2* __restrict__ out, int n2) {
    int i = blockIdx.x * blockDim.x + threadIdx.x;
    if (i < n2) {
        float2 v = __ldg(in + i);
        out[i] = __floats2half2_rn(v.x, v.y);
    }
}

// all-weights convert: 8 segments in one launch, grid-stride
struct WSeg { const float2* src; __half2* dst; int n; };
struct WConvArgs { WSeg seg[8]; int total; };
__global__ void wconv_kernel(WConvArgs a) {
    int stride = gridDim.x * blockDim.x;
    for (int idx = blockIdx.x * blockDim.x + threadIdx.x; idx < a.total; idx += stride) {
        int i = idx;
        #pragma unroll
        for (int s = 0; s < 8; s++) {
            if (i < a.seg[s].n) {
                float2 v = __ldg(a.seg[s].src + i);
                a.seg[s].dst[i] = __floats2half2_rn(v.x, v.y);
                break;
            }
            i -= a.seg[s].n;
        }
    }
}

// ---------------------------------------------------------------------------
// fp16 gather, neighbor loop unrolled x4
// ---------------------------------------------------------------------------
__device__ __forceinline__ float2 h2f2(uint32_t h) {
    return __half22float2(*(__half2*)&h);
}
template<int FH>
__global__ void gather_aggr_h_kernel(const uint2* __restrict__ feat,
                                     const int* __restrict__ rowptr,
                                     const int* __restrict__ srclist,
                                     uint2* __restrict__ aggr) {
    constexpr int L = FH / 4;
    constexpr int NPB = 256 / L;
    int i = blockIdx.x * NPB + threadIdx.x / L;
    if (i >= NNODES) return;
    int c = threadIdx.x % L;

    uint2 v0 = __ldg(&feat[i * L + c]);
    float2 ax = h2f2(v0.x), ay = h2f2(v0.y);

    int j = __ldg(rowptr + i);
    const int end = __ldg(rowptr + i + 1);
    for (; j + 3 < end; j += 4) {
        int s0 = __ldg(srclist + j);
        int s1 = __ldg(srclist + j + 1);
        int s2 = __ldg(srclist + j + 2);
        int s3 = __ldg(srclist + j + 3);
        uint2 t0 = __ldg(&feat[s0 * L + c]);
        uint2 t1 = __ldg(&feat[s1 * L + c]);
        uint2 t2 = __ldg(&feat[s2 * L + c]);
        uint2 t3 = __ldg(&feat[s3 * L + c]);
        float2 a0 = h2f2(t0.x), b0 = h2f2(t0.y);
        float2 a1 = h2f2(t1.x), b1 = h2f2(t1.y);
        float2 a2 = h2f2(t2.x), b2 = h2f2(t2.y);
        float2 a3 = h2f2(t3.x), b3 = h2f2(t3.y);
        ax.x += (a0.x + a1.x) + (a2.x + a3.x);
        ax.y += (a0.y + a1.y) + (a2.y + a3.y);
        ay.x += (b0.x + b1.x) + (b2.x + b3.x);
        ay.y += (b0.y + b1.y) + (b2.y + b3.y);
    }
    for (; j < end; j++) {
        int s0 = __ldg(srclist + j);
        uint2 t0 = __ldg(&feat[s0 * L + c]);
        float2 a = h2f2(t0.x), b = h2f2(t0.y);
        ax.x += a.x; ax.y += a.y; ay.x += b.x; ay.y += b.y;
    }
    __half2 r0 = __floats2half2_rn(ax.x, ax.y);
    __half2 r1 = __floats2half2_rn(ay.x, ay.y);
    uint2 o;
    o.x = *(uint32_t*)&r0; o.y = *(uint32_t*)&r1;
    aggr[i * L + c] = o;
}

// ---------------------------------------------------------------------------
// segment pool -> fp16 pool
// ---------------------------------------------------------------------------
__global__ void seg_pool_h_kernel(const __half2* __restrict__ feat,
                                  const int* __restrict__ gstart,
                                  __half2* __restrict__ pool,
                                  int F2, int off2) {
    int g = blockIdx.x;
    int t = threadIdx.x;
    int beg = __ldg(gstart + g), end = __ldg(gstart + g + 1);
    float2 a0 = make_float2(0.f, 0.f), a1 = make_float2(0.f, 0.f);
    int r = beg;
    for (; r + 1 < end; r += 2) {
        float2 v0 = __half22float2(__ldg(feat + (long long)r * F2 + t));
        float2 v1 = __half22float2(__ldg(feat + (long long)(r + 1) * F2 + t));
        a0.x += v0.x; a0.y += v0.y; a1.x += v1.x; a1.y += v1.y;
    }
    if (r < end) {
        float2 v0 = __half22float2(__ldg(feat + (long long)r * F2 + t));
        a0.x += v0.x; a0.y += v0.y;
    }
    pool[(long long)g * (RDIM / 2) + off2 + t] = __floats2half2_rn(a0.x + a1.x, a0.y + a1.y);
}

__global__ void fp_copy_kernel(const float4* __restrict__ fp, uint2* __restrict__ pool) {
    int col = blockIdx.x * blockDim.x + threadIdx.x;
    int row = blockIdx.y;
    if (col >= 1536) return;
    float4 v = __ldg(fp + row * 1536 + col);
    __half2 h0 = __floats2half2_rn(v.x, v.y);
    __half2 h1 = __floats2half2_rn(v.z, v.w);
    uint2 o;
    o.x = *(uint32_t*)&h0; o.y = *(uint32_t*)&h1;
    pool[row * (RDIM / 4) + 128 + col] = o;
}

// ---------------------------------------------------------------------------
// split-K reductions (fixed order)
// ---------------------------------------------------------------------------
__global__ void readout_reduce_kernel(const float4* __restrict__ part,
                                      const float* __restrict__ bias,
                                      const float* __restrict__ bng,
                                      const float* __restrict__ bnb,
                                      uint2* __restrict__ outh) {
    const int N4 = 3328 / 4;
    int idx = blockIdx.x * blockDim.x + threadIdx.x;
    if (idx >= NGRAPH * N4) return;
    const long long SZ4 = (long long)NGRAPH * N4;
    int col = (idx % N4) * 4;
    float4 s = part[idx];
    #pragma unroll
    for (int z = 1; z < 4; z++) {
        float4 t = part[idx + z * SZ4];
        s.x += t.x; s.y += t.y; s.z += t.z; s.w += t.w;
    }
    const float bninv = rsqrtf(1.0f + 1e-5f);
    float* sp = &s.x;
    #pragma unroll
    for (int c = 0; c < 4; c++) {
        float v = (sp[c] + __ldg(bias + col + c)) * (__ldg(bng + col + c) * bninv) + __ldg(bnb + col + c);
        sp[c] = fmaxf(v, 0.0f);
    }
    __half2 h0 = __floats2half2_rn(s.x, s.y);
    __half2 h1 = __floats2half2_rn(s.z, s.w);
    uint2 o;
    o.x = *(uint32_t*)&h0; o.y = *(uint32_t*)&h1;
    outh[idx] = o;
}
__global__ void final_reduce_kernel(const float* __restrict__ part,
                                    const float* __restrict__ bias,
                                    float* __restrict__ out) {
    int idx = blockIdx.x * blockDim.x + threadIdx.x;
    if (idx >= NGRAPH * 128) return;
    float s = 0.0f;
    #pragma unroll
    for (int z = 0; z < 8; z++) s += part[idx + z * NGRAPH * 128];
    out[idx] = s + __ldg(bias + (idx & 127));
}

// ---------------------------------------------------------------------------
// All-fp16 tensor-core GEMM, 3-stage cp.async pipeline, dynamic smem.
// A[M,ldA] fp16, B[K,Nn] fp16. BM=BN=128, BK=32, 256 thr.
// SPLIT=1: grid.z splits K, fp32 partials to C + bz*M*Nn.
// EPI: 0 = +bias, 1 = relu(+bias), 2 = relu(bn(+bias)); CH: fp16 C out.
// ---------------------------------------------------------------------------
#define SKA2 40
#define SKB2 136
#define A_STG (128 * SKA2)
#define B_STG (32 * SKB2)
#define HG_SMEM (3 * (A_STG + B_STG) * 2)

__device__ __forceinline__ uint32_t smem_u32(const void* p) {
    uint32_t a;
    asm("{ .reg .u64 t; cvta.to.shared.u64 t, %1; cvt.u32.u64 %0, t; }" : "=r"(a) : "l"(p));
    return a;
}
__device__ __forceinline__ void cp16(uint32_t s, const void* g, int sz) {
    asm volatile("cp.async.cg.shared.global [%0], [%1], 16, %2;" :: "r"(s), "l"(g), "r"(sz));
}
#define CP_COMMIT() asm volatile("cp.async.commit_group;")
#define LDMATRIX_X4(r0, r1, r2, r3, addr) \
    asm volatile("ldmatrix.sync.aligned.m8n8.x4.shared.b16 {%0,%1,%2,%3}, [%4];" \
        : "=r"(r0), "=r"(r1), "=r"(r2), "=r"(r3) : "r"(addr))
#define LDMATRIX_X4_T(r0, r1, r2, r3, addr) \
    asm volatile("ldmatrix.sync.aligned.m8n8.x4.trans.shared.b16 {%0,%1,%2,%3}, [%4];" \
        : "=r"(r0), "=r"(r1), "=r"(r2), "=r"(r3) : "r"(addr))

template<int EPI, int SPLIT, bool CH>
__global__ __launch_bounds__(256, 2) void hgemm16_kernel(
    int M, int Nn, int K, int ldA,
    const __half* __restrict__ A, const __half* __restrict__ B,
    const float* __restrict__ bias,
    const float* __restrict__ bng, const float* __restrict__ bnb,
    void* __restrict__ Cv)
{
    extern __shared__ __half dsm[];
    __half* AsBase = dsm;                 // 3 stages
    __half* BsBase = dsm + 3 * A_STG;

    const int tid = threadIdx.x, bx = blockIdx.x, by = blockIdx.y, bz = blockIdx.z;
    const int warp = tid >> 5, lane = tid & 31;
    const int wm = (warp >> 2) * 64;
    const int wn = (warp & 3) * 32;
    const int lr = lane >> 2;
    const int lc = lane & 3;

    const long long koff = (long long)bz * K;

    auto issueT = [&](int kk, int stg) {
        __half* As = AsBase + stg * A_STG;
        __half* Bs = BsBase + stg * B_STG;
        #pragma unroll
        for (int q = 0; q < 2; q++) {
            int c = tid + q * 256;
            int row = c >> 2, kc = (c & 3) * 8;
            int gr = by * 128 + row;
            uint32_t sa = smem_u32(&As[row * SKA2 + kc]);
            const __half* g = A + (long long)gr * ldA + koff + kk + kc;
            cp16(sa, g, gr < M ? 16 : 0);
        }
        #pragma unroll
        for (int q = 0; q < 2; q++) {
            int c = tid + q * 256;
            int row = c >> 4, nc = (c & 15) * 8;
            uint32_t sb = smem_u32(&Bs[row * SKB2 + nc]);
            const __half* g = B + (koff + kk + row) * (long long)Nn + (long long)bx * 128 + nc;
            cp16(sb, g, 16);
        }
        CP_COMMIT();
    };

    float acc[4][4][4];
    #pragma unroll
    for (int i = 0; i < 4; i++)
        #pragma unroll
        for (int j = 0; j < 4; j++)
            #pragma unroll
            for (int t = 0; t < 4; t++) acc[i][j][t] = 0.0f;

    const int a_r = lane & 15, a_s = lane >> 4;
    const int b_k = lane & 7,  b_s = lane >> 3;

    auto compute = [&](int stg) {
        const uint32_t aB = smem_u32(AsBase + stg * A_STG);
        const uint32_t bB = smem_u32(BsBase + stg * B_STG);
        #pragma unroll
        for (int ks = 0; ks < 32; ks += 16) {
            uint32_t af[4][4], bf[4][2];
            #pragma unroll
            for (int mt = 0; mt < 4; mt++) {
                uint32_t addr = aB + (uint32_t)(((wm + mt * 16 + a_r) * SKA2 + ks + a_s * 8) * 2);
                LDMATRIX_X4(af[mt][0], af[mt][1], af[mt][2], af[mt][3], addr);
            }
            #pragma unroll
            for (int np = 0; np < 2; np++) {
                uint32_t addr = bB + (uint32_t)(((ks + (b_s & 1) * 8 + b_k) * SKB2 + wn + np * 16 + (b_s >> 1) * 8) * 2);
                uint32_t r0, r1, r2, r3;
                LDMATRIX_X4_T(r0, r1, r2, r3, addr);
                bf[2*np][0] = r0; bf[2*np][1] = r1;
                bf[2*np+1][0] = r2; bf[2*np+1][1] = r3;
            }
            #pragma unroll
            for (int mt = 0; mt < 4; mt++)
                #pragma unroll
                for (int nt = 0; nt < 4; nt++) {
                    asm volatile(
                        "mma.sync.aligned.m16n8k16.row.col.f32.f16.f16.f32 "
                        "{%0,%1,%2,%3}, {%4,%5,%6,%7}, {%8,%9}, {%0,%1,%2,%3};"
                        : "+f"(acc[mt][nt][0]), "+f"(acc[mt][nt][1]),
                          "+f"(acc[mt][nt][2]), "+f"(acc[mt][nt][3])
                        : "r"(af[mt][0]), "r"(af[mt][1]), "r"(af[mt][2]), "r"(af[mt][3]),
                          "r"(bf[nt][0]), "r"(bf[nt][1]));
                }
        }
    };

    const int nIter = K / 32;   // >= 2 for all our shapes
    issueT(0, 0);
    issueT(32, 1);
    int stg = 0;
    for (int it = 0; it < nIter; it++) {
        if (it < nIter - 1) {
            asm volatile("cp.async.wait_group 1;");
        } else {
            asm volatile("cp.async.wait_group 0;");
        }
        __syncthreads();
        compute(stg);
        if (it + 2 < nIter) {
            int ns = stg + 2; if (ns >= 3) ns -= 3;
            issueT((it + 2) * 32, ns);
        }
        if (++stg == 3) stg = 0;
    }

    if (SPLIT) {
        float* Cz = (float*)Cv + (long long)bz * M * Nn;
        #pragma unroll
        for (int mt = 0; mt < 4; mt++) {
            int r0 = by * 128 + wm + mt * 16 + lr;
            int r1 = r0 + 8;
            #pragma unroll
            for (int nt = 0; nt < 4; nt++) {
                int col = bx * 128 + wn + nt * 8 + 2 * lc;
                if (r0 < M) *(float2*)&Cz[(long long)r0 * Nn + col] = make_float2(acc[mt][nt][0], acc[mt][nt][1]);
                if (r1 < M) *(float2*)&Cz[(long long)r1 * Nn + col] = make_float2(acc[mt][nt][2], acc[mt][nt][3]);
            }
        }
        return;
    }

    const float bninv = rsqrtf(1.0f + 1e-5f);
    #pragma unroll
    for (int mt = 0; mt < 4; mt++) {
        int r0 = by * 128 + wm + mt * 16 + lr;
        int r1 = r0 + 8;
        #pragma unroll
        for (int nt = 0; nt < 4; nt++) {
            int col = bx * 128 + wn + nt * 8 + 2 * lc;
            float b0 = __ldg(bias + col);
            float b1 = __ldg(bias + col + 1);
            float g0 = 1.f, g1 = 1.f, be0 = 0.f, be1 = 0.f;
            if (EPI == 2) {
                g0 = __ldg(bng + col) * bninv;  g1 = __ldg(bng + col + 1) * bninv;
                be0 = __ldg(bnb + col);         be1 = __ldg(bnb + col + 1);
            }
            float v00 = acc[mt][nt][0] + b0, v01 = acc[mt][nt][1] + b1;
            float v10 = acc[mt][nt][2] + b0, v11 = acc[mt][nt][3] + b1;
            if (EPI == 2) {
                v00 = v00 * g0 + be0; v01 = v01 * g1 + be1;
                v10 = v10 * g0 + be0; v11 = v11 * g1 + be1;
            }
            if (EPI >= 1) {
                v00 = fmaxf(v00, 0.f); v01 = fmaxf(v01, 0.f);
                v10 = fmaxf(v10, 0.f); v11 = fmaxf(v11, 0.f);
            }
            if (CH) {
                __half* Ch = (__half*)Cv;
                if (r0 < M) *(__half2*)&Ch[(long long)r0 * Nn + col] = __floats2half2_rn(v00, v01);
                if (r1 < M) *(__half2*)&Ch[(long long)r1 * Nn + col] = __floats2half2_rn(v10, v11);
            } else {
                float* Cf = (float*)Cv;
                if (r0 < M) *(float2*)&Cf[(long long)r0 * Nn + col] = make_float2(v00, v01);
                if (r1 < M) *(float2*)&Cf[(long long)r1 * Nn + col] = make_float2(v10, v11);
            }
        }
    }
}

// ---------------------------------------------------------------------------
extern "C" void kernel_launch(void* const* d_in, const int* in_sizes, int n_in,
                              void* d_out, int out_size) {
    const float* x     = (const float*)d_in[0];
    const int*   ei    = (const int*)  d_in[1];
    const int*   src   = ei;
    const int*   dst   = ei + NEDGES;
    const int*   batch = (const int*)  d_in[2];
    const float* fp    = (const float*)d_in[3];
    const float* c1w1 = (const float*)d_in[4],  *c1b1 = (const float*)d_in[5];
    const float* c1w2 = (const float*)d_in[6],  *c1b2 = (const float*)d_in[7];
    const float* c2w1 = (const float*)d_in[8],  *c2b1 = (const float*)d_in[9];
    const float* c2w2 = (const float*)d_in[10], *c2b2 = (const float*)d_in[11];
    const float* c3w1 = (const float*)d_in[12], *c3b1 = (const float*)d_in[13];
    const float* c3w2 = (const float*)d_in[14], *c3b2 = (const float*)d_in[15];
    const float* bn1g = (const float*)d_in[16], *bn1b = (const float*)d_in[17];
    const float* bn2g = (const float*)d_in[18], *bn2b = (const float*)d_in[19];
    const float* bn3g = (const float*)d_in[20], *bn3b = (const float*)d_in[21];
    const float* o1w  = (const float*)d_in[22], *o1b  = (const float*)d_in[23];
    const float* obng = (const float*)d_in[24], *obnb = (const float*)d_in[25];
    const float* o3w  = (const float*)d_in[26], *o3b  = (const float*)d_in[27];
    float* out = (float*)d_out;

    __half *xh, *aggrh, *tmph, *hh, *wh, *poolh;
    float *scr;
    int *deg, *cursor, *rowptr, *srclist, *gstart;
    cudaGetSymbolAddress((void**)&xh,      g_xh);
    cudaGetSymbolAddress((void**)&aggrh,   g_aggrh);
    cudaGetSymbolAddress((void**)&tmph,    g_tmph);
    cudaGetSymbolAddress((void**)&hh,      g_hh);
    cudaGetSymbolAddress((void**)&wh,      g_wh);
    cudaGetSymbolAddress((void**)&poolh,   g_poolh);
    cudaGetSymbolAddress((void**)&scr,     g_scr);
    cudaGetSymbolAddress((void**)&deg,     g_deg);
    cudaGetSymbolAddress((void**)&cursor,  g_cursor);
    cudaGetSymbolAddress((void**)&rowptr,  g_rowptr);
    cudaGetSymbolAddress((void**)&srclist, g_srclist);
    cudaGetSymbolAddress((void**)&gstart,  g_gstart);

    cudaFuncSetAttribute(hgemm16_kernel<1,0,true>,  cudaFuncAttributeMaxDynamicSharedMemorySize, HG_SMEM);
    cudaFuncSetAttribute(hgemm16_kernel<2,0,true>,  cudaFuncAttributeMaxDynamicSharedMemorySize, HG_SMEM);
    cudaFuncSetAttribute(hgemm16_kernel<0,1,false>, cudaFuncAttributeMaxDynamicSharedMemorySize, HG_SMEM);

    const int T = 256;
    const int gy = (NNODES + 127) / 128;

    // ---- CSR build + converts ----
    zero_deg_kernel<<<(NNODES + T - 1) / T, T>>>(deg);
    hist_kernel<<<(NEDGES + T - 1) / T, T>>>(dst, deg);
    scan_kernel<<<1, 1024>>>(deg, rowptr, cursor);
    fill_kernel<<<(NEDGES + T - 1) / T, T>>>(src, dst, cursor, srclist);
    gstart_kernel<<<3, 256>>>(batch, gstart);
    fp_copy_kernel<<<dim3((1536 + T - 1) / T, NGRAPH), T>>>((const float4*)fp, (uint2*)poolh);
    f2h_kernel<<<(NNODES * 32 + T - 1) / T, T>>>((const float2*)x, (__half2*)xh, NNODES * 32);

    WConvArgs wa;
    wa.seg[0] = { (const float2*)c1w1, (__half2*)(wh + W_C1W1), 4096 };
    wa.seg[1] = { (const float2*)c1w2, (__half2*)(wh + W_C1W2), 8192 };
    wa.seg[2] = { (const float2*)c2w1, (__half2*)(wh + W_C2W1), 8192 };
    wa.seg[3] = { (const float2*)c2w2, (__half2*)(wh + W_C2W2), 8192 };
    wa.seg[4] = { (const float2*)c3w1, (__half2*)(wh + W_C3W1), 16384 };
    wa.seg[5] = { (const float2*)c3w2, (__half2*)(wh + W_C3W2), 32768 };
    wa.seg[6] = { (const float2*)o3w,  (__half2*)(wh + W_O3W),  212992 };
    wa.seg[7] = { (const float2*)o1w,  (__half2*)(wh + W_O1W),  11075584 };
    wa.total = 4096 + 8192 + 8192 + 8192 + 16384 + 32768 + 212992 + 11075584;
    wconv_kernel<<<2048, T>>>(wa);

    // ---- conv1 (64 -> 128 -> 128) ----
    gather_aggr_h_kernel<64><<<(NNODES * 16 + T - 1) / T, T>>>((const uint2*)xh, rowptr, srclist, (uint2*)aggrh);
    hgemm16_kernel<1,0,true><<<dim3(1, gy), T, HG_SMEM>>>(NNODES, 128, 64, 64,  aggrh, wh + W_C1W1, c1b1, nullptr, nullptr, tmph);
    hgemm16_kernel<2,0,true><<<dim3(1, gy), T, HG_SMEM>>>(NNODES, 128, 128, 128, tmph, wh + W_C1W2, c1b2, bn1g, bn1b, hh);
    seg_pool_h_kernel<<<NGRAPH, 64>>>((const __half2*)hh, gstart, (__half2*)poolh, 64, 0);

    // ---- conv2 (128 -> 128 -> 128) ----
    gather_aggr_h_kernel<128><<<(NNODES * 32 + T - 1) / T, T>>>((const uint2*)hh, rowptr, srclist, (uint2*)aggrh);
    hgemm16_kernel<1,0,true><<<dim3(1, gy), T, HG_SMEM>>>(NNODES, 128, 128, 128, aggrh, wh + W_C2W1, c2b1, nullptr, nullptr, tmph);
    hgemm16_kernel<2,0,true><<<dim3(1, gy), T, HG_SMEM>>>(NNODES, 128, 128, 128, tmph, wh + W_C2W2, c2b2, bn2g, bn2b, hh);
    seg_pool_h_kernel<<<NGRAPH, 64>>>((const __half2*)hh, gstart, (__half2*)poolh, 64, 64);

    // ---- conv3 (128 -> 256 -> 256) ----
    gather_aggr_h_kernel<128><<<(NNODES * 32 + T - 1) / T, T>>>((const uint2*)hh, rowptr, srclist, (uint2*)aggrh);
    hgemm16_kernel<1,0,true><<<dim3(2, gy), T, HG_SMEM>>>(NNODES, 256, 128, 128, aggrh, wh + W_C3W1, c3b1, nullptr, nullptr, tmph);
    hgemm16_kernel<2,0,true><<<dim3(2, gy), T, HG_SMEM>>>(NNODES, 256, 256, 256, tmph, wh + W_C3W2, c3b2, bn3g, bn3b, hh);
    seg_pool_h_kernel<<<NGRAPH, 128>>>((const __half2*)hh, gstart, (__half2*)poolh, 128, 128);

    // ---- readout GEMM1: split-K=4, fp32 partials -> scr, reduce -> tmph fp16 ----
    hgemm16_kernel<0,1,false><<<dim3(3328 / 128, 4, 4), T, HG_SMEM>>>(NGRAPH, 3328, 1664, RDIM, poolh, wh + W_O1W, nullptr, nullptr, nullptr, scr);
    readout_reduce_kernel<<<(NGRAPH * 832 + T - 1) / T, T>>>((const float4*)scr, o1b, obng, obnb, (uint2*)tmph);

    // ---- readout GEMM2: split-K=8, partials -> scr2, reduce -> out ----
    float* scr2 = scr + 4 * NGRAPH * 3328;
    hgemm16_kernel<0,1,false><<<dim3(1, 4, 8), T, HG_SMEM>>>(NGRAPH, 128, 416, 3328, tmph, wh + W_O3W, nullptr, nullptr, nullptr, scr2);
    final_reduce_kernel<<<(NGRAPH * 128 + T - 1) / T, T>>>(scr2, o3b, out);
}

// round 11
// speedup vs baseline: 5.3863x; 1.0470x over previous
#include <cuda_runtime.h>
#include <cuda_fp16.h>
#include <cstdint>

#define NNODES 100000
#define NEDGES 1600000
#define NGRAPH 512
#define RDIM   6656

// fp16 weight buffer offsets (halves)
#define W_C1W1 0
#define W_C1W2 8192
#define W_C2W1 24576
#define W_C2W2 40960
#define W_C3W1 57344
#define W_C3W2 90112
#define W_O1W  155648
#define W_O3W  22306816
#define W_TOTAL 22732800

// ---- static device scratch (no allocations allowed) ----
static __device__ __align__(16) __half g_xh   [NNODES * 64];
static __device__ __align__(16) __half g_aggrh[NNODES * 256];
static __device__ __align__(16) __half g_tmph [NNODES * 256];
static __device__ __align__(16) __half g_hh   [NNODES * 256];
static __device__ __align__(16) __half g_wh   [W_TOTAL];
static __device__ __align__(16) __half g_poolh[NGRAPH * RDIM];
static __device__ __align__(16) float  g_scr  [8 * 1024 * 1024];
static __device__ int g_deg[NNODES];
static __device__ int g_cursor[NNODES];
static __device__ int g_rowptr[NNODES + 1];
static __device__ int g_srclist[NEDGES];
static __device__ int g_gstart[NGRAPH + 1];

// ---------------------------------------------------------------------------
// CSR build
// ---------------------------------------------------------------------------
__global__ void zero_deg_kernel(int* __restrict__ deg) {
    int i = blockIdx.x * blockDim.x + threadIdx.x;
    if (i < NNODES) deg[i] = 0;
}
__global__ void hist_kernel(const int* __restrict__ edst, int* __restrict__ deg) {
    int e = blockIdx.x * blockDim.x + threadIdx.x;
    if (e < NEDGES) atomicAdd(&deg[__ldg(edst + e)], 1);
}
__global__ __launch_bounds__(1024) void scan_kernel(const int* __restrict__ deg,
                                                    int* __restrict__ rowptr,
                                                    int* __restrict__ cursor) {
    __shared__ int sums[1024];
    const int t = threadIdx.x;
    const int chunk = (NNODES + 1023) / 1024;
    const int beg = t * chunk;
    const int end = min(beg + chunk, NNODES);
    int s = 0;
    for (int k = beg; k < end; k++) s += deg[k];
    sums[t] = s;
    __syncthreads();
    for (int off = 1; off < 1024; off <<= 1) {
        int v = (t >= off) ? sums[t - off] : 0;
        __syncthreads();
        sums[t] += v;
        __syncthreads();
    }
    int run = sums[t] - s;
    for (int k = beg; k < end; k++) {
        rowptr[k] = run;
        cursor[k] = run;
        run += deg[k];
    }
    if (t == 1023) rowptr[NNODES] = sums[1023];
}
__global__ void fill_kernel(const int* __restrict__ esrc, const int* __restrict__ edst,
                            int* __restrict__ cursor, int* __restrict__ srclist) {
    int e = blockIdx.x * blockDim.x + threadIdx.x;
    if (e >= NEDGES) return;
    int d = __ldg(edst + e);
    int pos = atomicAdd(&cursor[d], 1);
    srclist[pos] = __ldg(esrc + e);
}
__global__ void gstart_kernel(const int* __restrict__ batch, int* __restrict__ gstart) {
    int g = blockIdx.x * blockDim.x + threadIdx.x;
    if (g > NGRAPH) return;
    if (g == NGRAPH) { gstart[NGRAPH] = NNODES; return; }
    int lo = 0, hi = NNODES;
    while (lo < hi) {
        int mid = (lo + hi) >> 1;
        if (__ldg(batch + mid) < g) lo = mid + 1; else hi = mid;
    }
    gstart[g] = lo;
}

// ---------------------------------------------------------------------------
// converts
// ---------------------------------------------------------------------------
__global__ void f2h_kernel(const float2* __restrict__ in, __half2* __restrict__ out, int n2) {
    int i = blockIdx.x * blockDim.x + threadIdx.x;
    if (i < n2) {
        float2 v = __ldg(in + i);
        out[i] = __floats2half2_rn(v.x, v.y);
    }
}

struct WSeg { const float2* src; __half2* dst; int n; };
struct WConvArgs { WSeg seg[8]; int total; };
__global__ void wconv_kernel(WConvArgs a) {
    int stride = gridDim.x * blockDim.x;
    for (int idx = blockIdx.x * blockDim.x + threadIdx.x; idx < a.total; idx += stride) {
        int i = idx;
        #pragma unroll
        for (int s = 0; s < 8; s++) {
            if (i < a.seg[s].n) {
                float2 v = __ldg(a.seg[s].src + i);
                a.seg[s].dst[i] = __floats2half2_rn(v.x, v.y);
                break;
            }
            i -= a.seg[s].n;
        }
    }
}

// ---------------------------------------------------------------------------
// fp16 gather, neighbor loop unrolled x4
// ---------------------------------------------------------------------------
__device__ __forceinline__ float2 h2f2(uint32_t h) {
    return __half22float2(*(__half2*)&h);
}
template<int FH>
__global__ void gather_aggr_h_kernel(const uint2* __restrict__ feat,
                                     const int* __restrict__ rowptr,
                                     const int* __restrict__ srclist,
                                     uint2* __restrict__ aggr) {
    constexpr int L = FH / 4;
    constexpr int NPB = 256 / L;
    int i = blockIdx.x * NPB + threadIdx.x / L;
    if (i >= NNODES) return;
    int c = threadIdx.x % L;

    uint2 v0 = __ldg(&feat[i * L + c]);
    float2 ax = h2f2(v0.x), ay = h2f2(v0.y);

    int j = __ldg(rowptr + i);
    const int end = __ldg(rowptr + i + 1);
    for (; j + 3 < end; j += 4) {
        int s0 = __ldg(srclist + j);
        int s1 = __ldg(srclist + j + 1);
        int s2 = __ldg(srclist + j + 2);
        int s3 = __ldg(srclist + j + 3);
        uint2 t0 = __ldg(&feat[s0 * L + c]);
        uint2 t1 = __ldg(&feat[s1 * L + c]);
        uint2 t2 = __ldg(&feat[s2 * L + c]);
        uint2 t3 = __ldg(&feat[s3 * L + c]);
        float2 a0 = h2f2(t0.x), b0 = h2f2(t0.y);
        float2 a1 = h2f2(t1.x), b1 = h2f2(t1.y);
        float2 a2 = h2f2(t2.x), b2 = h2f2(t2.y);
        float2 a3 = h2f2(t3.x), b3 = h2f2(t3.y);
        ax.x += (a0.x + a1.x) + (a2.x + a3.x);
        ax.y += (a0.y + a1.y) + (a2.y + a3.y);
        ay.x += (b0.x + b1.x) + (b2.x + b3.x);
        ay.y += (b0.y + b1.y) + (b2.y + b3.y);
    }
    for (; j < end; j++) {
        int s0 = __ldg(srclist + j);
        uint2 t0 = __ldg(&feat[s0 * L + c]);
        float2 a = h2f2(t0.x), b = h2f2(t0.y);
        ax.x += a.x; ax.y += a.y; ay.x += b.x; ay.y += b.y;
    }
    __half2 r0 = __floats2half2_rn(ax.x, ax.y);
    __half2 r1 = __floats2half2_rn(ay.x, ay.y);
    uint2 o;
    o.x = *(uint32_t*)&r0; o.y = *(uint32_t*)&r1;
    aggr[i * L + c] = o;
}

// ---------------------------------------------------------------------------
// segment pool -> fp16 pool
// ---------------------------------------------------------------------------
__global__ void seg_pool_h_kernel(const __half2* __restrict__ feat,
                                  const int* __restrict__ gstart,
                                  __half2* __restrict__ pool,
                                  int F2, int off2) {
    int g = blockIdx.x;
    int t = threadIdx.x;
    int beg = __ldg(gstart + g), end = __ldg(gstart + g + 1);
    float2 a0 = make_float2(0.f, 0.f), a1 = make_float2(0.f, 0.f);
    int r = beg;
    for (; r + 1 < end; r += 2) {
        float2 v0 = __half22float2(__ldg(feat + (long long)r * F2 + t));
        float2 v1 = __half22float2(__ldg(feat + (long long)(r + 1) * F2 + t));
        a0.x += v0.x; a0.y += v0.y; a1.x += v1.x; a1.y += v1.y;
    }
    if (r < end) {
        float2 v0 = __half22float2(__ldg(feat + (long long)r * F2 + t));
        a0.x += v0.x; a0.y += v0.y;
    }
    pool[(long long)g * (RDIM / 2) + off2 + t] = __floats2half2_rn(a0.x + a1.x, a0.y + a1.y);
}

__global__ void fp_copy_kernel(const float4* __restrict__ fp, uint2* __restrict__ pool) {
    int col = blockIdx.x * blockDim.x + threadIdx.x;
    int row = blockIdx.y;
    if (col >= 1536) return;
    float4 v = __ldg(fp + row * 1536 + col);
    __half2 h0 = __floats2half2_rn(v.x, v.y);
    __half2 h1 = __floats2half2_rn(v.z, v.w);
    uint2 o;
    o.x = *(uint32_t*)&h0; o.y = *(uint32_t*)&h1;
    pool[row * (RDIM / 4) + 128 + col] = o;
}

// ---------------------------------------------------------------------------
// split-K reductions (fixed order)
// ---------------------------------------------------------------------------
__global__ void readout_reduce_kernel(const float4* __restrict__ part,
                                      const float* __restrict__ bias,
                                      const float* __restrict__ bng,
                                      const float* __restrict__ bnb,
                                      uint2* __restrict__ outh) {
    const int N4 = 3328 / 4;
    int idx = blockIdx.x * blockDim.x + threadIdx.x;
    if (idx >= NGRAPH * N4) return;
    const long long SZ4 = (long long)NGRAPH * N4;
    int col = (idx % N4) * 4;
    float4 s = part[idx];
    #pragma unroll
    for (int z = 1; z < 4; z++) {
        float4 t = part[idx + z * SZ4];
        s.x += t.x; s.y += t.y; s.z += t.z; s.w += t.w;
    }
    const float bninv = rsqrtf(1.0f + 1e-5f);
    float* sp = &s.x;
    #pragma unroll
    for (int c = 0; c < 4; c++) {
        float v = (sp[c] + __ldg(bias + col + c)) * (__ldg(bng + col + c) * bninv) + __ldg(bnb + col + c);
        sp[c] = fmaxf(v, 0.0f);
    }
    __half2 h0 = __floats2half2_rn(s.x, s.y);
    __half2 h1 = __floats2half2_rn(s.z, s.w);
    uint2 o;
    o.x = *(uint32_t*)&h0; o.y = *(uint32_t*)&h1;
    outh[idx] = o;
}
__global__ void final_reduce_kernel(const float* __restrict__ part,
                                    const float* __restrict__ bias,
                                    float* __restrict__ out) {
    int idx = blockIdx.x * blockDim.x + threadIdx.x;
    if (idx >= NGRAPH * 128) return;
    float s = 0.0f;
    #pragma unroll
    for (int z = 0; z < 8; z++) s += part[idx + z * NGRAPH * 128];
    out[idx] = s + __ldg(bias + (idx & 127));
}

// ---------------------------------------------------------------------------
// All-fp16 tensor-core GEMM, 3-stage cp.async pipeline, dynamic smem.
// ---------------------------------------------------------------------------
#define SKA2 40
#define SKB2 136
#define A_STG (128 * SKA2)
#define B_STG (32 * SKB2)
#define HG_SMEM (3 * (A_STG + B_STG) * 2)

__device__ __forceinline__ uint32_t smem_u32(const void* p) {
    uint32_t a;
    asm("{ .reg .u64 t; cvta.to.shared.u64 t, %1; cvt.u32.u64 %0, t; }" : "=r"(a) : "l"(p));
    return a;
}
__device__ __forceinline__ void cp16(uint32_t s, const void* g, int sz) {
    asm volatile("cp.async.cg.shared.global [%0], [%1], 16, %2;" :: "r"(s), "l"(g), "r"(sz));
}
#define CP_COMMIT() asm volatile("cp.async.commit_group;")
#define LDMATRIX_X4(r0, r1, r2, r3, addr) \
    asm volatile("ldmatrix.sync.aligned.m8n8.x4.shared.b16 {%0,%1,%2,%3}, [%4];" \
        : "=r"(r0), "=r"(r1), "=r"(r2), "=r"(r3) : "r"(addr))
#define LDMATRIX_X4_T(r0, r1, r2, r3, addr) \
    asm volatile("ldmatrix.sync.aligned.m8n8.x4.trans.shared.b16 {%0,%1,%2,%3}, [%4];" \
        : "=r"(r0), "=r"(r1), "=r"(r2), "=r"(r3) : "r"(addr))

template<int EPI, int SPLIT, bool CH>
__global__ __launch_bounds__(256, 2) void hgemm16_kernel(
    int M, int Nn, int K, int ldA,
    const __half* __restrict__ A, const __half* __restrict__ B,
    const float* __restrict__ bias,
    const float* __restrict__ bng, const float* __restrict__ bnb,
    void* __restrict__ Cv)
{
    extern __shared__ __half dsm[];
    __half* AsBase = dsm;
    __half* BsBase = dsm + 3 * A_STG;

    const int tid = threadIdx.x, bx = blockIdx.x, by = blockIdx.y, bz = blockIdx.z;
    const int warp = tid >> 5, lane = tid & 31;
    const int wm = (warp >> 2) * 64;
    const int wn = (warp & 3) * 32;
    const int lr = lane >> 2;
    const int lc = lane & 3;

    const long long koff = (long long)bz * K;

    auto issueT = [&](int kk, int stg) {
        __half* As = AsBase + stg * A_STG;
        __half* Bs = BsBase + stg * B_STG;
        #pragma unroll
        for (int q = 0; q < 2; q++) {
            int c = tid + q * 256;
            int row = c >> 2, kc = (c & 3) * 8;
            int gr = by * 128 + row;
            uint32_t sa = smem_u32(&As[row * SKA2 + kc]);
            const __half* g = A + (long long)gr * ldA + koff + kk + kc;
            cp16(sa, g, gr < M ? 16 : 0);
        }
        #pragma unroll
        for (int q = 0; q < 2; q++) {
            int c = tid + q * 256;
            int row = c >> 4, nc = (c & 15) * 8;
            uint32_t sb = smem_u32(&Bs[row * SKB2 + nc]);
            const __half* g = B + (koff + kk + row) * (long long)Nn + (long long)bx * 128 + nc;
            cp16(sb, g, 16);
        }
        CP_COMMIT();
    };

    float acc[4][4][4];
    #pragma unroll
    for (int i = 0; i < 4; i++)
        #pragma unroll
        for (int j = 0; j < 4; j++)
            #pragma unroll
            for (int t = 0; t < 4; t++) acc[i][j][t] = 0.0f;

    const int a_r = lane & 15, a_s = lane >> 4;
    const int b_k = lane & 7,  b_s = lane >> 3;

    auto compute = [&](int stg) {
        const uint32_t aB = smem_u32(AsBase + stg * A_STG);
        const uint32_t bB = smem_u32(BsBase + stg * B_STG);
        #pragma unroll
        for (int ks = 0; ks < 32; ks += 16) {
            uint32_t af[4][4], bf[4][2];
            #pragma unroll
            for (int mt = 0; mt < 4; mt++) {
                uint32_t addr = aB + (uint32_t)(((wm + mt * 16 + a_r) * SKA2 + ks + a_s * 8) * 2);
                LDMATRIX_X4(af[mt][0], af[mt][1], af[mt][2], af[mt][3], addr);
            }
            #pragma unroll
            for (int np = 0; np < 2; np++) {
                uint32_t addr = bB + (uint32_t)(((ks + (b_s & 1) * 8 + b_k) * SKB2 + wn + np * 16 + (b_s >> 1) * 8) * 2);
                uint32_t r0, r1, r2, r3;
                LDMATRIX_X4_T(r0, r1, r2, r3, addr);
                bf[2*np][0] = r0; bf[2*np][1] = r1;
                bf[2*np+1][0] = r2; bf[2*np+1][1] = r3;
            }
            #pragma unroll
            for (int mt = 0; mt < 4; mt++)
                #pragma unroll
                for (int nt = 0; nt < 4; nt++) {
                    asm volatile(
                        "mma.sync.aligned.m16n8k16.row.col.f32.f16.f16.f32 "
                        "{%0,%1,%2,%3}, {%4,%5,%6,%7}, {%8,%9}, {%0,%1,%2,%3};"
                        : "+f"(acc[mt][nt][0]), "+f"(acc[mt][nt][1]),
                          "+f"(acc[mt][nt][2]), "+f"(acc[mt][nt][3])
                        : "r"(af[mt][0]), "r"(af[mt][1]), "r"(af[mt][2]), "r"(af[mt][3]),
                          "r"(bf[nt][0]), "r"(bf[nt][1]));
                }
        }
    };

    const int nIter = K / 32;
    issueT(0, 0);
    issueT(32, 1);
    int stg = 0;
    for (int it = 0; it < nIter; it++) {
        if (it < nIter - 1) {
            asm volatile("cp.async.wait_group 1;");
        } else {
            asm volatile("cp.async.wait_group 0;");
        }
        __syncthreads();
        compute(stg);
        if (it + 2 < nIter) {
            int ns = stg + 2; if (ns >= 3) ns -= 3;
            issueT((it + 2) * 32, ns);
        }
        if (++stg == 3) stg = 0;
    }

    if (SPLIT) {
        float* Cz = (float*)Cv + (long long)bz * M * Nn;
        #pragma unroll
        for (int mt = 0; mt < 4; mt++) {
            int r0 = by * 128 + wm + mt * 16 + lr;
            int r1 = r0 + 8;
            #pragma unroll
            for (int nt = 0; nt < 4; nt++) {
                int col = bx * 128 + wn + nt * 8 + 2 * lc;
                if (r0 < M) *(float2*)&Cz[(long long)r0 * Nn + col] = make_float2(acc[mt][nt][0], acc[mt][nt][1]);
                if (r1 < M) *(float2*)&Cz[(long long)r1 * Nn + col] = make_float2(acc[mt][nt][2], acc[mt][nt][3]);
            }
        }
        return;
    }

    const float bninv = rsqrtf(1.0f + 1e-5f);
    #pragma unroll
    for (int mt = 0; mt < 4; mt++) {
        int r0 = by * 128 + wm + mt * 16 + lr;
        int r1 = r0 + 8;
        #pragma unroll
        for (int nt = 0; nt < 4; nt++) {
            int col = bx * 128 + wn + nt * 8 + 2 * lc;
            float b0 = __ldg(bias + col);
            float b1 = __ldg(bias + col + 1);
            float g0 = 1.f, g1 = 1.f, be0 = 0.f, be1 = 0.f;
            if (EPI == 2) {
                g0 = __ldg(bng + col) * bninv;  g1 = __ldg(bng + col + 1) * bninv;
                be0 = __ldg(bnb + col);         be1 = __ldg(bnb + col + 1);
            }
            float v00 = acc[mt][nt][0] + b0, v01 = acc[mt][nt][1] + b1;
            float v10 = acc[mt][nt][2] + b0, v11 = acc[mt][nt][3] + b1;
            if (EPI == 2) {
                v00 = v00 * g0 + be0; v01 = v01 * g1 + be1;
                v10 = v10 * g0 + be0; v11 = v11 * g1 + be1;
            }
            if (EPI >= 1) {
                v00 = fmaxf(v00, 0.f); v01 = fmaxf(v01, 0.f);
                v10 = fmaxf(v10, 0.f); v11 = fmaxf(v11, 0.f);
            }
            if (CH) {
                __half* Ch = (__half*)Cv;
                if (r0 < M) *(__half2*)&Ch[(long long)r0 * Nn + col] = __floats2half2_rn(v00, v01);
                if (r1 < M) *(__half2*)&Ch[(long long)r1 * Nn + col] = __floats2half2_rn(v10, v11);
            } else {
                float* Cf = (float*)Cv;
                if (r0 < M) *(float2*)&Cf[(long long)r0 * Nn + col] = make_float2(v00, v01);
                if (r1 < M) *(float2*)&Cf[(long long)r1 * Nn + col] = make_float2(v10, v11);
            }
        }
    }
}

// ---------------------------------------------------------------------------
extern "C" void kernel_launch(void* const* d_in, const int* in_sizes, int n_in,
                              void* d_out, int out_size) {
    const float* x     = (const float*)d_in[0];
    const int*   ei    = (const int*)  d_in[1];
    const int*   src   = ei;
    const int*   dst   = ei + NEDGES;
    const int*   batch = (const int*)  d_in[2];
    const float* fp    = (const float*)d_in[3];
    const float* c1w1 = (const float*)d_in[4],  *c1b1 = (const float*)d_in[5];
    const float* c1w2 = (const float*)d_in[6],  *c1b2 = (const float*)d_in[7];
    const float* c2w1 = (const float*)d_in[8],  *c2b1 = (const float*)d_in[9];
    const float* c2w2 = (const float*)d_in[10], *c2b2 = (const float*)d_in[11];
    const float* c3w1 = (const float*)d_in[12], *c3b1 = (const float*)d_in[13];
    const float* c3w2 = (const float*)d_in[14], *c3b2 = (const float*)d_in[15];
    const float* bn1g = (const float*)d_in[16], *bn1b = (const float*)d_in[17];
    const float* bn2g = (const float*)d_in[18], *bn2b = (const float*)d_in[19];
    const float* bn3g = (const float*)d_in[20], *bn3b = (const float*)d_in[21];
    const float* o1w  = (const float*)d_in[22], *o1b  = (const float*)d_in[23];
    const float* obng = (const float*)d_in[24], *obnb = (const float*)d_in[25];
    const float* o3w  = (const float*)d_in[26], *o3b  = (const float*)d_in[27];
    float* out = (float*)d_out;

    __half *xh, *aggrh, *tmph, *hh, *wh, *poolh;
    float *scr;
    int *deg, *cursor, *rowptr, *srclist, *gstart;
    cudaGetSymbolAddress((void**)&xh,      g_xh);
    cudaGetSymbolAddress((void**)&aggrh,   g_aggrh);
    cudaGetSymbolAddress((void**)&tmph,    g_tmph);
    cudaGetSymbolAddress((void**)&hh,      g_hh);
    cudaGetSymbolAddress((void**)&wh,      g_wh);
    cudaGetSymbolAddress((void**)&poolh,   g_poolh);
    cudaGetSymbolAddress((void**)&scr,     g_scr);
    cudaGetSymbolAddress((void**)&deg,     g_deg);
    cudaGetSymbolAddress((void**)&cursor,  g_cursor);
    cudaGetSymbolAddress((void**)&rowptr,  g_rowptr);
    cudaGetSymbolAddress((void**)&srclist, g_srclist);
    cudaGetSymbolAddress((void**)&gstart,  g_gstart);

    cudaFuncSetAttribute(hgemm16_kernel<1,0,true>,  cudaFuncAttributeMaxDynamicSharedMemorySize, HG_SMEM);
    cudaFuncSetAttribute(hgemm16_kernel<2,0,true>,  cudaFuncAttributeMaxDynamicSharedMemorySize, HG_SMEM);
    cudaFuncSetAttribute(hgemm16_kernel<0,1,false>, cudaFuncAttributeMaxDynamicSharedMemorySize, HG_SMEM);

    const int T = 256;
    const int gy = (NNODES + 127) / 128;

    // ---- fork/join infrastructure ----
    cudaStream_t sB, sC, sP;
    cudaStreamCreateWithFlags(&sB, cudaStreamNonBlocking);   // big weight convert
    cudaStreamCreateWithFlags(&sC, cudaStreamNonBlocking);   // small converts
    cudaStreamCreateWithFlags(&sP, cudaStreamNonBlocking);   // seg pools
    cudaEvent_t evRoot, evB, evC, evH[3], evP[3];
    cudaEventCreateWithFlags(&evRoot, cudaEventDisableTiming);
    cudaEventCreateWithFlags(&evB,    cudaEventDisableTiming);
    cudaEventCreateWithFlags(&evC,    cudaEventDisableTiming);
    for (int i = 0; i < 3; i++) {
        cudaEventCreateWithFlags(&evH[i], cudaEventDisableTiming);
        cudaEventCreateWithFlags(&evP[i], cudaEventDisableTiming);
    }

    cudaEventRecord(evRoot, 0);
    cudaStreamWaitEvent(sB, evRoot, 0);
    cudaStreamWaitEvent(sC, evRoot, 0);

    // ---- sB: big readout-weight converts (needed only at readout) ----
    {
        WConvArgs wb = {};
        wb.seg[0] = { (const float2*)o3w, (__half2*)(wh + W_O3W), 212992 };
        wb.seg[1] = { (const float2*)o1w, (__half2*)(wh + W_O1W), 11075584 };
        wb.total = 212992 + 11075584;
        wconv_kernel<<<2048, T, 0, sB>>>(wb);
        cudaEventRecord(evB, sB);
    }
    // ---- sC: x convert + fingerprint + conv weights (needed at conv1) ----
    {
        f2h_kernel<<<(NNODES * 32 + T - 1) / T, T, 0, sC>>>((const float2*)x, (__half2*)xh, NNODES * 32);
        fp_copy_kernel<<<dim3((1536 + T - 1) / T, NGRAPH), T, 0, sC>>>((const float4*)fp, (uint2*)poolh);
        WConvArgs wc = {};
        wc.seg[0] = { (const float2*)c1w1, (__half2*)(wh + W_C1W1), 4096 };
        wc.seg[1] = { (const float2*)c1w2, (__half2*)(wh + W_C1W2), 8192 };
        wc.seg[2] = { (const float2*)c2w1, (__half2*)(wh + W_C2W1), 8192 };
        wc.seg[3] = { (const float2*)c2w2, (__half2*)(wh + W_C2W2), 8192 };
        wc.seg[4] = { (const float2*)c3w1, (__half2*)(wh + W_C3W1), 16384 };
        wc.seg[5] = { (const float2*)c3w2, (__half2*)(wh + W_C3W2), 32768 };
        wc.total = 4096 + 8192 + 8192 + 8192 + 16384 + 32768;
        wconv_kernel<<<256, T, 0, sC>>>(wc);
        cudaEventRecord(evC, sC);
    }
    // ---- main: CSR build (critical path for gather1) ----
    zero_deg_kernel<<<(NNODES + T - 1) / T, T>>>(deg);
    hist_kernel<<<(NEDGES + T - 1) / T, T>>>(dst, deg);
    scan_kernel<<<1, 1024>>>(deg, rowptr, cursor);
    fill_kernel<<<(NEDGES + T - 1) / T, T>>>(src, dst, cursor, srclist);
    gstart_kernel<<<3, 256>>>(batch, gstart);
    cudaStreamWaitEvent(0, evC, 0);   // xh + conv weights ready

    // ---- conv1 (64 -> 128 -> 128) ----
    gather_aggr_h_kernel<64><<<(NNODES * 16 + T - 1) / T, T>>>((const uint2*)xh, rowptr, srclist, (uint2*)aggrh);
    hgemm16_kernel<1,0,true><<<dim3(1, gy), T, HG_SMEM>>>(NNODES, 128, 64, 64,  aggrh, wh + W_C1W1, c1b1, nullptr, nullptr, tmph);
    hgemm16_kernel<2,0,true><<<dim3(1, gy), T, HG_SMEM>>>(NNODES, 128, 128, 128, tmph, wh + W_C1W2, c1b2, bn1g, bn1b, hh);
    cudaEventRecord(evH[0], 0);
    cudaStreamWaitEvent(sP, evH[0], 0);
    seg_pool_h_kernel<<<NGRAPH, 64, 0, sP>>>((const __half2*)hh, gstart, (__half2*)poolh, 64, 0);
    cudaEventRecord(evP[0], sP);

    // ---- conv2 (128 -> 128 -> 128) ----
    gather_aggr_h_kernel<128><<<(NNODES * 32 + T - 1) / T, T>>>((const uint2*)hh, rowptr, srclist, (uint2*)aggrh);
    hgemm16_kernel<1,0,true><<<dim3(1, gy), T, HG_SMEM>>>(NNODES, 128, 128, 128, aggrh, wh + W_C2W1, c2b1, nullptr, nullptr, tmph);
    cudaStreamWaitEvent(0, evP[0], 0);   // pool1 must finish before hh overwrite
    hgemm16_kernel<2,0,true><<<dim3(1, gy), T, HG_SMEM>>>(NNODES, 128, 128, 128, tmph, wh + W_C2W2, c2b2, bn2g, bn2b, hh);
    cudaEventRecord(evH[1], 0);
    cudaStreamWaitEvent(sP, evH[1], 0);
    seg_pool_h_kernel<<<NGRAPH, 64, 0, sP>>>((const __half2*)hh, gstart, (__half2*)poolh, 64, 64);
    cudaEventRecord(evP[1], sP);

    // ---- conv3 (128 -> 256 -> 256) ----
    gather_aggr_h_kernel<128><<<(NNODES * 32 + T - 1) / T, T>>>((const uint2*)hh, rowptr, srclist, (uint2*)aggrh);
    hgemm16_kernel<1,0,true><<<dim3(2, gy), T, HG_SMEM>>>(NNODES, 256, 128, 128, aggrh, wh + W_C3W1, c3b1, nullptr, nullptr, tmph);
    cudaStreamWaitEvent(0, evP[1], 0);   // pool2 must finish before hh overwrite
    hgemm16_kernel<2,0,true><<<dim3(2, gy), T, HG_SMEM>>>(NNODES, 256, 256, 256, tmph, wh + W_C3W2, c3b2, bn3g, bn3b, hh);
    cudaEventRecord(evH[2], 0);
    cudaStreamWaitEvent(sP, evH[2], 0);
    seg_pool_h_kernel<<<NGRAPH, 128, 0, sP>>>((const __half2*)hh, gstart, (__half2*)poolh, 128, 128);
    cudaEventRecord(evP[2], sP);

    // ---- join: pools + big weights before readout ----
    cudaStreamWaitEvent(0, evP[2], 0);
    cudaStreamWaitEvent(0, evB, 0);

    // ---- readout GEMM1: split-K=4, fp32 partials -> scr, reduce -> tmph fp16 ----
    hgemm16_kernel<0,1,false><<<dim3(3328 / 128, 4, 4), T, HG_SMEM>>>(NGRAPH, 3328, 1664, RDIM, poolh, wh + W_O1W, nullptr, nullptr, nullptr, scr);
    readout_reduce_kernel<<<(NGRAPH * 832 + T - 1) / T, T>>>((const float4*)scr, o1b, obng, obnb, (uint2*)tmph);

    // ---- readout GEMM2: split-K=8, partials -> scr2, reduce -> out ----
    float* scr2 = scr + 4 * NGRAPH * 3328;
    hgemm16_kernel<0,1,false><<<dim3(1, 4, 8), T, HG_SMEM>>>(NGRAPH, 128, 416, 3328, tmph, wh + W_O3W, nullptr, nullptr, nullptr, scr2);
    final_reduce_kernel<<<(NGRAPH * 128 + T - 1) / T, T>>>(scr2, o3b, out);

    // ---- cleanup (host objects only) ----
    cudaEventDestroy(evRoot); cudaEventDestroy(evB); cudaEventDestroy(evC);
    for (int i = 0; i < 3; i++) { cudaEventDestroy(evH[i]); cudaEventDestroy(evP[i]); }
    cudaStreamDestroy(sB); cudaStreamDestroy(sC); cudaStreamDestroy(sP);
}

// round 12
// speedup vs baseline: 5.6160x; 1.0426x over previous
#include <cuda_runtime.h>
#include <cuda_fp16.h>
#include <cstdint>

#define NNODES 100000
#define NEDGES 1600000
#define NGRAPH 512
#define RDIM   6656

// fp16 weight buffer offsets (halves)
#define W_C1W1 0
#define W_C1W2 8192
#define W_C2W1 24576
#define W_C2W2 40960
#define W_C3W1 57344
#define W_C3W2 90112
#define W_O1W  155648
#define W_O3W  22306816
#define W_TOTAL 22732800

// ---- static device scratch (no allocations allowed) ----
static __device__ __align__(16) __half g_xh   [NNODES * 64];
static __device__ __align__(16) __half g_aggrh[NNODES * 256];
static __device__ __align__(16) __half g_tmph [NNODES * 256];
static __device__ __align__(16) __half g_hh   [NNODES * 256];
static __device__ __align__(16) __half g_wh   [W_TOTAL];
static __device__ __align__(16) __half g_poolh[NGRAPH * RDIM];
static __device__ __align__(16) float  g_scr  [8 * 1024 * 1024];
static __device__ int g_deg[NNODES];
static __device__ int g_cursor[NNODES];
static __device__ int g_rowptr[NNODES + 1];
static __device__ int g_srclist[NEDGES];
static __device__ int g_gstart[NGRAPH + 1];

// ---------------------------------------------------------------------------
// CSR build
// ---------------------------------------------------------------------------
__global__ void zero_deg_kernel(int* __restrict__ deg) {
    int i = blockIdx.x * blockDim.x + threadIdx.x;
    if (i < NNODES) deg[i] = 0;
}
__global__ void hist_kernel(const int* __restrict__ edst, int* __restrict__ deg) {
    int e = blockIdx.x * blockDim.x + threadIdx.x;
    if (e < NEDGES) atomicAdd(&deg[__ldg(edst + e)], 1);
}
__global__ __launch_bounds__(1024) void scan_kernel(const int* __restrict__ deg,
                                                    int* __restrict__ rowptr,
                                                    int* __restrict__ cursor) {
    __shared__ int sums[1024];
    const int t = threadIdx.x;
    const int chunk = (NNODES + 1023) / 1024;
    const int beg = t * chunk;
    const int end = min(beg + chunk, NNODES);
    int s = 0;
    for (int k = beg; k < end; k++) s += deg[k];
    sums[t] = s;
    __syncthreads();
    for (int off = 1; off < 1024; off <<= 1) {
        int v = (t >= off) ? sums[t - off] : 0;
        __syncthreads();
        sums[t] += v;
        __syncthreads();
    }
    int run = sums[t] - s;
    for (int k = beg; k < end; k++) {
        rowptr[k] = run;
        cursor[k] = run;
        run += deg[k];
    }
    if (t == 1023) rowptr[NNODES] = sums[1023];
}
__global__ void fill_kernel(const int* __restrict__ esrc, const int* __restrict__ edst,
                            int* __restrict__ cursor, int* __restrict__ srclist) {
    int e = blockIdx.x * blockDim.x + threadIdx.x;
    if (e >= NEDGES) return;
    int d = __ldg(edst + e);
    int pos = atomicAdd(&cursor[d], 1);
    srclist[pos] = __ldg(esrc + e);
}
__global__ void gstart_kernel(const int* __restrict__ batch, int* __restrict__ gstart) {
    int g = blockIdx.x * blockDim.x + threadIdx.x;
    if (g > NGRAPH) return;
    if (g == NGRAPH) { gstart[NGRAPH] = NNODES; return; }
    int lo = 0, hi = NNODES;
    while (lo < hi) {
        int mid = (lo + hi) >> 1;
        if (__ldg(batch + mid) < g) lo = mid + 1; else hi = mid;
    }
    gstart[g] = lo;
}

// ---------------------------------------------------------------------------
// converts
// ---------------------------------------------------------------------------
__global__ void f2h_kernel(const float2* __restrict__ in, __half2* __restrict__ out, int n2) {
    int i = blockIdx.x * blockDim.x + threadIdx.x;
    if (i < n2) {
        float2 v = __ldg(in + i);
        out[i] = __floats2half2_rn(v.x, v.y);
    }
}

struct WSeg { const float2* src; __half2* dst; int n; };
struct WConvArgs { WSeg seg[8]; int total; };
__global__ void wconv_kernel(WConvArgs a) {
    int stride = gridDim.x * blockDim.x;
    for (int idx = blockIdx.x * blockDim.x + threadIdx.x; idx < a.total; idx += stride) {
        int i = idx;
        #pragma unroll
        for (int s = 0; s < 8; s++) {
            if (i < a.seg[s].n) {
                float2 v = __ldg(a.seg[s].src + i);
                a.seg[s].dst[i] = __floats2half2_rn(v.x, v.y);
                break;
            }
            i -= a.seg[s].n;
        }
    }
}

// ---------------------------------------------------------------------------
// fp16 gather, neighbor loop unrolled x4
// ---------------------------------------------------------------------------
__device__ __forceinline__ float2 h2f2(uint32_t h) {
    return __half22float2(*(__half2*)&h);
}
template<int FH>
__global__ void gather_aggr_h_kernel(const uint2* __restrict__ feat,
                                     const int* __restrict__ rowptr,
                                     const int* __restrict__ srclist,
                                     uint2* __restrict__ aggr) {
    constexpr int L = FH / 4;
    constexpr int NPB = 256 / L;
    int i = blockIdx.x * NPB + threadIdx.x / L;
    if (i >= NNODES) return;
    int c = threadIdx.x % L;

    uint2 v0 = __ldg(&feat[i * L + c]);
    float2 ax = h2f2(v0.x), ay = h2f2(v0.y);

    int j = __ldg(rowptr + i);
    const int end = __ldg(rowptr + i + 1);
    for (; j + 3 < end; j += 4) {
        int s0 = __ldg(srclist + j);
        int s1 = __ldg(srclist + j + 1);
        int s2 = __ldg(srclist + j + 2);
        int s3 = __ldg(srclist + j + 3);
        uint2 t0 = __ldg(&feat[s0 * L + c]);
        uint2 t1 = __ldg(&feat[s1 * L + c]);
        uint2 t2 = __ldg(&feat[s2 * L + c]);
        uint2 t3 = __ldg(&feat[s3 * L + c]);
        float2 a0 = h2f2(t0.x), b0 = h2f2(t0.y);
        float2 a1 = h2f2(t1.x), b1 = h2f2(t1.y);
        float2 a2 = h2f2(t2.x), b2 = h2f2(t2.y);
        float2 a3 = h2f2(t3.x), b3 = h2f2(t3.y);
        ax.x += (a0.x + a1.x) + (a2.x + a3.x);
        ax.y += (a0.y + a1.y) + (a2.y + a3.y);
        ay.x += (b0.x + b1.x) + (b2.x + b3.x);
        ay.y += (b0.y + b1.y) + (b2.y + b3.y);
    }
    for (; j < end; j++) {
        int s0 = __ldg(srclist + j);
        uint2 t0 = __ldg(&feat[s0 * L + c]);
        float2 a = h2f2(t0.x), b = h2f2(t0.y);
        ax.x += a.x; ax.y += a.y; ay.x += b.x; ay.y += b.y;
    }
    __half2 r0 = __floats2half2_rn(ax.x, ax.y);
    __half2 r1 = __floats2half2_rn(ay.x, ay.y);
    uint2 o;
    o.x = *(uint32_t*)&r0; o.y = *(uint32_t*)&r1;
    aggr[i * L + c] = o;
}

// ---------------------------------------------------------------------------
// segment pool -> fp16 pool
// ---------------------------------------------------------------------------
__global__ void seg_pool_h_kernel(const __half2* __restrict__ feat,
                                  const int* __restrict__ gstart,
                                  __half2* __restrict__ pool,
                                  int F2, int off2) {
    int g = blockIdx.x;
    int t = threadIdx.x;
    int beg = __ldg(gstart + g), end = __ldg(gstart + g + 1);
    float2 a0 = make_float2(0.f, 0.f), a1 = make_float2(0.f, 0.f);
    int r = beg;
    for (; r + 1 < end; r += 2) {
        float2 v0 = __half22float2(__ldg(feat + (long long)r * F2 + t));
        float2 v1 = __half22float2(__ldg(feat + (long long)(r + 1) * F2 + t));
        a0.x += v0.x; a0.y += v0.y; a1.x += v1.x; a1.y += v1.y;
    }
    if (r < end) {
        float2 v0 = __half22float2(__ldg(feat + (long long)r * F2 + t));
        a0.x += v0.x; a0.y += v0.y;
    }
    pool[(long long)g * (RDIM / 2) + off2 + t] = __floats2half2_rn(a0.x + a1.x, a0.y + a1.y);
}

__global__ void fp_copy_kernel(const float4* __restrict__ fp, uint2* __restrict__ pool) {
    int col = blockIdx.x * blockDim.x + threadIdx.x;
    int row = blockIdx.y;
    if (col >= 1536) return;
    float4 v = __ldg(fp + row * 1536 + col);
    __half2 h0 = __floats2half2_rn(v.x, v.y);
    __half2 h1 = __floats2half2_rn(v.z, v.w);
    uint2 o;
    o.x = *(uint32_t*)&h0; o.y = *(uint32_t*)&h1;
    pool[row * (RDIM / 4) + 128 + col] = o;
}

// ---------------------------------------------------------------------------
// split-K reductions (fixed order)
// ---------------------------------------------------------------------------
__global__ void readout_reduce_kernel(const float4* __restrict__ part,
                                      const float* __restrict__ bias,
                                      const float* __restrict__ bng,
                                      const float* __restrict__ bnb,
                                      uint2* __restrict__ outh) {
    const int N4 = 3328 / 4;
    int idx = blockIdx.x * blockDim.x + threadIdx.x;
    if (idx >= NGRAPH * N4) return;
    const long long SZ4 = (long long)NGRAPH * N4;
    int col = (idx % N4) * 4;
    float4 s = part[idx];
    #pragma unroll
    for (int z = 1; z < 4; z++) {
        float4 t = part[idx + z * SZ4];
        s.x += t.x; s.y += t.y; s.z += t.z; s.w += t.w;
    }
    const float bninv = rsqrtf(1.0f + 1e-5f);
    float* sp = &s.x;
    #pragma unroll
    for (int c = 0; c < 4; c++) {
        float v = (sp[c] + __ldg(bias + col + c)) * (__ldg(bng + col + c) * bninv) + __ldg(bnb + col + c);
        sp[c] = fmaxf(v, 0.0f);
    }
    __half2 h0 = __floats2half2_rn(s.x, s.y);
    __half2 h1 = __floats2half2_rn(s.z, s.w);
    uint2 o;
    o.x = *(uint32_t*)&h0; o.y = *(uint32_t*)&h1;
    outh[idx] = o;
}
__global__ void final_reduce_kernel(const float* __restrict__ part,
                                    const float* __restrict__ bias,
                                    float* __restrict__ out) {
    int idx = blockIdx.x * blockDim.x + threadIdx.x;
    if (idx >= NGRAPH * 128) return;
    float s = 0.0f;
    #pragma unroll
    for (int z = 0; z < 8; z++) s += part[idx + z * NGRAPH * 128];
    out[idx] = s + __ldg(bias + (idx & 127));
}

// ---------------------------------------------------------------------------
// shared GEMM machinery
// ---------------------------------------------------------------------------
#define SKA2 40
#define SKB2 136
#define A_STG (128 * SKA2)
#define B_STG (32 * SKB2)
#define HG_SMEM (3 * (A_STG + B_STG) * 2)
#define H1_STG (128 * SKB2)
#define FU_SMEM ((3 * (A_STG + B_STG) + H1_STG) * 2)

__device__ __forceinline__ uint32_t smem_u32(const void* p) {
    uint32_t a;
    asm("{ .reg .u64 t; cvta.to.shared.u64 t, %1; cvt.u32.u64 %0, t; }" : "=r"(a) : "l"(p));
    return a;
}
__device__ __forceinline__ void cp16(uint32_t s, const void* g, int sz) {
    asm volatile("cp.async.cg.shared.global [%0], [%1], 16, %2;" :: "r"(s), "l"(g), "r"(sz));
}
#define CP_COMMIT() asm volatile("cp.async.commit_group;")
#define LDMATRIX_X4(r0, r1, r2, r3, addr) \
    asm volatile("ldmatrix.sync.aligned.m8n8.x4.shared.b16 {%0,%1,%2,%3}, [%4];" \
        : "=r"(r0), "=r"(r1), "=r"(r2), "=r"(r3) : "r"(addr))
#define LDMATRIX_X4_T(r0, r1, r2, r3, addr) \
    asm volatile("ldmatrix.sync.aligned.m8n8.x4.trans.shared.b16 {%0,%1,%2,%3}, [%4];" \
        : "=r"(r0), "=r"(r1), "=r"(r2), "=r"(r3) : "r"(addr))
#define HMMA16816(acc, a0, a1, a2, a3, b0, b1) \
    asm volatile("mma.sync.aligned.m16n8k16.row.col.f32.f16.f16.f32 " \
        "{%0,%1,%2,%3}, {%4,%5,%6,%7}, {%8,%9}, {%0,%1,%2,%3};" \
        : "+f"((acc)[0]), "+f"((acc)[1]), "+f"((acc)[2]), "+f"((acc)[3]) \
        : "r"(a0), "r"(a1), "r"(a2), "r"(a3), "r"(b0), "r"(b1))

// ---------------------------------------------------------------------------
// unfused GEMM (conv3 + readout)
// ---------------------------------------------------------------------------
template<int EPI, int SPLIT, bool CH>
__global__ __launch_bounds__(256, 2) void hgemm16_kernel(
    int M, int Nn, int K, int ldA,
    const __half* __restrict__ A, const __half* __restrict__ B,
    const float* __restrict__ bias,
    const float* __restrict__ bng, const float* __restrict__ bnb,
    void* __restrict__ Cv)
{
    extern __shared__ __half dsm[];
    __half* AsBase = dsm;
    __half* BsBase = dsm + 3 * A_STG;

    const int tid = threadIdx.x, bx = blockIdx.x, by = blockIdx.y, bz = blockIdx.z;
    const int warp = tid >> 5, lane = tid & 31;
    const int wm = (warp >> 2) * 64;
    const int wn = (warp & 3) * 32;
    const int lr = lane >> 2;
    const int lc = lane & 3;

    const long long koff = (long long)bz * K;

    auto issueT = [&](int kk, int stg) {
        __half* As = AsBase + stg * A_STG;
        __half* Bs = BsBase + stg * B_STG;
        #pragma unroll
        for (int q = 0; q < 2; q++) {
            int c = tid + q * 256;
            int row = c >> 2, kc = (c & 3) * 8;
            int gr = by * 128 + row;
            uint32_t sa = smem_u32(&As[row * SKA2 + kc]);
            const __half* g = A + (long long)gr * ldA + koff + kk + kc;
            cp16(sa, g, gr < M ? 16 : 0);
        }
        #pragma unroll
        for (int q = 0; q < 2; q++) {
            int c = tid + q * 256;
            int row = c >> 4, nc = (c & 15) * 8;
            uint32_t sb = smem_u32(&Bs[row * SKB2 + nc]);
            const __half* g = B + (koff + kk + row) * (long long)Nn + (long long)bx * 128 + nc;
            cp16(sb, g, 16);
        }
        CP_COMMIT();
    };

    float acc[4][4][4];
    #pragma unroll
    for (int i = 0; i < 4; i++)
        #pragma unroll
        for (int j = 0; j < 4; j++)
            #pragma unroll
            for (int t = 0; t < 4; t++) acc[i][j][t] = 0.0f;

    const int a_r = lane & 15, a_s = lane >> 4;
    const int b_k = lane & 7,  b_s = lane >> 3;

    auto compute = [&](int stg) {
        const uint32_t aB = smem_u32(AsBase + stg * A_STG);
        const uint32_t bB = smem_u32(BsBase + stg * B_STG);
        #pragma unroll
        for (int ks = 0; ks < 32; ks += 16) {
            uint32_t af[4][4], bf[4][2];
            #pragma unroll
            for (int mt = 0; mt < 4; mt++) {
                uint32_t addr = aB + (uint32_t)(((wm + mt * 16 + a_r) * SKA2 + ks + a_s * 8) * 2);
                LDMATRIX_X4(af[mt][0], af[mt][1], af[mt][2], af[mt][3], addr);
            }
            #pragma unroll
            for (int np = 0; np < 2; np++) {
                uint32_t addr = bB + (uint32_t)(((ks + (b_s & 1) * 8 + b_k) * SKB2 + wn + np * 16 + (b_s >> 1) * 8) * 2);
                uint32_t r0, r1, r2, r3;
                LDMATRIX_X4_T(r0, r1, r2, r3, addr);
                bf[2*np][0] = r0; bf[2*np][1] = r1;
                bf[2*np+1][0] = r2; bf[2*np+1][1] = r3;
            }
            #pragma unroll
            for (int mt = 0; mt < 4; mt++)
                #pragma unroll
                for (int nt = 0; nt < 4; nt++)
                    HMMA16816(acc[mt][nt], af[mt][0], af[mt][1], af[mt][2], af[mt][3], bf[nt][0], bf[nt][1]);
        }
    };

    const int nIter = K / 32;
    issueT(0, 0);
    issueT(32, 1);
    int stg = 0;
    for (int it = 0; it < nIter; it++) {
        if (it < nIter - 1) {
            asm volatile("cp.async.wait_group 1;");
        } else {
            asm volatile("cp.async.wait_group 0;");
        }
        __syncthreads();
        compute(stg);
        if (it + 2 < nIter) {
            int ns = stg + 2; if (ns >= 3) ns -= 3;
            issueT((it + 2) * 32, ns);
        }
        if (++stg == 3) stg = 0;
    }

    if (SPLIT) {
        float* Cz = (float*)Cv + (long long)bz * M * Nn;
        #pragma unroll
        for (int mt = 0; mt < 4; mt++) {
            int r0 = by * 128 + wm + mt * 16 + lr;
            int r1 = r0 + 8;
            #pragma unroll
            for (int nt = 0; nt < 4; nt++) {
                int col = bx * 128 + wn + nt * 8 + 2 * lc;
                if (r0 < M) *(float2*)&Cz[(long long)r0 * Nn + col] = make_float2(acc[mt][nt][0], acc[mt][nt][1]);
                if (r1 < M) *(float2*)&Cz[(long long)r1 * Nn + col] = make_float2(acc[mt][nt][2], acc[mt][nt][3]);
            }
        }
        return;
    }

    const float bninv = rsqrtf(1.0f + 1e-5f);
    #pragma unroll
    for (int mt = 0; mt < 4; mt++) {
        int r0 = by * 128 + wm + mt * 16 + lr;
        int r1 = r0 + 8;
        #pragma unroll
        for (int nt = 0; nt < 4; nt++) {
            int col = bx * 128 + wn + nt * 8 + 2 * lc;
            float b0 = __ldg(bias + col);
            float b1 = __ldg(bias + col + 1);
            float g0 = 1.f, g1 = 1.f, be0 = 0.f, be1 = 0.f;
            if (EPI == 2) {
                g0 = __ldg(bng + col) * bninv;  g1 = __ldg(bng + col + 1) * bninv;
                be0 = __ldg(bnb + col);         be1 = __ldg(bnb + col + 1);
            }
            float v00 = acc[mt][nt][0] + b0, v01 = acc[mt][nt][1] + b1;
            float v10 = acc[mt][nt][2] + b0, v11 = acc[mt][nt][3] + b1;
            if (EPI == 2) {
                v00 = v00 * g0 + be0; v01 = v01 * g1 + be1;
                v10 = v10 * g0 + be0; v11 = v11 * g1 + be1;
            }
            if (EPI >= 1) {
                v00 = fmaxf(v00, 0.f); v01 = fmaxf(v01, 0.f);
                v10 = fmaxf(v10, 0.f); v11 = fmaxf(v11, 0.f);
            }
            if (CH) {
                __half* Ch = (__half*)Cv;
                if (r0 < M) *(__half2*)&Ch[(long long)r0 * Nn + col] = __floats2half2_rn(v00, v01);
                if (r1 < M) *(__half2*)&Ch[(long long)r1 * Nn + col] = __floats2half2_rn(v10, v11);
            } else {
                float* Cf = (float*)Cv;
                if (r0 < M) *(float2*)&Cf[(long long)r0 * Nn + col] = make_float2(v00, v01);
                if (r1 < M) *(float2*)&Cf[(long long)r1 * Nn + col] = make_float2(v10, v11);
            }
        }
    }
}

// ---------------------------------------------------------------------------
// FUSED conv MLP: C = relu(bn(relu(A@W1 + b1) @ W2 + b2))  (Nmid = Nout = 128)
// Phase 1 -> h1 in smem (stride SKB2); phase 2 stages W2 in reused B buffers.
// ---------------------------------------------------------------------------
template<int K1>
__global__ __launch_bounds__(256, 2) void hgemm_fused_kernel(
    int M,
    const __half* __restrict__ A, const __half* __restrict__ W1,
    const float* __restrict__ b1,
    const __half* __restrict__ W2, const float* __restrict__ b2,
    const float* __restrict__ bng, const float* __restrict__ bnb,
    __half* __restrict__ C)
{
    extern __shared__ __half dsm[];
    __half* AsBase = dsm;
    __half* BsBase = dsm + 3 * A_STG;
    __half* H1     = dsm + 3 * A_STG + 3 * B_STG;

    const int tid = threadIdx.x, by = blockIdx.y;
    const int warp = tid >> 5, lane = tid & 31;
    const int wm = (warp >> 2) * 64;
    const int wn = (warp & 3) * 32;
    const int lr = lane >> 2;
    const int lc = lane & 3;
    const int a_r = lane & 15, a_s = lane >> 4;
    const int b_k = lane & 7,  b_s = lane >> 3;

    // ---- staging lambdas ----
    auto issueA = [&](int kk, int stg, int ld) {
        __half* As = AsBase + stg * A_STG;
        #pragma unroll
        for (int q = 0; q < 2; q++) {
            int c = tid + q * 256;
            int row = c >> 2, kc = (c & 3) * 8;
            int gr = by * 128 + row;
            uint32_t sa = smem_u32(&As[row * SKA2 + kc]);
            cp16(sa, A + (long long)gr * ld + kk + kc, gr < M ? 16 : 0);
        }
    };
    auto issueB = [&](const __half* B, int kk, int stg) {
        __half* Bs = BsBase + stg * B_STG;
        #pragma unroll
        for (int q = 0; q < 2; q++) {
            int c = tid + q * 256;
            int row = c >> 4, nc = (c & 15) * 8;
            uint32_t sb = smem_u32(&Bs[row * SKB2 + nc]);
            cp16(sb, B + (long long)(kk + row) * 128 + nc, 16);
        }
    };

    float acc[4][4][4];
    #pragma unroll
    for (int i = 0; i < 4; i++)
        #pragma unroll
        for (int j = 0; j < 4; j++)
            #pragma unroll
            for (int t = 0; t < 4; t++) acc[i][j][t] = 0.0f;

    auto computeAB = [&](uint32_t aB, int aStride, uint32_t bB) {
        #pragma unroll
        for (int ks = 0; ks < 32; ks += 16) {
            uint32_t af[4][4], bf[4][2];
            #pragma unroll
            for (int mt = 0; mt < 4; mt++) {
                uint32_t addr = aB + (uint32_t)(((wm + mt * 16 + a_r) * aStride + ks + a_s * 8) * 2);
                LDMATRIX_X4(af[mt][0], af[mt][1], af[mt][2], af[mt][3], addr);
            }
            #pragma unroll
            for (int np = 0; np < 2; np++) {
                uint32_t addr = bB + (uint32_t)(((ks + (b_s & 1) * 8 + b_k) * SKB2 + wn + np * 16 + (b_s >> 1) * 8) * 2);
                uint32_t r0, r1, r2, r3;
                LDMATRIX_X4_T(r0, r1, r2, r3, addr);
                bf[2*np][0] = r0; bf[2*np][1] = r1;
                bf[2*np+1][0] = r2; bf[2*np+1][1] = r3;
            }
            #pragma unroll
            for (int mt = 0; mt < 4; mt++)
                #pragma unroll
                for (int nt = 0; nt < 4; nt++)
                    HMMA16816(acc[mt][nt], af[mt][0], af[mt][1], af[mt][2], af[mt][3], bf[nt][0], bf[nt][1]);
        }
    };

    // ======== phase 1: acc = A @ W1 ========
    {
        const int nIter = K1 / 32;
        issueA(0, 0, K1); issueB(W1, 0, 0); CP_COMMIT();
        issueA(32, 1, K1); issueB(W1, 32, 1); CP_COMMIT();
        int stg = 0;
        for (int it = 0; it < nIter; it++) {
            if (it < nIter - 1) asm volatile("cp.async.wait_group 1;");
            else                asm volatile("cp.async.wait_group 0;");
            __syncthreads();
            computeAB(smem_u32(AsBase + stg * A_STG), SKA2, smem_u32(BsBase + stg * B_STG));
            if (it + 2 < nIter) {
                int ns = stg + 2; if (ns >= 3) ns -= 3;
                issueA((it + 2) * 32, ns, K1); issueB(W1, (it + 2) * 32, ns); CP_COMMIT();
            }
            if (++stg == 3) stg = 0;
        }
    }
    __syncthreads();   // all warps done reading stage buffers

    // ---- epilogue 1: h1 = relu(acc + b1) -> smem fp16 ----
    #pragma unroll
    for (int mt = 0; mt < 4; mt++) {
        int r0 = wm + mt * 16 + lr;
        int r1 = r0 + 8;
        #pragma unroll
        for (int nt = 0; nt < 4; nt++) {
            int col = wn + nt * 8 + 2 * lc;
            float bb0 = __ldg(b1 + col);
            float bb1 = __ldg(b1 + col + 1);
            float v00 = fmaxf(acc[mt][nt][0] + bb0, 0.f);
            float v01 = fmaxf(acc[mt][nt][1] + bb1, 0.f);
            float v10 = fmaxf(acc[mt][nt][2] + bb0, 0.f);
            float v11 = fmaxf(acc[mt][nt][3] + bb1, 0.f);
            *(__half2*)&H1[r0 * SKB2 + col] = __floats2half2_rn(v00, v01);
            *(__half2*)&H1[r1 * SKB2 + col] = __floats2half2_rn(v10, v11);
            acc[mt][nt][0] = 0.f; acc[mt][nt][1] = 0.f;
            acc[mt][nt][2] = 0.f; acc[mt][nt][3] = 0.f;
        }
    }
    __syncthreads();   // h1 visible to all warps

    // ======== phase 2: acc = h1 @ W2 (K = 128) ========
    {
        issueB(W2, 0, 0); CP_COMMIT();
        issueB(W2, 32, 1); CP_COMMIT();
        const uint32_t h1B = smem_u32(H1);
        int stg = 0;
        for (int it = 0; it < 4; it++) {
            if (it < 3) asm volatile("cp.async.wait_group 1;");
            else        asm volatile("cp.async.wait_group 0;");
            __syncthreads();
            // A fragments come from H1 at k-offset it*32
            {
                const uint32_t aB = h1B + (uint32_t)(it * 32 * 2);
                computeAB(aB, SKB2, smem_u32(BsBase + stg * B_STG));
            }
            if (it + 2 < 4) {
                int ns = stg + 2; if (ns >= 3) ns -= 3;
                issueB(W2, (it + 2) * 32, ns); CP_COMMIT();
            }
            if (++stg == 3) stg = 0;
        }
    }

    // ---- epilogue 2: C = relu(bn(acc + b2)) fp16 ----
    const float bninv = rsqrtf(1.0f + 1e-5f);
    #pragma unroll
    for (int mt = 0; mt < 4; mt++) {
        int r0 = by * 128 + wm + mt * 16 + lr;
        int r1 = r0 + 8;
        #pragma unroll
        for (int nt = 0; nt < 4; nt++) {
            int col = wn + nt * 8 + 2 * lc;
            float bb0 = __ldg(b2 + col), bb1 = __ldg(b2 + col + 1);
            float g0 = __ldg(bng + col) * bninv, g1 = __ldg(bng + col + 1) * bninv;
            float be0 = __ldg(bnb + col), be1 = __ldg(bnb + col + 1);
            float v00 = fmaxf((acc[mt][nt][0] + bb0) * g0 + be0, 0.f);
            float v01 = fmaxf((acc[mt][nt][1] + bb1) * g1 + be1, 0.f);
            float v10 = fmaxf((acc[mt][nt][2] + bb0) * g0 + be0, 0.f);
            float v11 = fmaxf((acc[mt][nt][3] + bb1) * g1 + be1, 0.f);
            if (r0 < M) *(__half2*)&C[(long long)r0 * 128 + col] = __floats2half2_rn(v00, v01);
            if (r1 < M) *(__half2*)&C[(long long)r1 * 128 + col] = __floats2half2_rn(v10, v11);
        }
    }
}

// ---------------------------------------------------------------------------
extern "C" void kernel_launch(void* const* d_in, const int* in_sizes, int n_in,
                              void* d_out, int out_size) {
    const float* x     = (const float*)d_in[0];
    const int*   ei    = (const int*)  d_in[1];
    const int*   src   = ei;
    const int*   dst   = ei + NEDGES;
    const int*   batch = (const int*)  d_in[2];
    const float* fp    = (const float*)d_in[3];
    const float* c1w1 = (const float*)d_in[4],  *c1b1 = (const float*)d_in[5];
    const float* c1w2 = (const float*)d_in[6],  *c1b2 = (const float*)d_in[7];
    const float* c2w1 = (const float*)d_in[8],  *c2b1 = (const float*)d_in[9];
    const float* c2w2 = (const float*)d_in[10], *c2b2 = (const float*)d_in[11];
    const float* c3w1 = (const float*)d_in[12], *c3b1 = (const float*)d_in[13];
    const float* c3w2 = (const float*)d_in[14], *c3b2 = (const float*)d_in[15];
    const float* bn1g = (const float*)d_in[16], *bn1b = (const float*)d_in[17];
    const float* bn2g = (const float*)d_in[18], *bn2b = (const float*)d_in[19];
    const float* bn3g = (const float*)d_in[20], *bn3b = (const float*)d_in[21];
    const float* o1w  = (const float*)d_in[22], *o1b  = (const float*)d_in[23];
    const float* obng = (const float*)d_in[24], *obnb = (const float*)d_in[25];
    const float* o3w  = (const float*)d_in[26], *o3b  = (const float*)d_in[27];
    float* out = (float*)d_out;

    __half *xh, *aggrh, *tmph, *hh, *wh, *poolh;
    float *scr;
    int *deg, *cursor, *rowptr, *srclist, *gstart;
    cudaGetSymbolAddress((void**)&xh,      g_xh);
    cudaGetSymbolAddress((void**)&aggrh,   g_aggrh);
    cudaGetSymbolAddress((void**)&tmph,    g_tmph);
    cudaGetSymbolAddress((void**)&hh,      g_hh);
    cudaGetSymbolAddress((void**)&wh,      g_wh);
    cudaGetSymbolAddress((void**)&poolh,   g_poolh);
    cudaGetSymbolAddress((void**)&scr,     g_scr);
    cudaGetSymbolAddress((void**)&deg,     g_deg);
    cudaGetSymbolAddress((void**)&cursor,  g_cursor);
    cudaGetSymbolAddress((void**)&rowptr,  g_rowptr);
    cudaGetSymbolAddress((void**)&srclist, g_srclist);
    cudaGetSymbolAddress((void**)&gstart,  g_gstart);

    cudaFuncSetAttribute(hgemm16_kernel<1,0,true>,  cudaFuncAttributeMaxDynamicSharedMemorySize, HG_SMEM);
    cudaFuncSetAttribute(hgemm16_kernel<2,0,true>,  cudaFuncAttributeMaxDynamicSharedMemorySize, HG_SMEM);
    cudaFuncSetAttribute(hgemm16_kernel<0,1,false>, cudaFuncAttributeMaxDynamicSharedMemorySize, HG_SMEM);
    cudaFuncSetAttribute(hgemm_fused_kernel<64>,  cudaFuncAttributeMaxDynamicSharedMemorySize, FU_SMEM);
    cudaFuncSetAttribute(hgemm_fused_kernel<128>, cudaFuncAttributeMaxDynamicSharedMemorySize, FU_SMEM);

    const int T = 256;
    const int gy = (NNODES + 127) / 128;

    // ---- fork/join infrastructure ----
    cudaStream_t sB, sC, sP;
    cudaStreamCreateWithFlags(&sB, cudaStreamNonBlocking);
    cudaStreamCreateWithFlags(&sC, cudaStreamNonBlocking);
    cudaStreamCreateWithFlags(&sP, cudaStreamNonBlocking);
    cudaEvent_t evRoot, evB, evC, evH[3], evP[3];
    cudaEventCreateWithFlags(&evRoot, cudaEventDisableTiming);
    cudaEventCreateWithFlags(&evB,    cudaEventDisableTiming);
    cudaEventCreateWithFlags(&evC,    cudaEventDisableTiming);
    for (int i = 0; i < 3; i++) {
        cudaEventCreateWithFlags(&evH[i], cudaEventDisableTiming);
        cudaEventCreateWithFlags(&evP[i], cudaEventDisableTiming);
    }

    cudaEventRecord(evRoot, 0);
    cudaStreamWaitEvent(sB, evRoot, 0);
    cudaStreamWaitEvent(sC, evRoot, 0);

    // ---- sB: big readout-weight converts ----
    {
        WConvArgs wb = {};
        wb.seg[0] = { (const float2*)o3w, (__half2*)(wh + W_O3W), 212992 };
        wb.seg[1] = { (const float2*)o1w, (__half2*)(wh + W_O1W), 11075584 };
        wb.total = 212992 + 11075584;
        wconv_kernel<<<2048, T, 0, sB>>>(wb);
        cudaEventRecord(evB, sB);
    }
    // ---- sC: x convert + fingerprint + conv weights ----
    {
        f2h_kernel<<<(NNODES * 32 + T - 1) / T, T, 0, sC>>>((const float2*)x, (__half2*)xh, NNODES * 32);
        fp_copy_kernel<<<dim3((1536 + T - 1) / T, NGRAPH), T, 0, sC>>>((const float4*)fp, (uint2*)poolh);
        WConvArgs wc = {};
        wc.seg[0] = { (const float2*)c1w1, (__half2*)(wh + W_C1W1), 4096 };
        wc.seg[1] = { (const float2*)c1w2, (__half2*)(wh + W_C1W2), 8192 };
        wc.seg[2] = { (const float2*)c2w1, (__half2*)(wh + W_C2W1), 8192 };
        wc.seg[3] = { (const float2*)c2w2, (__half2*)(wh + W_C2W2), 8192 };
        wc.seg[4] = { (const float2*)c3w1, (__half2*)(wh + W_C3W1), 16384 };
        wc.seg[5] = { (const float2*)c3w2, (__half2*)(wh + W_C3W2), 32768 };
        wc.total = 4096 + 8192 + 8192 + 8192 + 16384 + 32768;
        wconv_kernel<<<256, T, 0, sC>>>(wc);
        cudaEventRecord(evC, sC);
    }
    // ---- main: CSR build ----
    zero_deg_kernel<<<(NNODES + T - 1) / T, T>>>(deg);
    hist_kernel<<<(NEDGES + T - 1) / T, T>>>(dst, deg);
    scan_kernel<<<1, 1024>>>(deg, rowptr, cursor);
    fill_kernel<<<(NEDGES + T - 1) / T, T>>>(src, dst, cursor, srclist);
    gstart_kernel<<<3, 256>>>(batch, gstart);
    cudaStreamWaitEvent(0, evC, 0);

    // ---- conv1 (64 -> 128 -> 128), fused MLP ----
    gather_aggr_h_kernel<64><<<(NNODES * 16 + T - 1) / T, T>>>((const uint2*)xh, rowptr, srclist, (uint2*)aggrh);
    hgemm_fused_kernel<64><<<dim3(1, gy), T, FU_SMEM>>>(NNODES, aggrh, wh + W_C1W1, c1b1, wh + W_C1W2, c1b2, bn1g, bn1b, hh);
    cudaEventRecord(evH[0], 0);
    cudaStreamWaitEvent(sP, evH[0], 0);
    seg_pool_h_kernel<<<NGRAPH, 64, 0, sP>>>((const __half2*)hh, gstart, (__half2*)poolh, 64, 0);
    cudaEventRecord(evP[0], sP);

    // ---- conv2 (128 -> 128 -> 128), fused MLP ----
    gather_aggr_h_kernel<128><<<(NNODES * 32 + T - 1) / T, T>>>((const uint2*)hh, rowptr, srclist, (uint2*)aggrh);
    cudaStreamWaitEvent(0, evP[0], 0);   // pool1 before hh overwrite
    hgemm_fused_kernel<128><<<dim3(1, gy), T, FU_SMEM>>>(NNODES, aggrh, wh + W_C2W1, c2b1, wh + W_C2W2, c2b2, bn2g, bn2b, hh);
    cudaEventRecord(evH[1], 0);
    cudaStreamWaitEvent(sP, evH[1], 0);
    seg_pool_h_kernel<<<NGRAPH, 64, 0, sP>>>((const __half2*)hh, gstart, (__half2*)poolh, 64, 64);
    cudaEventRecord(evP[1], sP);

    // ---- conv3 (128 -> 256 -> 256), unfused ----
    gather_aggr_h_kernel<128><<<(NNODES * 32 + T - 1) / T, T>>>((const uint2*)hh, rowptr, srclist, (uint2*)aggrh);
    hgemm16_kernel<1,0,true><<<dim3(2, gy), T, HG_SMEM>>>(NNODES, 256, 128, 128, aggrh, wh + W_C3W1, c3b1, nullptr, nullptr, tmph);
    cudaStreamWaitEvent(0, evP[1], 0);   // pool2 before hh overwrite
    hgemm16_kernel<2,0,true><<<dim3(2, gy), T, HG_SMEM>>>(NNODES, 256, 256, 256, tmph, wh + W_C3W2, c3b2, bn3g, bn3b, hh);
    cudaEventRecord(evH[2], 0);
    cudaStreamWaitEvent(sP, evH[2], 0);
    seg_pool_h_kernel<<<NGRAPH, 128, 0, sP>>>((const __half2*)hh, gstart, (__half2*)poolh, 128, 128);
    cudaEventRecord(evP[2], sP);

    // ---- join before readout ----
    cudaStreamWaitEvent(0, evP[2], 0);
    cudaStreamWaitEvent(0, evB, 0);

    // ---- readout GEMM1: split-K=4 ----
    hgemm16_kernel<0,1,false><<<dim3(3328 / 128, 4, 4), T, HG_SMEM>>>(NGRAPH, 3328, 1664, RDIM, poolh, wh + W_O1W, nullptr, nullptr, nullptr, scr);
    readout_reduce_kernel<<<(NGRAPH * 832 + T - 1) / T, T>>>((const float4*)scr, o1b, obng, obnb, (uint2*)tmph);

    // ---- readout GEMM2: split-K=8 ----
    float* scr2 = scr + 4 * NGRAPH * 3328;
    hgemm16_kernel<0,1,false><<<dim3(1, 4, 8), T, HG_SMEM>>>(NGRAPH, 128, 416, 3328, tmph, wh + W_O3W, nullptr, nullptr, nullptr, scr2);
    final_reduce_kernel<<<(NGRAPH * 128 + T - 1) / T, T>>>(scr2, o3b, out);

    // ---- cleanup ----
    cudaEventDestroy(evRoot); cudaEventDestroy(evB); cudaEventDestroy(evC);
    for (int i = 0; i < 3; i++) { cudaEventDestroy(evH[i]); cudaEventDestroy(evP[i]); }
    cudaStreamDestroy(sB); cudaStreamDestroy(sC); cudaStreamDestroy(sP);
}

// round 13
// speedup vs baseline: 5.6719x; 1.0100x over previous
#include <cuda_runtime.h>
#include <cuda_fp16.h>
#include <cstdint>

#define NNODES 100000
#define NEDGES 1600000
#define NGRAPH 512
#define RDIM   6656

// fp16 weight buffer offsets (halves)
#define W_C1W1 0
#define W_C1W2 8192
#define W_C2W1 24576
#define W_C2W2 40960
#define W_C3W1 57344
#define W_C3W2 90112
#define W_O1W  155648
#define W_O3W  22306816
#define W_TOTAL 22732800

// ---- static device scratch (no allocations allowed) ----
static __device__ __align__(16) __half g_xh   [NNODES * 64];
static __device__ __align__(16) __half g_aggrh[NNODES * 256];
static __device__ __align__(16) __half g_tmph [NNODES * 256];
static __device__ __align__(16) __half g_hh   [NNODES * 256];
static __device__ __align__(16) __half g_wh   [W_TOTAL];
static __device__ __align__(16) __half g_poolh[NGRAPH * RDIM];
static __device__ __align__(16) float  g_scr  [8 * 1024 * 1024];
static __device__ int g_deg[NNODES];
static __device__ int g_cursor[NNODES];
static __device__ int g_rowptr[NNODES + 1];
static __device__ int g_srclist[NEDGES];
static __device__ int g_gstart[NGRAPH + 1];

// ---------------------------------------------------------------------------
// CSR build
// ---------------------------------------------------------------------------
__global__ void hist_kernel(const int* __restrict__ edst, int* __restrict__ deg) {
    int e = blockIdx.x * blockDim.x + threadIdx.x;
    if (e < NEDGES) atomicAdd(&deg[__ldg(edst + e)], 1);
}
__global__ __launch_bounds__(1024) void scan_kernel(const int* __restrict__ deg,
                                                    int* __restrict__ rowptr,
                                                    int* __restrict__ cursor) {
    __shared__ int sums[1024];
    const int t = threadIdx.x;
    const int chunk = (NNODES + 1023) / 1024;
    const int beg = t * chunk;
    const int end = min(beg + chunk, NNODES);
    int s = 0;
    for (int k = beg; k < end; k++) s += deg[k];
    sums[t] = s;
    __syncthreads();
    for (int off = 1; off < 1024; off <<= 1) {
        int v = (t >= off) ? sums[t - off] : 0;
        __syncthreads();
        sums[t] += v;
        __syncthreads();
    }
    int run = sums[t] - s;
    for (int k = beg; k < end; k++) {
        rowptr[k] = run;
        cursor[k] = run;
        run += deg[k];
    }
    if (t == 1023) rowptr[NNODES] = sums[1023];
}
// 4 edges per thread: independent atomic chains -> MLP 4
__global__ void fill_kernel(const int* __restrict__ esrc, const int* __restrict__ edst,
                            int* __restrict__ cursor, int* __restrict__ srclist) {
    int base = (blockIdx.x * blockDim.x + threadIdx.x) * 4;
    #pragma unroll
    for (int q = 0; q < 4; q++) {
        int e = base + q;
        if (e < NEDGES) {
            int d = __ldg(edst + e);
            int pos = atomicAdd(&cursor[d], 1);
            srclist[pos] = __ldg(esrc + e);
        }
    }
}
__global__ void gstart_kernel(const int* __restrict__ batch, int* __restrict__ gstart) {
    int g = blockIdx.x * blockDim.x + threadIdx.x;
    if (g > NGRAPH) return;
    if (g == NGRAPH) { gstart[NGRAPH] = NNODES; return; }
    int lo = 0, hi = NNODES;
    while (lo < hi) {
        int mid = (lo + hi) >> 1;
        if (__ldg(batch + mid) < g) lo = mid + 1; else hi = mid;
    }
    gstart[g] = lo;
}

// ---------------------------------------------------------------------------
// converts
// ---------------------------------------------------------------------------
__global__ void f2h_kernel(const float2* __restrict__ in, __half2* __restrict__ out, int n2) {
    int i = blockIdx.x * blockDim.x + threadIdx.x;
    if (i < n2) {
        float2 v = __ldg(in + i);
        out[i] = __floats2half2_rn(v.x, v.y);
    }
}

struct WSeg { const float2* src; __half2* dst; int n; };
struct WConvArgs { WSeg seg[8]; int total; };
__global__ void wconv_kernel(WConvArgs a) {
    int stride = gridDim.x * blockDim.x;
    for (int idx = blockIdx.x * blockDim.x + threadIdx.x; idx < a.total; idx += stride) {
        int i = idx;
        #pragma unroll
        for (int s = 0; s < 8; s++) {
            if (i < a.seg[s].n) {
                float2 v = __ldg(a.seg[s].src + i);
                a.seg[s].dst[i] = __floats2half2_rn(v.x, v.y);
                break;
            }
            i -= a.seg[s].n;
        }
    }
}

// ---------------------------------------------------------------------------
// fp16 gather, uint4 (16B) lane loads, neighbor loop unrolled x4
// ---------------------------------------------------------------------------
__device__ __forceinline__ float2 h2f2(uint32_t h) {
    return __half22float2(*(__half2*)&h);
}
__device__ __forceinline__ void acc4(float2* a, const uint4& t) {
    float2 v0 = h2f2(t.x), v1 = h2f2(t.y), v2 = h2f2(t.z), v3 = h2f2(t.w);
    a[0].x += v0.x; a[0].y += v0.y;
    a[1].x += v1.x; a[1].y += v1.y;
    a[2].x += v2.x; a[2].y += v2.y;
    a[3].x += v3.x; a[3].y += v3.y;
}
template<int FH>
__global__ void gather_aggr_h_kernel(const uint4* __restrict__ feat,
                                     const int* __restrict__ rowptr,
                                     const int* __restrict__ srclist,
                                     uint4* __restrict__ aggr) {
    constexpr int L = FH / 8;          // uint4 lanes per node (8 halves each)
    constexpr int NPB = 256 / L;
    int i = blockIdx.x * NPB + threadIdx.x / L;
    if (i >= NNODES) return;
    int c = threadIdx.x % L;

    float2 a[4];
    {
        uint4 v0 = __ldg(&feat[i * L + c]);
        a[0] = h2f2(v0.x); a[1] = h2f2(v0.y); a[2] = h2f2(v0.z); a[3] = h2f2(v0.w);
    }

    int j = __ldg(rowptr + i);
    const int end = __ldg(rowptr + i + 1);
    for (; j + 3 < end; j += 4) {
        int s0 = __ldg(srclist + j);
        int s1 = __ldg(srclist + j + 1);
        int s2 = __ldg(srclist + j + 2);
        int s3 = __ldg(srclist + j + 3);
        uint4 t0 = __ldg(&feat[s0 * L + c]);
        uint4 t1 = __ldg(&feat[s1 * L + c]);
        uint4 t2 = __ldg(&feat[s2 * L + c]);
        uint4 t3 = __ldg(&feat[s3 * L + c]);
        acc4(a, t0); acc4(a, t1); acc4(a, t2); acc4(a, t3);
    }
    for (; j < end; j++) {
        int s0 = __ldg(srclist + j);
        uint4 t0 = __ldg(&feat[s0 * L + c]);
        acc4(a, t0);
    }
    __half2 r0 = __floats2half2_rn(a[0].x, a[0].y);
    __half2 r1 = __floats2half2_rn(a[1].x, a[1].y);
    __half2 r2 = __floats2half2_rn(a[2].x, a[2].y);
    __half2 r3 = __floats2half2_rn(a[3].x, a[3].y);
    uint4 o;
    o.x = *(uint32_t*)&r0; o.y = *(uint32_t*)&r1;
    o.z = *(uint32_t*)&r2; o.w = *(uint32_t*)&r3;
    aggr[i * L + c] = o;
}

// ---------------------------------------------------------------------------
// segment pool -> fp16 pool
// ---------------------------------------------------------------------------
__global__ void seg_pool_h_kernel(const __half2* __restrict__ feat,
                                  const int* __restrict__ gstart,
                                  __half2* __restrict__ pool,
                                  int F2, int off2) {
    int g = blockIdx.x;
    int t = threadIdx.x;
    int beg = __ldg(gstart + g), end = __ldg(gstart + g + 1);
    float2 a0 = make_float2(0.f, 0.f), a1 = make_float2(0.f, 0.f);
    int r = beg;
    for (; r + 1 < end; r += 2) {
        float2 v0 = __half22float2(__ldg(feat + (long long)r * F2 + t));
        float2 v1 = __half22float2(__ldg(feat + (long long)(r + 1) * F2 + t));
        a0.x += v0.x; a0.y += v0.y; a1.x += v1.x; a1.y += v1.y;
    }
    if (r < end) {
        float2 v0 = __half22float2(__ldg(feat + (long long)r * F2 + t));
        a0.x += v0.x; a0.y += v0.y;
    }
    pool[(long long)g * (RDIM / 2) + off2 + t] = __floats2half2_rn(a0.x + a1.x, a0.y + a1.y);
}

__global__ void fp_copy_kernel(const float4* __restrict__ fp, uint2* __restrict__ pool) {
    int col = blockIdx.x * blockDim.x + threadIdx.x;
    int row = blockIdx.y;
    if (col >= 1536) return;
    float4 v = __ldg(fp + row * 1536 + col);
    __half2 h0 = __floats2half2_rn(v.x, v.y);
    __half2 h1 = __floats2half2_rn(v.z, v.w);
    uint2 o;
    o.x = *(uint32_t*)&h0; o.y = *(uint32_t*)&h1;
    pool[row * (RDIM / 4) + 128 + col] = o;
}

// ---------------------------------------------------------------------------
// split-K reductions (fixed order)
// ---------------------------------------------------------------------------
__global__ void readout_reduce_kernel(const float4* __restrict__ part,
                                      const float* __restrict__ bias,
                                      const float* __restrict__ bng,
                                      const float* __restrict__ bnb,
                                      uint2* __restrict__ outh) {
    const int N4 = 3328 / 4;
    int idx = blockIdx.x * blockDim.x + threadIdx.x;
    if (idx >= NGRAPH * N4) return;
    const long long SZ4 = (long long)NGRAPH * N4;
    int col = (idx % N4) * 4;
    float4 s = part[idx];
    #pragma unroll
    for (int z = 1; z < 4; z++) {
        float4 t = part[idx + z * SZ4];
        s.x += t.x; s.y += t.y; s.z += t.z; s.w += t.w;
    }
    const float bninv = rsqrtf(1.0f + 1e-5f);
    float* sp = &s.x;
    #pragma unroll
    for (int c = 0; c < 4; c++) {
        float v = (sp[c] + __ldg(bias + col + c)) * (__ldg(bng + col + c) * bninv) + __ldg(bnb + col + c);
        sp[c] = fmaxf(v, 0.0f);
    }
    __half2 h0 = __floats2half2_rn(s.x, s.y);
    __half2 h1 = __floats2half2_rn(s.z, s.w);
    uint2 o;
    o.x = *(uint32_t*)&h0; o.y = *(uint32_t*)&h1;
    outh[idx] = o;
}
__global__ void final_reduce_kernel(const float* __restrict__ part,
                                    const float* __restrict__ bias,
                                    float* __restrict__ out) {
    int idx = blockIdx.x * blockDim.x + threadIdx.x;
    if (idx >= NGRAPH * 128) return;
    float s = 0.0f;
    #pragma unroll
    for (int z = 0; z < 8; z++) s += part[idx + z * NGRAPH * 128];
    out[idx] = s + __ldg(bias + (idx & 127));
}

// ---------------------------------------------------------------------------
// shared GEMM machinery
// ---------------------------------------------------------------------------
#define SKA2 40
#define SKB2 136
#define A_STG (128 * SKA2)
#define B_STG (32 * SKB2)
#define HG_SMEM (3 * (A_STG + B_STG) * 2)
#define H1_STG (128 * SKB2)
#define FU_SMEM ((3 * (A_STG + B_STG) + H1_STG) * 2)

__device__ __forceinline__ uint32_t smem_u32(const void* p) {
    uint32_t a;
    asm("{ .reg .u64 t; cvta.to.shared.u64 t, %1; cvt.u32.u64 %0, t; }" : "=r"(a) : "l"(p));
    return a;
}
__device__ __forceinline__ void cp16(uint32_t s, const void* g, int sz) {
    asm volatile("cp.async.cg.shared.global [%0], [%1], 16, %2;" :: "r"(s), "l"(g), "r"(sz));
}
#define CP_COMMIT() asm volatile("cp.async.commit_group;")
#define LDMATRIX_X4(r0, r1, r2, r3, addr) \
    asm volatile("ldmatrix.sync.aligned.m8n8.x4.shared.b16 {%0,%1,%2,%3}, [%4];" \
        : "=r"(r0), "=r"(r1), "=r"(r2), "=r"(r3) : "r"(addr))
#define LDMATRIX_X4_T(r0, r1, r2, r3, addr) \
    asm volatile("ldmatrix.sync.aligned.m8n8.x4.trans.shared.b16 {%0,%1,%2,%3}, [%4];" \
        : "=r"(r0), "=r"(r1), "=r"(r2), "=r"(r3) : "r"(addr))
#define HMMA16816(acc, a0, a1, a2, a3, b0, b1) \
    asm volatile("mma.sync.aligned.m16n8k16.row.col.f32.f16.f16.f32 " \
        "{%0,%1,%2,%3}, {%4,%5,%6,%7}, {%8,%9}, {%0,%1,%2,%3};" \
        : "+f"((acc)[0]), "+f"((acc)[1]), "+f"((acc)[2]), "+f"((acc)[3]) \
        : "r"(a0), "r"(a1), "r"(a2), "r"(a3), "r"(b0), "r"(b1))

// ---------------------------------------------------------------------------
// unfused GEMM (conv3 + readout)
// ---------------------------------------------------------------------------
template<int EPI, int SPLIT, bool CH>
__global__ __launch_bounds__(256, 2) void hgemm16_kernel(
    int M, int Nn, int K, int ldA,
    const __half* __restrict__ A, const __half* __restrict__ B,
    const float* __restrict__ bias,
    const float* __restrict__ bng, const float* __restrict__ bnb,
    void* __restrict__ Cv)
{
    extern __shared__ __half dsm[];
    __half* AsBase = dsm;
    __half* BsBase = dsm + 3 * A_STG;

    const int tid = threadIdx.x, bx = blockIdx.x, by = blockIdx.y, bz = blockIdx.z;
    const int warp = tid >> 5, lane = tid & 31;
    const int wm = (warp >> 2) * 64;
    const int wn = (warp & 3) * 32;
    const int lr = lane >> 2;
    const int lc = lane & 3;

    const long long koff = (long long)bz * K;

    auto issueT = [&](int kk, int stg) {
        __half* As = AsBase + stg * A_STG;
        __half* Bs = BsBase + stg * B_STG;
        #pragma unroll
        for (int q = 0; q < 2; q++) {
            int c = tid + q * 256;
            int row = c >> 2, kc = (c & 3) * 8;
            int gr = by * 128 + row;
            uint32_t sa = smem_u32(&As[row * SKA2 + kc]);
            const __half* g = A + (long long)gr * ldA + koff + kk + kc;
            cp16(sa, g, gr < M ? 16 : 0);
        }
        #pragma unroll
        for (int q = 0; q < 2; q++) {
            int c = tid + q * 256;
            int row = c >> 4, nc = (c & 15) * 8;
            uint32_t sb = smem_u32(&Bs[row * SKB2 + nc]);
            const __half* g = B + (koff + kk + row) * (long long)Nn + (long long)bx * 128 + nc;
            cp16(sb, g, 16);
        }
        CP_COMMIT();
    };

    float acc[4][4][4];
    #pragma unroll
    for (int i = 0; i < 4; i++)
        #pragma unroll
        for (int j = 0; j < 4; j++)
            #pragma unroll
            for (int t = 0; t < 4; t++) acc[i][j][t] = 0.0f;

    const int a_r = lane & 15, a_s = lane >> 4;
    const int b_k = lane & 7,  b_s = lane >> 3;

    auto compute = [&](int stg) {
        const uint32_t aB = smem_u32(AsBase + stg * A_STG);
        const uint32_t bB = smem_u32(BsBase + stg * B_STG);
        #pragma unroll
        for (int ks = 0; ks < 32; ks += 16) {
            uint32_t af[4][4], bf[4][2];
            #pragma unroll
            for (int mt = 0; mt < 4; mt++) {
                uint32_t addr = aB + (uint32_t)(((wm + mt * 16 + a_r) * SKA2 + ks + a_s * 8) * 2);
                LDMATRIX_X4(af[mt][0], af[mt][1], af[mt][2], af[mt][3], addr);
            }
            #pragma unroll
            for (int np = 0; np < 2; np++) {
                uint32_t addr = bB + (uint32_t)(((ks + (b_s & 1) * 8 + b_k) * SKB2 + wn + np * 16 + (b_s >> 1) * 8) * 2);
                uint32_t r0, r1, r2, r3;
                LDMATRIX_X4_T(r0, r1, r2, r3, addr);
                bf[2*np][0] = r0; bf[2*np][1] = r1;
                bf[2*np+1][0] = r2; bf[2*np+1][1] = r3;
            }
            #pragma unroll
            for (int mt = 0; mt < 4; mt++)
                #pragma unroll
                for (int nt = 0; nt < 4; nt++)
                    HMMA16816(acc[mt][nt], af[mt][0], af[mt][1], af[mt][2], af[mt][3], bf[nt][0], bf[nt][1]);
        }
    };

    const int nIter = K / 32;
    issueT(0, 0);
    issueT(32, 1);
    int stg = 0;
    for (int it = 0; it < nIter; it++) {
        if (it < nIter - 1) {
            asm volatile("cp.async.wait_group 1;");
        } else {
            asm volatile("cp.async.wait_group 0;");
        }
        __syncthreads();
        compute(stg);
        if (it + 2 < nIter) {
            int ns = stg + 2; if (ns >= 3) ns -= 3;
            issueT((it + 2) * 32, ns);
        }
        if (++stg == 3) stg = 0;
    }

    if (SPLIT) {
        float* Cz = (float*)Cv + (long long)bz * M * Nn;
        #pragma unroll
        for (int mt = 0; mt < 4; mt++) {
            int r0 = by * 128 + wm + mt * 16 + lr;
            int r1 = r0 + 8;
            #pragma unroll
            for (int nt = 0; nt < 4; nt++) {
                int col = bx * 128 + wn + nt * 8 + 2 * lc;
                if (r0 < M) *(float2*)&Cz[(long long)r0 * Nn + col] = make_float2(acc[mt][nt][0], acc[mt][nt][1]);
                if (r1 < M) *(float2*)&Cz[(long long)r1 * Nn + col] = make_float2(acc[mt][nt][2], acc[mt][nt][3]);
            }
        }
        return;
    }

    const float bninv = rsqrtf(1.0f + 1e-5f);
    #pragma unroll
    for (int mt = 0; mt < 4; mt++) {
        int r0 = by * 128 + wm + mt * 16 + lr;
        int r1 = r0 + 8;
        #pragma unroll
        for (int nt = 0; nt < 4; nt++) {
            int col = bx * 128 + wn + nt * 8 + 2 * lc;
            float b0 = __ldg(bias + col);
            float b1 = __ldg(bias + col + 1);
            float g0 = 1.f, g1 = 1.f, be0 = 0.f, be1 = 0.f;
            if (EPI == 2) {
                g0 = __ldg(bng + col) * bninv;  g1 = __ldg(bng + col + 1) * bninv;
                be0 = __ldg(bnb + col);         be1 = __ldg(bnb + col + 1);
            }
            float v00 = acc[mt][nt][0] + b0, v01 = acc[mt][nt][1] + b1;
            float v10 = acc[mt][nt][2] + b0, v11 = acc[mt][nt][3] + b1;
            if (EPI == 2) {
                v00 = v00 * g0 + be0; v01 = v01 * g1 + be1;
                v10 = v10 * g0 + be0; v11 = v11 * g1 + be1;
            }
            if (EPI >= 1) {
                v00 = fmaxf(v00, 0.f); v01 = fmaxf(v01, 0.f);
                v10 = fmaxf(v10, 0.f); v11 = fmaxf(v11, 0.f);
            }
            if (CH) {
                __half* Ch = (__half*)Cv;
                if (r0 < M) *(__half2*)&Ch[(long long)r0 * Nn + col] = __floats2half2_rn(v00, v01);
                if (r1 < M) *(__half2*)&Ch[(long long)r1 * Nn + col] = __floats2half2_rn(v10, v11);
            } else {
                float* Cf = (float*)Cv;
                if (r0 < M) *(float2*)&Cf[(long long)r0 * Nn + col] = make_float2(v00, v01);
                if (r1 < M) *(float2*)&Cf[(long long)r1 * Nn + col] = make_float2(v10, v11);
            }
        }
    }
}

// ---------------------------------------------------------------------------
// FUSED conv MLP: C = relu(bn(relu(A@W1 + b1) @ W2 + b2))  (Nmid = Nout = 128)
// ---------------------------------------------------------------------------
template<int K1>
__global__ __launch_bounds__(256, 2) void hgemm_fused_kernel(
    int M,
    const __half* __restrict__ A, const __half* __restrict__ W1,
    const float* __restrict__ b1,
    const __half* __restrict__ W2, const float* __restrict__ b2,
    const float* __restrict__ bng, const float* __restrict__ bnb,
    __half* __restrict__ C)
{
    extern __shared__ __half dsm[];
    __half* AsBase = dsm;
    __half* BsBase = dsm + 3 * A_STG;
    __half* H1     = dsm + 3 * A_STG + 3 * B_STG;

    const int tid = threadIdx.x, by = blockIdx.y;
    const int warp = tid >> 5, lane = tid & 31;
    const int wm = (warp >> 2) * 64;
    const int wn = (warp & 3) * 32;
    const int lr = lane >> 2;
    const int lc = lane & 3;
    const int a_r = lane & 15, a_s = lane >> 4;
    const int b_k = lane & 7,  b_s = lane >> 3;

    auto issueA = [&](int kk, int stg, int ld) {
        __half* As = AsBase + stg * A_STG;
        #pragma unroll
        for (int q = 0; q < 2; q++) {
            int c = tid + q * 256;
            int row = c >> 2, kc = (c & 3) * 8;
            int gr = by * 128 + row;
            uint32_t sa = smem_u32(&As[row * SKA2 + kc]);
            cp16(sa, A + (long long)gr * ld + kk + kc, gr < M ? 16 : 0);
        }
    };
    auto issueB = [&](const __half* B, int kk, int stg) {
        __half* Bs = BsBase + stg * B_STG;
        #pragma unroll
        for (int q = 0; q < 2; q++) {
            int c = tid + q * 256;
            int row = c >> 4, nc = (c & 15) * 8;
            uint32_t sb = smem_u32(&Bs[row * SKB2 + nc]);
            cp16(sb, B + (long long)(kk + row) * 128 + nc, 16);
        }
    };

    float acc[4][4][4];
    #pragma unroll
    for (int i = 0; i < 4; i++)
        #pragma unroll
        for (int j = 0; j < 4; j++)
            #pragma unroll
            for (int t = 0; t < 4; t++) acc[i][j][t] = 0.0f;

    auto computeAB = [&](uint32_t aB, int aStride, uint32_t bB) {
        #pragma unroll
        for (int ks = 0; ks < 32; ks += 16) {
            uint32_t af[4][4], bf[4][2];
            #pragma unroll
            for (int mt = 0; mt < 4; mt++) {
                uint32_t addr = aB + (uint32_t)(((wm + mt * 16 + a_r) * aStride + ks + a_s * 8) * 2);
                LDMATRIX_X4(af[mt][0], af[mt][1], af[mt][2], af[mt][3], addr);
            }
            #pragma unroll
            for (int np = 0; np < 2; np++) {
                uint32_t addr = bB + (uint32_t)(((ks + (b_s & 1) * 8 + b_k) * SKB2 + wn + np * 16 + (b_s >> 1) * 8) * 2);
                uint32_t r0, r1, r2, r3;
                LDMATRIX_X4_T(r0, r1, r2, r3, addr);
                bf[2*np][0] = r0; bf[2*np][1] = r1;
                bf[2*np+1][0] = r2; bf[2*np+1][1] = r3;
            }
            #pragma unroll
            for (int mt = 0; mt < 4; mt++)
                #pragma unroll
                for (int nt = 0; nt < 4; nt++)
                    HMMA16816(acc[mt][nt], af[mt][0], af[mt][1], af[mt][2], af[mt][3], bf[nt][0], bf[nt][1]);
        }
    };

    // ======== phase 1: acc = A @ W1 ========
    {
        const int nIter = K1 / 32;
        issueA(0, 0, K1); issueB(W1, 0, 0); CP_COMMIT();
        issueA(32, 1, K1); issueB(W1, 32, 1); CP_COMMIT();
        int stg = 0;
        for (int it = 0; it < nIter; it++) {
            if (it < nIter - 1) asm volatile("cp.async.wait_group 1;");
            else                asm volatile("cp.async.wait_group 0;");
            __syncthreads();
            computeAB(smem_u32(AsBase + stg * A_STG), SKA2, smem_u32(BsBase + stg * B_STG));
            if (it + 2 < nIter) {
                int ns = stg + 2; if (ns >= 3) ns -= 3;
                issueA((it + 2) * 32, ns, K1); issueB(W1, (it + 2) * 32, ns); CP_COMMIT();
            }
            if (++stg == 3) stg = 0;
        }
    }
    __syncthreads();

    // ---- epilogue 1: h1 = relu(acc + b1) -> smem fp16 ----
    #pragma unroll
    for (int mt = 0; mt < 4; mt++) {
        int r0 = wm + mt * 16 + lr;
        int r1 = r0 + 8;
        #pragma unroll
        for (int nt = 0; nt < 4; nt++) {
            int col = wn + nt * 8 + 2 * lc;
            float bb0 = __ldg(b1 + col);
            float bb1 = __ldg(b1 + col + 1);
            float v00 = fmaxf(acc[mt][nt][0] + bb0, 0.f);
            float v01 = fmaxf(acc[mt][nt][1] + bb1, 0.f);
            float v10 = fmaxf(acc[mt][nt][2] + bb0, 0.f);
            float v11 = fmaxf(acc[mt][nt][3] + bb1, 0.f);
            *(__half2*)&H1[r0 * SKB2 + col] = __floats2half2_rn(v00, v01);
            *(__half2*)&H1[r1 * SKB2 + col] = __floats2half2_rn(v10, v11);
            acc[mt][nt][0] = 0.f; acc[mt][nt][1] = 0.f;
            acc[mt][nt][2] = 0.f; acc[mt][nt][3] = 0.f;
        }
    }
    __syncthreads();

    // ======== phase 2: acc = h1 @ W2 (K = 128) ========
    {
        issueB(W2, 0, 0); CP_COMMIT();
        issueB(W2, 32, 1); CP_COMMIT();
        const uint32_t h1B = smem_u32(H1);
        int stg = 0;
        for (int it = 0; it < 4; it++) {
            if (it < 3) asm volatile("cp.async.wait_group 1;");
            else        asm volatile("cp.async.wait_group 0;");
            __syncthreads();
            {
                const uint32_t aB = h1B + (uint32_t)(it * 32 * 2);
                computeAB(aB, SKB2, smem_u32(BsBase + stg * B_STG));
            }
            if (it + 2 < 4) {
                int ns = stg + 2; if (ns >= 3) ns -= 3;
                issueB(W2, (it + 2) * 32, ns); CP_COMMIT();
            }
            if (++stg == 3) stg = 0;
        }
    }

    // ---- epilogue 2: C = relu(bn(acc + b2)) fp16 ----
    const float bninv = rsqrtf(1.0f + 1e-5f);
    #pragma unroll
    for (int mt = 0; mt < 4; mt++) {
        int r0 = by * 128 + wm + mt * 16 + lr;
        int r1 = r0 + 8;
        #pragma unroll
        for (int nt = 0; nt < 4; nt++) {
            int col = wn + nt * 8 + 2 * lc;
            float bb0 = __ldg(b2 + col), bb1 = __ldg(b2 + col + 1);
            float g0 = __ldg(bng + col) * bninv, g1 = __ldg(bng + col + 1) * bninv;
            float be0 = __ldg(bnb + col), be1 = __ldg(bnb + col + 1);
            float v00 = fmaxf((acc[mt][nt][0] + bb0) * g0 + be0, 0.f);
            float v01 = fmaxf((acc[mt][nt][1] + bb1) * g1 + be1, 0.f);
            float v10 = fmaxf((acc[mt][nt][2] + bb0) * g0 + be0, 0.f);
            float v11 = fmaxf((acc[mt][nt][3] + bb1) * g1 + be1, 0.f);
            if (r0 < M) *(__half2*)&C[(long long)r0 * 128 + col] = __floats2half2_rn(v00, v01);
            if (r1 < M) *(__half2*)&C[(long long)r1 * 128 + col] = __floats2half2_rn(v10, v11);
        }
    }
}

// ---------------------------------------------------------------------------
extern "C" void kernel_launch(void* const* d_in, const int* in_sizes, int n_in,
                              void* d_out, int out_size) {
    const float* x     = (const float*)d_in[0];
    const int*   ei    = (const int*)  d_in[1];
    const int*   src   = ei;
    const int*   dst   = ei + NEDGES;
    const int*   batch = (const int*)  d_in[2];
    const float* fp    = (const float*)d_in[3];
    const float* c1w1 = (const float*)d_in[4],  *c1b1 = (const float*)d_in[5];
    const float* c1w2 = (const float*)d_in[6],  *c1b2 = (const float*)d_in[7];
    const float* c2w1 = (const float*)d_in[8],  *c2b1 = (const float*)d_in[9];
    const float* c2w2 = (const float*)d_in[10], *c2b2 = (const float*)d_in[11];
    const float* c3w1 = (const float*)d_in[12], *c3b1 = (const float*)d_in[13];
    const float* c3w2 = (const float*)d_in[14], *c3b2 = (const float*)d_in[15];
    const float* bn1g = (const float*)d_in[16], *bn1b = (const float*)d_in[17];
    const float* bn2g = (const float*)d_in[18], *bn2b = (const float*)d_in[19];
    const float* bn3g = (const float*)d_in[20], *bn3b = (const float*)d_in[21];
    const float* o1w  = (const float*)d_in[22], *o1b  = (const float*)d_in[23];
    const float* obng = (const float*)d_in[24], *obnb = (const float*)d_in[25];
    const float* o3w  = (const float*)d_in[26], *o3b  = (const float*)d_in[27];
    float* out = (float*)d_out;

    __half *xh, *aggrh, *tmph, *hh, *wh, *poolh;
    float *scr;
    int *deg, *cursor, *rowptr, *srclist, *gstart;
    cudaGetSymbolAddress((void**)&xh,      g_xh);
    cudaGetSymbolAddress((void**)&aggrh,   g_aggrh);
    cudaGetSymbolAddress((void**)&tmph,    g_tmph);
    cudaGetSymbolAddress((void**)&hh,      g_hh);
    cudaGetSymbolAddress((void**)&wh,      g_wh);
    cudaGetSymbolAddress((void**)&poolh,   g_poolh);
    cudaGetSymbolAddress((void**)&scr,     g_scr);
    cudaGetSymbolAddress((void**)&deg,     g_deg);
    cudaGetSymbolAddress((void**)&cursor,  g_cursor);
    cudaGetSymbolAddress((void**)&rowptr,  g_rowptr);
    cudaGetSymbolAddress((void**)&srclist, g_srclist);
    cudaGetSymbolAddress((void**)&gstart,  g_gstart);

    cudaFuncSetAttribute(hgemm16_kernel<1,0,true>,  cudaFuncAttributeMaxDynamicSharedMemorySize, HG_SMEM);
    cudaFuncSetAttribute(hgemm16_kernel<2,0,true>,  cudaFuncAttributeMaxDynamicSharedMemorySize, HG_SMEM);
    cudaFuncSetAttribute(hgemm16_kernel<0,1,false>, cudaFuncAttributeMaxDynamicSharedMemorySize, HG_SMEM);
    cudaFuncSetAttribute(hgemm_fused_kernel<64>,  cudaFuncAttributeMaxDynamicSharedMemorySize, FU_SMEM);
    cudaFuncSetAttribute(hgemm_fused_kernel<128>, cudaFuncAttributeMaxDynamicSharedMemorySize, FU_SMEM);

    const int T = 256;
    const int gy = (NNODES + 127) / 128;

    // ---- fork/join infrastructure ----
    cudaStream_t sB, sC, sP;
    cudaStreamCreateWithFlags(&sB, cudaStreamNonBlocking);
    cudaStreamCreateWithFlags(&sC, cudaStreamNonBlocking);
    cudaStreamCreateWithFlags(&sP, cudaStreamNonBlocking);
    cudaEvent_t evRoot, evB, evC, evH[3], evP[3];
    cudaEventCreateWithFlags(&evRoot, cudaEventDisableTiming);
    cudaEventCreateWithFlags(&evB,    cudaEventDisableTiming);
    cudaEventCreateWithFlags(&evC,    cudaEventDisableTiming);
    for (int i = 0; i < 3; i++) {
        cudaEventCreateWithFlags(&evH[i], cudaEventDisableTiming);
        cudaEventCreateWithFlags(&evP[i], cudaEventDisableTiming);
    }

    cudaEventRecord(evRoot, 0);
    cudaStreamWaitEvent(sB, evRoot, 0);
    cudaStreamWaitEvent(sC, evRoot, 0);

    // ---- sB: big readout-weight converts ----
    {
        WConvArgs wb = {};
        wb.seg[0] = { (const float2*)o3w, (__half2*)(wh + W_O3W), 212992 };
        wb.seg[1] = { (const float2*)o1w, (__half2*)(wh + W_O1W), 11075584 };
        wb.total = 212992 + 11075584;
        wconv_kernel<<<2048, T, 0, sB>>>(wb);
        cudaEventRecord(evB, sB);
    }
    // ---- sC: x convert + fingerprint + conv weights ----
    {
        f2h_kernel<<<(NNODES * 32 + T - 1) / T, T, 0, sC>>>((const float2*)x, (__half2*)xh, NNODES * 32);
        fp_copy_kernel<<<dim3((1536 + T - 1) / T, NGRAPH), T, 0, sC>>>((const float4*)fp, (uint2*)poolh);
        WConvArgs wc = {};
        wc.seg[0] = { (const float2*)c1w1, (__half2*)(wh + W_C1W1), 4096 };
        wc.seg[1] = { (const float2*)c1w2, (__half2*)(wh + W_C1W2), 8192 };
        wc.seg[2] = { (const float2*)c2w1, (__half2*)(wh + W_C2W1), 8192 };
        wc.seg[3] = { (const float2*)c2w2, (__half2*)(wh + W_C2W2), 8192 };
        wc.seg[4] = { (const float2*)c3w1, (__half2*)(wh + W_C3W1), 16384 };
        wc.seg[5] = { (const float2*)c3w2, (__half2*)(wh + W_C3W2), 32768 };
        wc.total = 4096 + 8192 + 8192 + 8192 + 16384 + 32768;
        wconv_kernel<<<256, T, 0, sC>>>(wc);
        cudaEventRecord(evC, sC);
    }
    // ---- main: CSR build ----
    cudaMemsetAsync(deg, 0, NNODES * sizeof(int), 0);
    hist_kernel<<<(NEDGES + T - 1) / T, T>>>(dst, deg);
    scan_kernel<<<1, 1024>>>(deg, rowptr, cursor);
    fill_kernel<<<(NEDGES / 4 + T - 1) / T, T>>>(src, dst, cursor, srclist);
    gstart_kernel<<<3, 256>>>(batch, gstart);
    cudaStreamWaitEvent(0, evC, 0);

    // ---- conv1 (64 -> 128 -> 128), fused MLP ----
    gather_aggr_h_kernel<64><<<(NNODES * 8 + T - 1) / T, T>>>((const uint4*)xh, rowptr, srclist, (uint4*)aggrh);
    hgemm_fused_kernel<64><<<dim3(1, gy), T, FU_SMEM>>>(NNODES, aggrh, wh + W_C1W1, c1b1, wh + W_C1W2, c1b2, bn1g, bn1b, hh);
    cudaEventRecord(evH[0], 0);
    cudaStreamWaitEvent(sP, evH[0], 0);
    seg_pool_h_kernel<<<NGRAPH, 64, 0, sP>>>((const __half2*)hh, gstart, (__half2*)poolh, 64, 0);
    cudaEventRecord(evP[0], sP);

    // ---- conv2 (128 -> 128 -> 128), fused MLP ----
    gather_aggr_h_kernel<128><<<(NNODES * 16 + T - 1) / T, T>>>((const uint4*)hh, rowptr, srclist, (uint4*)aggrh);
    cudaStreamWaitEvent(0, evP[0], 0);
    hgemm_fused_kernel<128><<<dim3(1, gy), T, FU_SMEM>>>(NNODES, aggrh, wh + W_C2W1, c2b1, wh + W_C2W2, c2b2, bn2g, bn2b, hh);
    cudaEventRecord(evH[1], 0);
    cudaStreamWaitEvent(sP, evH[1], 0);
    seg_pool_h_kernel<<<NGRAPH, 64, 0, sP>>>((const __half2*)hh, gstart, (__half2*)poolh, 64, 64);
    cudaEventRecord(evP[1], sP);

    // ---- conv3 (128 -> 256 -> 256), unfused ----
    gather_aggr_h_kernel<128><<<(NNODES * 16 + T - 1) / T, T>>>((const uint4*)hh, rowptr, srclist, (uint4*)aggrh);
    hgemm16_kernel<1,0,true><<<dim3(2, gy), T, HG_SMEM>>>(NNODES, 256, 128, 128, aggrh, wh + W_C3W1, c3b1, nullptr, nullptr, tmph);
    cudaStreamWaitEvent(0, evP[1], 0);
    hgemm16_kernel<2,0,true><<<dim3(2, gy), T, HG_SMEM>>>(NNODES, 256, 256, 256, tmph, wh + W_C3W2, c3b2, bn3g, bn3b, hh);
    cudaEventRecord(evH[2], 0);
    cudaStreamWaitEvent(sP, evH[2], 0);
    seg_pool_h_kernel<<<NGRAPH, 128, 0, sP>>>((const __half2*)hh, gstart, (__half2*)poolh, 128, 128);
    cudaEventRecord(evP[2], sP);

    // ---- join before readout ----
    cudaStreamWaitEvent(0, evP[2], 0);
    cudaStreamWaitEvent(0, evB, 0);

    // ---- readout GEMM1: split-K=4 ----
    hgemm16_kernel<0,1,false><<<dim3(3328 / 128, 4, 4), T, HG_SMEM>>>(NGRAPH, 3328, 1664, RDIM, poolh, wh + W_O1W, nullptr, nullptr, nullptr, scr);
    readout_reduce_kernel<<<(NGRAPH * 832 + T - 1) / T, T>>>((const float4*)scr, o1b, obng, obnb, (uint2*)tmph);

    // ---- readout GEMM2: split-K=8 ----
    float* scr2 = scr + 4 * NGRAPH * 3328;
    hgemm16_kernel<0,1,false><<<dim3(1, 4, 8), T, HG_SMEM>>>(NGRAPH, 128, 416, 3328, tmph, wh + W_O3W, nullptr, nullptr, nullptr, scr2);
    final_reduce_kernel<<<(NGRAPH * 128 + T - 1) / T, T>>>(scr2, o3b, out);

    // ---- cleanup ----
    cudaEventDestroy(evRoot); cudaEventDestroy(evB); cudaEventDestroy(evC);
    for (int i = 0; i < 3; i++) { cudaEventDestroy(evH[i]); cudaEventDestroy(evP[i]); }
    cudaStreamDestroy(sB); cudaStreamDestroy(sC); cudaStreamDestroy(sP);
}

// round 15
// speedup vs baseline: 6.2988x; 1.1105x over previous
#include <cuda_runtime.h>
#include <cuda_fp16.h>
#include <cstdint>

#define NNODES 100000
#define NEDGES 1600000
#define NGRAPH 512
#define RDIM   6656

#define W_C1W1 0
#define W_C1W2 8192
#define W_C2W1 24576
#define W_C2W2 40960
#define W_C3W1 57344
#define W_C3W2 90112
#define W_O1W  155648
#define W_O3W  22306816
#define W_TOTAL 22732800

// ---- static device scratch (no allocations allowed) ----
static __device__ __align__(16) __half g_xh   [NNODES * 64];
static __device__ __align__(16) __half g_aggrh[NNODES * 256];
static __device__ __align__(16) __half g_tmph [NNODES * 256];
static __device__ __align__(16) __half g_hh   [NNODES * 256];
static __device__ __align__(16) __half g_wh   [W_TOTAL];
static __device__ __align__(16) __half g_poolh[NGRAPH * RDIM];
static __device__ __align__(16) float  g_scr  [10 * 1024 * 1024];
static __device__ int g_deg[NNODES];
static __device__ int g_cursor[NNODES];
static __device__ int g_rowptr[NNODES + 1];
static __device__ int g_srclist[NEDGES];
static __device__ int g_gstart[NGRAPH + 1];

// ---------------------------------------------------------------------------
// CSR build
// ---------------------------------------------------------------------------
__global__ void hist_kernel(const int* __restrict__ edst, int* __restrict__ deg) {
    int base = (blockIdx.x * blockDim.x + threadIdx.x) * 4;
    #pragma unroll
    for (int q = 0; q < 4; q++) {
        int e = base + q;
        if (e < NEDGES) atomicAdd(&deg[__ldg(edst + e)], 1);
    }
}
__global__ __launch_bounds__(1024) void scan_kernel(const int* __restrict__ deg,
                                                    int* __restrict__ rowptr,
                                                    int* __restrict__ cursor) {
    __shared__ int sums[1024];
    const int t = threadIdx.x;
    const int chunk = (NNODES + 1023) / 1024;
    const int beg = t * chunk;
    const int end = min(beg + chunk, NNODES);
    int s = 0;
    for (int k = beg; k < end; k++) s += deg[k];
    sums[t] = s;
    __syncthreads();
    for (int off = 1; off < 1024; off <<= 1) {
        int v = (t >= off) ? sums[t - off] : 0;
        __syncthreads();
        sums[t] += v;
        __syncthreads();
    }
    int run = sums[t] - s;
    for (int k = beg; k < end; k++) {
        rowptr[k] = run;
        cursor[k] = run;
        run += deg[k];
    }
    if (t == 1023) rowptr[NNODES] = sums[1023];
}
__global__ void fill_kernel(const int* __restrict__ esrc, const int* __restrict__ edst,
                            int* __restrict__ cursor, int* __restrict__ srclist) {
    int base = (blockIdx.x * blockDim.x + threadIdx.x) * 4;
    #pragma unroll
    for (int q = 0; q < 4; q++) {
        int e = base + q;
        if (e < NEDGES) {
            int d = __ldg(edst + e);
            int pos = atomicAdd(&cursor[d], 1);
            srclist[pos] = __ldg(esrc + e);
        }
    }
}
__global__ void gstart_kernel(const int* __restrict__ batch, int* __restrict__ gstart) {
    int g = blockIdx.x * blockDim.x + threadIdx.x;
    if (g > NGRAPH) return;
    if (g == NGRAPH) { gstart[NGRAPH] = NNODES; return; }
    int lo = 0, hi = NNODES;
    while (lo < hi) {
        int mid = (lo + hi) >> 1;
        if (__ldg(batch + mid) < g) lo = mid + 1; else hi = mid;
    }
    gstart[g] = lo;
}

// ---------------------------------------------------------------------------
// converts
// ---------------------------------------------------------------------------
__global__ void f2h_kernel(const float2* __restrict__ in, __half2* __restrict__ out, int n2) {
    int i = blockIdx.x * blockDim.x + threadIdx.x;
    if (i < n2) {
        float2 v = __ldg(in + i);
        out[i] = __floats2half2_rn(v.x, v.y);
    }
}
struct WSeg { const float2* src; __half2* dst; int n; };
struct WConvArgs { WSeg seg[8]; int total; };
__global__ void wconv_kernel(WConvArgs a) {
    int stride = gridDim.x * blockDim.x;
    for (int idx = blockIdx.x * blockDim.x + threadIdx.x; idx < a.total; idx += stride) {
        int i = idx;
        #pragma unroll
        for (int s = 0; s < 8; s++) {
            if (i < a.seg[s].n) {
                float2 v = __ldg(a.seg[s].src + i);
                a.seg[s].dst[i] = __floats2half2_rn(v.x, v.y);
                break;
            }
            i -= a.seg[s].n;
        }
    }
}

// ---------------------------------------------------------------------------
// fp16 gather, uint4 lane loads, x4 neighbor unroll
// ---------------------------------------------------------------------------
__device__ __forceinline__ float2 h2f2(uint32_t h) {
    return __half22float2(*(__half2*)&h);
}
__device__ __forceinline__ void acc4(float2* a, const uint4& t) {
    float2 v0 = h2f2(t.x), v1 = h2f2(t.y), v2 = h2f2(t.z), v3 = h2f2(t.w);
    a[0].x += v0.x; a[0].y += v0.y;
    a[1].x += v1.x; a[1].y += v1.y;
    a[2].x += v2.x; a[2].y += v2.y;
    a[3].x += v3.x; a[3].y += v3.y;
}
template<int FH>
__global__ void gather_aggr_h_kernel(const uint4* __restrict__ feat,
                                     const int* __restrict__ rowptr,
                                     const int* __restrict__ srclist,
                                     uint4* __restrict__ aggr) {
    constexpr int L = FH / 8;
    constexpr int NPB = 256 / L;
    int i = blockIdx.x * NPB + threadIdx.x / L;
    if (i >= NNODES) return;
    int c = threadIdx.x % L;

    float2 a[4];
    {
        uint4 v0 = __ldg(&feat[i * L + c]);
        a[0] = h2f2(v0.x); a[1] = h2f2(v0.y); a[2] = h2f2(v0.z); a[3] = h2f2(v0.w);
    }
    int j = __ldg(rowptr + i);
    const int end = __ldg(rowptr + i + 1);
    for (; j + 3 < end; j += 4) {
        int s0 = __ldg(srclist + j);
        int s1 = __ldg(srclist + j + 1);
        int s2 = __ldg(srclist + j + 2);
        int s3 = __ldg(srclist + j + 3);
        uint4 t0 = __ldg(&feat[s0 * L + c]);
        uint4 t1 = __ldg(&feat[s1 * L + c]);
        uint4 t2 = __ldg(&feat[s2 * L + c]);
        uint4 t3 = __ldg(&feat[s3 * L + c]);
        acc4(a, t0); acc4(a, t1); acc4(a, t2); acc4(a, t3);
    }
    for (; j < end; j++) {
        int s0 = __ldg(srclist + j);
        uint4 t0 = __ldg(&feat[s0 * L + c]);
        acc4(a, t0);
    }
    __half2 r0 = __floats2half2_rn(a[0].x, a[0].y);
    __half2 r1 = __floats2half2_rn(a[1].x, a[1].y);
    __half2 r2 = __floats2half2_rn(a[2].x, a[2].y);
    __half2 r3 = __floats2half2_rn(a[3].x, a[3].y);
    uint4 o;
    o.x = *(uint32_t*)&r0; o.y = *(uint32_t*)&r1;
    o.z = *(uint32_t*)&r2; o.w = *(uint32_t*)&r3;
    aggr[i * L + c] = o;
}

// ---------------------------------------------------------------------------
// pools / copies / reductions
// ---------------------------------------------------------------------------
__global__ void seg_pool_h_kernel(const __half2* __restrict__ feat,
                                  const int* __restrict__ gstart,
                                  __half2* __restrict__ pool,
                                  int F2, int off2) {
    int g = blockIdx.x;
    int t = threadIdx.x;
    int beg = __ldg(gstart + g), end = __ldg(gstart + g + 1);
    float2 a0 = make_float2(0.f, 0.f), a1 = make_float2(0.f, 0.f);
    int r = beg;
    for (; r + 1 < end; r += 2) {
        float2 v0 = __half22float2(__ldg(feat + (long long)r * F2 + t));
        float2 v1 = __half22float2(__ldg(feat + (long long)(r + 1) * F2 + t));
        a0.x += v0.x; a0.y += v0.y; a1.x += v1.x; a1.y += v1.y;
    }
    if (r < end) {
        float2 v0 = __half22float2(__ldg(feat + (long long)r * F2 + t));
        a0.x += v0.x; a0.y += v0.y;
    }
    pool[(long long)g * (RDIM / 2) + off2 + t] = __floats2half2_rn(a0.x + a1.x, a0.y + a1.y);
}
__global__ void fp_copy_kernel(const float4* __restrict__ fp, uint2* __restrict__ pool) {
    int col = blockIdx.x * blockDim.x + threadIdx.x;
    int row = blockIdx.y;
    if (col >= 1536) return;
    float4 v = __ldg(fp + row * 1536 + col);
    __half2 h0 = __floats2half2_rn(v.x, v.y);
    __half2 h1 = __floats2half2_rn(v.z, v.w);
    uint2 o;
    o.x = *(uint32_t*)&h0; o.y = *(uint32_t*)&h1;
    pool[row * (RDIM / 4) + 128 + col] = o;
}
// sums 5 partial slots (4 fingerprint-part + 1 pool-part), fixed order
__global__ void readout_reduce_kernel(const float4* __restrict__ part,
                                      const float* __restrict__ bias,
                                      const float* __restrict__ bng,
                                      const float* __restrict__ bnb,
                                      uint2* __restrict__ outh) {
    const int N4 = 3328 / 4;
    int idx = blockIdx.x * blockDim.x + threadIdx.x;
    if (idx >= NGRAPH * N4) return;
    const long long SZ4 = (long long)NGRAPH * N4;
    int col = (idx % N4) * 4;
    float4 s = part[idx];
    #pragma unroll
    for (int z = 1; z < 5; z++) {
        float4 t = part[idx + z * SZ4];
        s.x += t.x; s.y += t.y; s.z += t.z; s.w += t.w;
    }
    const float bninv = rsqrtf(1.0f + 1e-5f);
    float* sp = &s.x;
    #pragma unroll
    for (int c = 0; c < 4; c++) {
        float v = (sp[c] + __ldg(bias + col + c)) * (__ldg(bng + col + c) * bninv) + __ldg(bnb + col + c);
        sp[c] = fmaxf(v, 0.0f);
    }
    __half2 h0 = __floats2half2_rn(s.x, s.y);
    __half2 h1 = __floats2half2_rn(s.z, s.w);
    uint2 o;
    o.x = *(uint32_t*)&h0; o.y = *(uint32_t*)&h1;
    outh[idx] = o;
}
__global__ void final_reduce_kernel(const float* __restrict__ part,
                                    const float* __restrict__ bias,
                                    float* __restrict__ out) {
    int idx = blockIdx.x * blockDim.x + threadIdx.x;
    if (idx >= NGRAPH * 128) return;
    float s = 0.0f;
    #pragma unroll
    for (int z = 0; z < 8; z++) s += part[idx + z * NGRAPH * 128];
    out[idx] = s + __ldg(bias + (idx & 127));
}

// ---------------------------------------------------------------------------
// shared GEMM machinery
// ---------------------------------------------------------------------------
#define SKA2 40
#define SKB2 136
#define A_STG (128 * SKA2)
#define B_STG (32 * SKB2)
#define HG_SMEM (3 * (A_STG + B_STG) * 2)
#define H1_STG (128 * SKB2)
#define FU_SMEM ((3 * (A_STG + B_STG) + H1_STG) * 2)

__device__ __forceinline__ uint32_t smem_u32(const void* p) {
    uint32_t a;
    asm("{ .reg .u64 t; cvta.to.shared.u64 t, %1; cvt.u32.u64 %0, t; }" : "=r"(a) : "l"(p));
    return a;
}
__device__ __forceinline__ void cp16(uint32_t s, const void* g, int sz) {
    asm volatile("cp.async.cg.shared.global [%0], [%1], 16, %2;" :: "r"(s), "l"(g), "r"(sz));
}
#define CP_COMMIT() asm volatile("cp.async.commit_group;")
#define LDMATRIX_X4(r0, r1, r2, r3, addr) \
    asm volatile("ldmatrix.sync.aligned.m8n8.x4.shared.b16 {%0,%1,%2,%3}, [%4];" \
        : "=r"(r0), "=r"(r1), "=r"(r2), "=r"(r3) : "r"(addr))
#define LDMATRIX_X4_T(r0, r1, r2, r3, addr) \
    asm volatile("ldmatrix.sync.aligned.m8n8.x4.trans.shared.b16 {%0,%1,%2,%3}, [%4];" \
        : "=r"(r0), "=r"(r1), "=r"(r2), "=r"(r3) : "r"(addr))
#define HMMA16816(acc, a0, a1, a2, a3, b0, b1) \
    asm volatile("mma.sync.aligned.m16n8k16.row.col.f32.f16.f16.f32 " \
        "{%0,%1,%2,%3}, {%4,%5,%6,%7}, {%8,%9}, {%0,%1,%2,%3};" \
        : "+f"((acc)[0]), "+f"((acc)[1]), "+f"((acc)[2]), "+f"((acc)[3]) \
        : "r"(a0), "r"(a1), "r"(a2), "r"(a3), "r"(b0), "r"(b1))

// ---------------------------------------------------------------------------
// unfused GEMM (conv3 + readout); SPLIT writes fp32 partials at C + (bz+ZOFF)*M*Nn
// ---------------------------------------------------------------------------
template<int EPI, int SPLIT, bool CH>
__global__ __launch_bounds__(256, 2) void hgemm16_kernel(
    int M, int Nn, int K, int ldA, int zoff,
    const __half* __restrict__ A, const __half* __restrict__ B,
    const float* __restrict__ bias,
    const float* __restrict__ bng, const float* __restrict__ bnb,
    void* __restrict__ Cv)
{
    extern __shared__ __half dsm[];
    __half* AsBase = dsm;
    __half* BsBase = dsm + 3 * A_STG;

    const int tid = threadIdx.x, bx = blockIdx.x, by = blockIdx.y, bz = blockIdx.z;
    const int warp = tid >> 5, lane = tid & 31;
    const int wm = (warp >> 2) * 64;
    const int wn = (warp & 3) * 32;
    const int lr = lane >> 2;
    const int lc = lane & 3;

    const long long koff = (long long)bz * K;

    auto issueT = [&](int kk, int stg) {
        __half* As = AsBase + stg * A_STG;
        __half* Bs = BsBase + stg * B_STG;
        #pragma unroll
        for (int q = 0; q < 2; q++) {
            int c = tid + q * 256;
            int row = c >> 2, kc = (c & 3) * 8;
            int gr = by * 128 + row;
            uint32_t sa = smem_u32(&As[row * SKA2 + kc]);
            const __half* g = A + (long long)gr * ldA + koff + kk + kc;
            cp16(sa, g, gr < M ? 16 : 0);
        }
        #pragma unroll
        for (int q = 0; q < 2; q++) {
            int c = tid + q * 256;
            int row = c >> 4, nc = (c & 15) * 8;
            uint32_t sb = smem_u32(&Bs[row * SKB2 + nc]);
            const __half* g = B + (koff + kk + row) * (long long)Nn + (long long)bx * 128 + nc;
            cp16(sb, g, 16);
        }
        CP_COMMIT();
    };

    float acc[4][4][4];
    #pragma unroll
    for (int i = 0; i < 4; i++)
        #pragma unroll
        for (int j = 0; j < 4; j++)
            #pragma unroll
            for (int t = 0; t < 4; t++) acc[i][j][t] = 0.0f;

    const int a_r = lane & 15, a_s = lane >> 4;
    const int b_k = lane & 7,  b_s = lane >> 3;

    auto compute = [&](int stg) {
        const uint32_t aB = smem_u32(AsBase + stg * A_STG);
        const uint32_t bB = smem_u32(BsBase + stg * B_STG);
        #pragma unroll
        for (int ks = 0; ks < 32; ks += 16) {
            uint32_t af[4][4], bf[4][2];
            #pragma unroll
            for (int mt = 0; mt < 4; mt++) {
                uint32_t addr = aB + (uint32_t)(((wm + mt * 16 + a_r) * SKA2 + ks + a_s * 8) * 2);
                LDMATRIX_X4(af[mt][0], af[mt][1], af[mt][2], af[mt][3], addr);
            }
            #pragma unroll
            for (int np = 0; np < 2; np++) {
                uint32_t addr = bB + (uint32_t)(((ks + (b_s & 1) * 8 + b_k) * SKB2 + wn + np * 16 + (b_s >> 1) * 8) * 2);
                uint32_t r0, r1, r2, r3;
                LDMATRIX_X4_T(r0, r1, r2, r3, addr);
                bf[2*np][0] = r0; bf[2*np][1] = r1;
                bf[2*np+1][0] = r2; bf[2*np+1][1] = r3;
            }
            #pragma unroll
            for (int mt = 0; mt < 4; mt++)
                #pragma unroll
                for (int nt = 0; nt < 4; nt++)
                    HMMA16816(acc[mt][nt], af[mt][0], af[mt][1], af[mt][2], af[mt][3], bf[nt][0], bf[nt][1]);
        }
    };

    const int nIter = K / 32;
    issueT(0, 0);
    issueT(32, 1);
    int stg = 0;
    for (int it = 0; it < nIter; it++) {
        if (it < nIter - 1) {
            asm volatile("cp.async.wait_group 1;");
        } else {
            asm volatile("cp.async.wait_group 0;");
        }
        __syncthreads();
        compute(stg);
        if (it + 2 < nIter) {
            int ns = stg + 2; if (ns >= 3) ns -= 3;
            issueT((it + 2) * 32, ns);
        }
        if (++stg == 3) stg = 0;
    }

    if (SPLIT) {
        float* Cz = (float*)Cv + (long long)(bz + zoff) * M * Nn;
        #pragma unroll
        for (int mt = 0; mt < 4; mt++) {
            int r0 = by * 128 + wm + mt * 16 + lr;
            int r1 = r0 + 8;
            #pragma unroll
            for (int nt = 0; nt < 4; nt++) {
                int col = bx * 128 + wn + nt * 8 + 2 * lc;
                if (r0 < M) *(float2*)&Cz[(long long)r0 * Nn + col] = make_float2(acc[mt][nt][0], acc[mt][nt][1]);
                if (r1 < M) *(float2*)&Cz[(long long)r1 * Nn + col] = make_float2(acc[mt][nt][2], acc[mt][nt][3]);
            }
        }
        return;
    }

    const float bninv = rsqrtf(1.0f + 1e-5f);
    #pragma unroll
    for (int mt = 0; mt < 4; mt++) {
        int r0 = by * 128 + wm + mt * 16 + lr;
        int r1 = r0 + 8;
        #pragma unroll
        for (int nt = 0; nt < 4; nt++) {
            int col = bx * 128 + wn + nt * 8 + 2 * lc;
            float b0 = __ldg(bias + col);
            float b1 = __ldg(bias + col + 1);
            float g0 = 1.f, g1 = 1.f, be0 = 0.f, be1 = 0.f;
            if (EPI == 2) {
                g0 = __ldg(bng + col) * bninv;  g1 = __ldg(bng + col + 1) * bninv;
                be0 = __ldg(bnb + col);         be1 = __ldg(bnb + col + 1);
            }
            float v00 = acc[mt][nt][0] + b0, v01 = acc[mt][nt][1] + b1;
            float v10 = acc[mt][nt][2] + b0, v11 = acc[mt][nt][3] + b1;
            if (EPI == 2) {
                v00 = v00 * g0 + be0; v01 = v01 * g1 + be1;
                v10 = v10 * g0 + be0; v11 = v11 * g1 + be1;
            }
            if (EPI >= 1) {
                v00 = fmaxf(v00, 0.f); v01 = fmaxf(v01, 0.f);
                v10 = fmaxf(v10, 0.f); v11 = fmaxf(v11, 0.f);
            }
            if (CH) {
                __half* Ch = (__half*)Cv;
                if (r0 < M) *(__half2*)&Ch[(long long)r0 * Nn + col] = __floats2half2_rn(v00, v01);
                if (r1 < M) *(__half2*)&Ch[(long long)r1 * Nn + col] = __floats2half2_rn(v10, v11);
            } else {
                float* Cf = (float*)Cv;
                if (r0 < M) *(float2*)&Cf[(long long)r0 * Nn + col] = make_float2(v00, v01);
                if (r1 < M) *(float2*)&Cf[(long long)r1 * Nn + col] = make_float2(v10, v11);
            }
        }
    }
}

// ---------------------------------------------------------------------------
// FUSED conv MLP (unchanged from R12)
// ---------------------------------------------------------------------------
template<int K1>
__global__ __launch_bounds__(256, 2) void hgemm_fused_kernel(
    int M,
    const __half* __restrict__ A, const __half* __restrict__ W1,
    const float* __restrict__ b1,
    const __half* __restrict__ W2, const float* __restrict__ b2,
    const float* __restrict__ bng, const float* __restrict__ bnb,
    __half* __restrict__ C)
{
    extern __shared__ __half dsm[];
    __half* AsBase = dsm;
    __half* BsBase = dsm + 3 * A_STG;
    __half* H1     = dsm + 3 * A_STG + 3 * B_STG;

    const int tid = threadIdx.x, by = blockIdx.y;
    const int warp = tid >> 5, lane = tid & 31;
    const int wm = (warp >> 2) * 64;
    const int wn = (warp & 3) * 32;
    const int lr = lane >> 2;
    const int lc = lane & 3;
    const int a_r = lane & 15, a_s = lane >> 4;
    const int b_k = lane & 7,  b_s = lane >> 3;

    auto issueA = [&](int kk, int stg, int ld) {
        __half* As = AsBase + stg * A_STG;
        #pragma unroll
        for (int q = 0; q < 2; q++) {
            int c = tid + q * 256;
            int row = c >> 2, kc = (c & 3) * 8;
            int gr = by * 128 + row;
            uint32_t sa = smem_u32(&As[row * SKA2 + kc]);
            cp16(sa, A + (long long)gr * ld + kk + kc, gr < M ? 16 : 0);
        }
    };
    auto issueB = [&](const __half* B, int kk, int stg) {
        __half* Bs = BsBase + stg * B_STG;
        #pragma unroll
        for (int q = 0; q < 2; q++) {
            int c = tid + q * 256;
            int row = c >> 4, nc = (c & 15) * 8;
            uint32_t sb = smem_u32(&Bs[row * SKB2 + nc]);
            cp16(sb, B + (long long)(kk + row) * 128 + nc, 16);
        }
    };

    float acc[4][4][4];
    #pragma unroll
    for (int i = 0; i < 4; i++)
        #pragma unroll
        for (int j = 0; j < 4; j++)
            #pragma unroll
            for (int t = 0; t < 4; t++) acc[i][j][t] = 0.0f;

    auto computeAB = [&](uint32_t aB, int aStride, uint32_t bB) {
        #pragma unroll
        for (int ks = 0; ks < 32; ks += 16) {
            uint32_t af[4][4], bf[4][2];
            #pragma unroll
            for (int mt = 0; mt < 4; mt++) {
                uint32_t addr = aB + (uint32_t)(((wm + mt * 16 + a_r) * aStride + ks + a_s * 8) * 2);
                LDMATRIX_X4(af[mt][0], af[mt][1], af[mt][2], af[mt][3], addr);
            }
            #pragma unroll
            for (int np = 0; np < 2; np++) {
                uint32_t addr = bB + (uint32_t)(((ks + (b_s & 1) * 8 + b_k) * SKB2 + wn + np * 16 + (b_s >> 1) * 8) * 2);
                uint32_t r0, r1, r2, r3;
                LDMATRIX_X4_T(r0, r1, r2, r3, addr);
                bf[2*np][0] = r0; bf[2*np][1] = r1;
                bf[2*np+1][0] = r2; bf[2*np+1][1] = r3;
            }
            #pragma unroll
            for (int mt = 0; mt < 4; mt++)
                #pragma unroll
                for (int nt = 0; nt < 4; nt++)
                    HMMA16816(acc[mt][nt], af[mt][0], af[mt][1], af[mt][2], af[mt][3], bf[nt][0], bf[nt][1]);
        }
    };

    {
        const int nIter = K1 / 32;
        issueA(0, 0, K1); issueB(W1, 0, 0); CP_COMMIT();
        issueA(32, 1, K1); issueB(W1, 32, 1); CP_COMMIT();
        int stg = 0;
        for (int it = 0; it < nIter; it++) {
            if (it < nIter - 1) asm volatile("cp.async.wait_group 1;");
            else                asm volatile("cp.async.wait_group 0;");
            __syncthreads();
            computeAB(smem_u32(AsBase + stg * A_STG), SKA2, smem_u32(BsBase + stg * B_STG));
            if (it + 2 < nIter) {
                int ns = stg + 2; if (ns >= 3) ns -= 3;
                issueA((it + 2) * 32, ns, K1); issueB(W1, (it + 2) * 32, ns); CP_COMMIT();
            }
            if (++stg == 3) stg = 0;
        }
    }
    __syncthreads();

    #pragma unroll
    for (int mt = 0; mt < 4; mt++) {
        int r0 = wm + mt * 16 + lr;
        int r1 = r0 + 8;
        #pragma unroll
        for (int nt = 0; nt < 4; nt++) {
            int col = wn + nt * 8 + 2 * lc;
            float bb0 = __ldg(b1 + col);
            float bb1 = __ldg(b1 + col + 1);
            float v00 = fmaxf(acc[mt][nt][0] + bb0, 0.f);
            float v01 = fmaxf(acc[mt][nt][1] + bb1, 0.f);
            float v10 = fmaxf(acc[mt][nt][2] + bb0, 0.f);
            float v11 = fmaxf(acc[mt][nt][3] + bb1, 0.f);
            *(__half2*)&H1[r0 * SKB2 + col] = __floats2half2_rn(v00, v01);
            *(__half2*)&H1[r1 * SKB2 + col] = __floats2half2_rn(v10, v11);
            acc[mt][nt][0] = 0.f; acc[mt][nt][1] = 0.f;
            acc[mt][nt][2] = 0.f; acc[mt][nt][3] = 0.f;
        }
    }
    __syncthreads();

    {
        issueB(W2, 0, 0); CP_COMMIT();
        issueB(W2, 32, 1); CP_COMMIT();
        const uint32_t h1B = smem_u32(H1);
        int stg = 0;
        for (int it = 0; it < 4; it++) {
            if (it < 3) asm volatile("cp.async.wait_group 1;");
            else        asm volatile("cp.async.wait_group 0;");
            __syncthreads();
            {
                const uint32_t aB = h1B + (uint32_t)(it * 32 * 2);
                computeAB(aB, SKB2, smem_u32(BsBase + stg * B_STG));
            }
            if (it + 2 < 4) {
                int ns = stg + 2; if (ns >= 3) ns -= 3;
                issueB(W2, (it + 2) * 32, ns); CP_COMMIT();
            }
            if (++stg == 3) stg = 0;
        }
    }

    const float bninv = rsqrtf(1.0f + 1e-5f);
    #pragma unroll
    for (int mt = 0; mt < 4; mt++) {
        int r0 = by * 128 + wm + mt * 16 + lr;
        int r1 = r0 + 8;
        #pragma unroll
        for (int nt = 0; nt < 4; nt++) {
            int col = wn + nt * 8 + 2 * lc;
            float bb0 = __ldg(b2 + col), bb1 = __ldg(b2 + col + 1);
            float g0 = __ldg(bng + col) * bninv, g1 = __ldg(bng + col + 1) * bninv;
            float be0 = __ldg(bnb + col), be1 = __ldg(bnb + col + 1);
            float v00 = fmaxf((acc[mt][nt][0] + bb0) * g0 + be0, 0.f);
            float v01 = fmaxf((acc[mt][nt][1] + bb1) * g1 + be1, 0.f);
            float v10 = fmaxf((acc[mt][nt][2] + bb0) * g0 + be0, 0.f);
            float v11 = fmaxf((acc[mt][nt][3] + bb1) * g1 + be1, 0.f);
            if (r0 < M) *(__half2*)&C[(long long)r0 * 128 + col] = __floats2half2_rn(v00, v01);
            if (r1 < M) *(__half2*)&C[(long long)r1 * 128 + col] = __floats2half2_rn(v10, v11);
        }
    }
}

// ---------------------------------------------------------------------------
extern "C" void kernel_launch(void* const* d_in, const int* in_sizes, int n_in,
                              void* d_out, int out_size) {
    const float* x     = (const float*)d_in[0];
    const int*   ei    = (const int*)  d_in[1];
    const int*   src   = ei;
    const int*   dst   = ei + NEDGES;
    const int*   batch = (const int*)  d_in[2];
    const float* fp    = (const float*)d_in[3];
    const float* c1w1 = (const float*)d_in[4],  *c1b1 = (const float*)d_in[5];
    const float* c1w2 = (const float*)d_in[6],  *c1b2 = (const float*)d_in[7];
    const float* c2w1 = (const float*)d_in[8],  *c2b1 = (const float*)d_in[9];
    const float* c2w2 = (const float*)d_in[10], *c2b2 = (const float*)d_in[11];
    const float* c3w1 = (const float*)d_in[12], *c3b1 = (const float*)d_in[13];
    const float* c3w2 = (const float*)d_in[14], *c3b2 = (const float*)d_in[15];
    const float* bn1g = (const float*)d_in[16], *bn1b = (const float*)d_in[17];
    const float* bn2g = (const float*)d_in[18], *bn2b = (const float*)d_in[19];
    const float* bn3g = (const float*)d_in[20], *bn3b = (const float*)d_in[21];
    const float* o1w  = (const float*)d_in[22], *o1b  = (const float*)d_in[23];
    const float* obng = (const float*)d_in[24], *obnb = (const float*)d_in[25];
    const float* o3w  = (const float*)d_in[26], *o3b  = (const float*)d_in[27];
    float* out = (float*)d_out;

    __half *xh, *aggrh, *tmph, *hh, *wh, *poolh;
    float *scr;
    int *deg, *cursor, *rowptr, *srclist, *gstart;
    cudaGetSymbolAddress((void**)&xh,      g_xh);
    cudaGetSymbolAddress((void**)&aggrh,   g_aggrh);
    cudaGetSymbolAddress((void**)&tmph,    g_tmph);
    cudaGetSymbolAddress((void**)&hh,      g_hh);
    cudaGetSymbolAddress((void**)&wh,      g_wh);
    cudaGetSymbolAddress((void**)&poolh,   g_poolh);
    cudaGetSymbolAddress((void**)&scr,     g_scr);
    cudaGetSymbolAddress((void**)&deg,     g_deg);
    cudaGetSymbolAddress((void**)&cursor,  g_cursor);
    cudaGetSymbolAddress((void**)&rowptr,  g_rowptr);
    cudaGetSymbolAddress((void**)&srclist, g_srclist);
    cudaGetSymbolAddress((void**)&gstart,  g_gstart);

    cudaFuncSetAttribute(hgemm16_kernel<1,0,true>,  cudaFuncAttributeMaxDynamicSharedMemorySize, HG_SMEM);
    cudaFuncSetAttribute(hgemm16_kernel<2,0,true>,  cudaFuncAttributeMaxDynamicSharedMemorySize, HG_SMEM);
    cudaFuncSetAttribute(hgemm16_kernel<0,1,false>, cudaFuncAttributeMaxDynamicSharedMemorySize, HG_SMEM);
    cudaFuncSetAttribute(hgemm_fused_kernel<64>,  cudaFuncAttributeMaxDynamicSharedMemorySize, FU_SMEM);
    cudaFuncSetAttribute(hgemm_fused_kernel<128>, cudaFuncAttributeMaxDynamicSharedMemorySize, FU_SMEM);

    const int T = 256;
    const int gy = (NNODES + 127) / 128;
    const long long SZ = (long long)NGRAPH * 3328;

    // ---- fork/join infrastructure ----
    cudaStream_t sB, sC, sP;
    cudaStreamCreateWithFlags(&sB, cudaStreamNonBlocking);
    cudaStreamCreateWithFlags(&sC, cudaStreamNonBlocking);
    cudaStreamCreateWithFlags(&sP, cudaStreamNonBlocking);
    cudaEvent_t evRoot, evB, evC, evH[3], evP[3];
    cudaEventCreateWithFlags(&evRoot, cudaEventDisableTiming);
    cudaEventCreateWithFlags(&evB,    cudaEventDisableTiming);
    cudaEventCreateWithFlags(&evC,    cudaEventDisableTiming);
    for (int i = 0; i < 3; i++) {
        cudaEventCreateWithFlags(&evH[i], cudaEventDisableTiming);
        cudaEventCreateWithFlags(&evP[i], cudaEventDisableTiming);
    }

    cudaEventRecord(evRoot, 0);
    cudaStreamWaitEvent(sB, evRoot, 0);
    cudaStreamWaitEvent(sC, evRoot, 0);

    // ---- sC: x convert + fingerprint + conv weights ----
    {
        f2h_kernel<<<(NNODES * 32 + T - 1) / T, T, 0, sC>>>((const float2*)x, (__half2*)xh, NNODES * 32);
        fp_copy_kernel<<<dim3((1536 + T - 1) / T, NGRAPH), T, 0, sC>>>((const float4*)fp, (uint2*)poolh);
        WConvArgs wc = {};
        wc.seg[0] = { (const float2*)c1w1, (__half2*)(wh + W_C1W1), 4096 };
        wc.seg[1] = { (const float2*)c1w2, (__half2*)(wh + W_C1W2), 8192 };
        wc.seg[2] = { (const float2*)c2w1, (__half2*)(wh + W_C2W1), 8192 };
        wc.seg[3] = { (const float2*)c2w2, (__half2*)(wh + W_C2W2), 8192 };
        wc.seg[4] = { (const float2*)c3w1, (__half2*)(wh + W_C3W1), 16384 };
        wc.seg[5] = { (const float2*)c3w2, (__half2*)(wh + W_C3W2), 32768 };
        wc.total = 4096 + 8192 + 8192 + 8192 + 16384 + 32768;
        wconv_kernel<<<256, T, 0, sC>>>(wc);
        cudaEventRecord(evC, sC);
    }
    // ---- sB: big weight converts, then fingerprint-part of readout GEMM1 ----
    {
        WConvArgs wb = {};
        wb.seg[0] = { (const float2*)o3w, (__half2*)(wh + W_O3W), 212992 };
        wb.seg[1] = { (const float2*)o1w, (__half2*)(wh + W_O1W), 11075584 };
        wb.total = 212992 + 11075584;
        wconv_kernel<<<2048, T, 0, sB>>>(wb);
        cudaStreamWaitEvent(sB, evC, 0);   // fingerprint columns of poolh ready
        // GEMM1 part-B: K = 6144 (pool cols 512..6655), split-K 4 -> slots 0..3
        hgemm16_kernel<0,1,false><<<dim3(3328 / 128, 4, 4), T, HG_SMEM, sB>>>(
            NGRAPH, 3328, 1536, RDIM, 0, poolh + 512, wh + W_O1W + (long long)512 * 3328,
            nullptr, nullptr, nullptr, scr);
        cudaEventRecord(evB, sB);
    }
    // ---- main: CSR build ----
    cudaMemsetAsync(deg, 0, NNODES * sizeof(int), 0);
    hist_kernel<<<(NEDGES / 4 + T - 1) / T, T>>>(dst, deg);
    scan_kernel<<<1, 1024>>>(deg, rowptr, cursor);
    fill_kernel<<<(NEDGES / 4 + T - 1) / T, T>>>(src, dst, cursor, srclist);
    gstart_kernel<<<3, 256>>>(batch, gstart);
    cudaStreamWaitEvent(0, evC, 0);

    // ---- conv1 (64 -> 128 -> 128), fused MLP ----
    gather_aggr_h_kernel<64><<<(NNODES * 8 + T - 1) / T, T>>>((const uint4*)xh, rowptr, srclist, (uint4*)aggrh);
    hgemm_fused_kernel<64><<<dim3(1, gy), T, FU_SMEM>>>(NNODES, aggrh, wh + W_C1W1, c1b1, wh + W_C1W2, c1b2, bn1g, bn1b, hh);
    cudaEventRecord(evH[0], 0);
    cudaStreamWaitEvent(sP, evH[0], 0);
    seg_pool_h_kernel<<<NGRAPH, 64, 0, sP>>>((const __half2*)hh, gstart, (__half2*)poolh, 64, 0);
    cudaEventRecord(evP[0], sP);

    // ---- conv2 (128 -> 128 -> 128), fused MLP ----
    gather_aggr_h_kernel<128><<<(NNODES * 16 + T - 1) / T, T>>>((const uint4*)hh, rowptr, srclist, (uint4*)aggrh);
    cudaStreamWaitEvent(0, evP[0], 0);
    hgemm_fused_kernel<128><<<dim3(1, gy), T, FU_SMEM>>>(NNODES, aggrh, wh + W_C2W1, c2b1, wh + W_C2W2, c2b2, bn2g, bn2b, hh);
    cudaEventRecord(evH[1], 0);
    cudaStreamWaitEvent(sP, evH[1], 0);
    seg_pool_h_kernel<<<NGRAPH, 64, 0, sP>>>((const __half2*)hh, gstart, (__half2*)poolh, 64, 64);
    cudaEventRecord(evP[1], sP);

    // ---- conv3 (128 -> 256 -> 256), unfused ----
    gather_aggr_h_kernel<128><<<(NNODES * 16 + T - 1) / T, T>>>((const uint4*)hh, rowptr, srclist, (uint4*)aggrh);
    hgemm16_kernel<1,0,true><<<dim3(2, gy), T, HG_SMEM>>>(NNODES, 256, 128, 128, 0, aggrh, wh + W_C3W1, c3b1, nullptr, nullptr, tmph);
    cudaStreamWaitEvent(0, evP[1], 0);
    hgemm16_kernel<2,0,true><<<dim3(2, gy), T, HG_SMEM>>>(NNODES, 256, 256, 256, 0, tmph, wh + W_C3W2, c3b2, bn3g, bn3b, hh);
    cudaEventRecord(evH[2], 0);
    cudaStreamWaitEvent(sP, evH[2], 0);
    seg_pool_h_kernel<<<NGRAPH, 128, 0, sP>>>((const __half2*)hh, gstart, (__half2*)poolh, 128, 128);
    cudaEventRecord(evP[2], sP);

    // ---- GEMM1 part-A: K = 512 (pool cols 0..511), 1 slot -> slot 4 ----
    cudaStreamWaitEvent(0, evP[2], 0);
    cudaStreamWaitEvent(0, evB, 0);
    hgemm16_kernel<0,1,false><<<dim3(3328 / 128, 4, 1), T, HG_SMEM>>>(
        NGRAPH, 3328, 512, RDIM, 4, poolh, wh + W_O1W, nullptr, nullptr, nullptr, scr);
    readout_reduce_kernel<<<(NGRAPH * 832 + T - 1) / T, T>>>((const float4*)scr, o1b, obng, obnb, (uint2*)tmph);

    // ---- readout GEMM2: split-K=8, slots after the 5 GEMM1 slots ----
    float* scr2 = scr + 5 * SZ;
    hgemm16_kernel<0,1,false><<<dim3(1, 4, 8), T, HG_SMEM>>>(NGRAPH, 128, 416, 3328, 0, tmph, wh + W_O3W, nullptr, nullptr, nullptr, scr2);
    final_reduce_kernel<<<(NGRAPH * 128 + T - 1) / T, T>>>(scr2, o3b, out);

    // ---- cleanup ----
    cudaEventDestroy(evRoot); cudaEventDestroy(evB); cudaEventDestroy(evC);
    for (int i = 0; i < 3; i++) { cudaEventDestroy(evH[i]); cudaEventDestroy(evP[i]); }
    cudaStreamDestroy(sB); cudaStreamDestroy(sC); cudaStreamDestroy(sP);
}

// round 16
// speedup vs baseline: 7.6072x; 1.2077x over previous
#include <cuda_runtime.h>
#include <cuda_fp16.h>
#include <cstdint>

#define NNODES 100000
#define NEDGES 1600000
#define NGRAPH 512
#define RDIM   6656

#define W_C1W1 0
#define W_C1W2 8192
#define W_C2W1 24576
#define W_C2W2 40960
#define W_C3W1 57344
#define W_C3W2 90112
#define W_O1W  155648
#define W_O3W  22306816
#define W_TOTAL 22732800

#define NSCANB ((NNODES + 1023) / 1024)

// ---- static device scratch (no allocations allowed) ----
static __device__ __align__(16) __half g_xh   [NNODES * 64];
static __device__ __align__(16) __half g_aggrh[NNODES * 256];
static __device__ __align__(16) __half g_tmph [NNODES * 256];
static __device__ __align__(16) __half g_hh   [NNODES * 256];
static __device__ __align__(16) __half g_wh   [W_TOTAL];
static __device__ __align__(16) __half g_poolh[NGRAPH * RDIM];
static __device__ __align__(16) float  g_scr  [10 * 1024 * 1024];
static __device__ int g_deg[NNODES];
static __device__ int g_cursor[NNODES];
static __device__ int g_rowptr[NNODES + 1];
static __device__ int g_srclist[NEDGES];
static __device__ int g_gstart[NGRAPH + 1];
static __device__ int g_bsum[NSCANB + 1];

// ---------------------------------------------------------------------------
// CSR build
// ---------------------------------------------------------------------------
__global__ void hist_kernel(const int* __restrict__ edst, int* __restrict__ deg) {
    int base = (blockIdx.x * blockDim.x + threadIdx.x) * 4;
    #pragma unroll
    for (int q = 0; q < 4; q++) {
        int e = base + q;
        if (e < NEDGES) atomicAdd(&deg[__ldg(edst + e)], 1);
    }
}
// phase 1: per-block sums
__global__ __launch_bounds__(1024) void bsum_kernel(const int* __restrict__ deg, int* __restrict__ bsum) {
    __shared__ int red[1024];
    int t = threadIdx.x;
    int idx = blockIdx.x * 1024 + t;
    red[t] = (idx < NNODES) ? deg[idx] : 0;
    __syncthreads();
    for (int off = 512; off > 0; off >>= 1) {
        if (t < off) red[t] += red[t + off];
        __syncthreads();
    }
    if (t == 0) bsum[blockIdx.x] = red[0];
}
// phase 2: serial scan of block sums (tiny)
__global__ void boff_kernel(int* __restrict__ bsum, int* __restrict__ rowptr) {
    int run = 0;
    for (int b = 0; b < NSCANB; b++) { int v = bsum[b]; bsum[b] = run; run += v; }
    rowptr[NNODES] = run;
}
// phase 3: intra-block scan + offset
__global__ __launch_bounds__(1024) void rowptr_kernel(const int* __restrict__ deg,
                                                      const int* __restrict__ bsum,
                                                      int* __restrict__ rowptr,
                                                      int* __restrict__ cursor) {
    __shared__ int s[1024];
    int t = threadIdx.x;
    int idx = blockIdx.x * 1024 + t;
    int v = (idx < NNODES) ? deg[idx] : 0;
    s[t] = v;
    __syncthreads();
    for (int off = 1; off < 1024; off <<= 1) {
        int u = (t >= off) ? s[t - off] : 0;
        __syncthreads();
        s[t] += u;
        __syncthreads();
    }
    if (idx < NNODES) {
        int ex = s[t] - v + __ldg(bsum + blockIdx.x);
        rowptr[idx] = ex;
        cursor[idx] = ex;
    }
}
__global__ void fill_kernel(const int* __restrict__ esrc, const int* __restrict__ edst,
                            int* __restrict__ cursor, int* __restrict__ srclist) {
    int base = (blockIdx.x * blockDim.x + threadIdx.x) * 4;
    #pragma unroll
    for (int q = 0; q < 4; q++) {
        int e = base + q;
        if (e < NEDGES) {
            int d = __ldg(edst + e);
            int pos = atomicAdd(&cursor[d], 1);
            srclist[pos] = __ldg(esrc + e);
        }
    }
}
__global__ void gstart_kernel(const int* __restrict__ batch, int* __restrict__ gstart) {
    int g = blockIdx.x * blockDim.x + threadIdx.x;
    if (g > NGRAPH) return;
    if (g == NGRAPH) { gstart[NGRAPH] = NNODES; return; }
    int lo = 0, hi = NNODES;
    while (lo < hi) {
        int mid = (lo + hi) >> 1;
        if (__ldg(batch + mid) < g) lo = mid + 1; else hi = mid;
    }
    gstart[g] = lo;
}

// ---------------------------------------------------------------------------
// converts
// ---------------------------------------------------------------------------
__global__ void f2h_kernel(const float2* __restrict__ in, __half2* __restrict__ out, int n2) {
    int i = blockIdx.x * blockDim.x + threadIdx.x;
    if (i < n2) {
        float2 v = __ldg(in + i);
        out[i] = __floats2half2_rn(v.x, v.y);
    }
}
struct WSeg { const float2* src; __half2* dst; int n; };
struct WConvArgs { WSeg seg[8]; int total; };
__global__ void wconv_kernel(WConvArgs a) {
    int stride = gridDim.x * blockDim.x;
    for (int idx = blockIdx.x * blockDim.x + threadIdx.x; idx < a.total; idx += stride) {
        int i = idx;
        #pragma unroll
        for (int s = 0; s < 8; s++) {
            if (i < a.seg[s].n) {
                float2 v = __ldg(a.seg[s].src + i);
                a.seg[s].dst[i] = __floats2half2_rn(v.x, v.y);
                break;
            }
            i -= a.seg[s].n;
        }
    }
}

// ---------------------------------------------------------------------------
// fp16 gather, uint4 lane loads, x4 neighbor unroll
// ---------------------------------------------------------------------------
__device__ __forceinline__ float2 h2f2(uint32_t h) {
    return __half22float2(*(__half2*)&h);
}
__device__ __forceinline__ void acc4(float2* a, const uint4& t) {
    float2 v0 = h2f2(t.x), v1 = h2f2(t.y), v2 = h2f2(t.z), v3 = h2f2(t.w);
    a[0].x += v0.x; a[0].y += v0.y;
    a[1].x += v1.x; a[1].y += v1.y;
    a[2].x += v2.x; a[2].y += v2.y;
    a[3].x += v3.x; a[3].y += v3.y;
}
template<int FH>
__global__ void gather_aggr_h_kernel(const uint4* __restrict__ feat,
                                     const int* __restrict__ rowptr,
                                     const int* __restrict__ srclist,
                                     uint4* __restrict__ aggr) {
    constexpr int L = FH / 8;
    constexpr int NPB = 256 / L;
    int i = blockIdx.x * NPB + threadIdx.x / L;
    if (i >= NNODES) return;
    int c = threadIdx.x % L;

    float2 a[4];
    {
        uint4 v0 = __ldg(&feat[i * L + c]);
        a[0] = h2f2(v0.x); a[1] = h2f2(v0.y); a[2] = h2f2(v0.z); a[3] = h2f2(v0.w);
    }
    int j = __ldg(rowptr + i);
    const int end = __ldg(rowptr + i + 1);
    for (; j + 3 < end; j += 4) {
        int s0 = __ldg(srclist + j);
        int s1 = __ldg(srclist + j + 1);
        int s2 = __ldg(srclist + j + 2);
        int s3 = __ldg(srclist + j + 3);
        uint4 t0 = __ldg(&feat[s0 * L + c]);
        uint4 t1 = __ldg(&feat[s1 * L + c]);
        uint4 t2 = __ldg(&feat[s2 * L + c]);
        uint4 t3 = __ldg(&feat[s3 * L + c]);
        acc4(a, t0); acc4(a, t1); acc4(a, t2); acc4(a, t3);
    }
    for (; j < end; j++) {
        int s0 = __ldg(srclist + j);
        uint4 t0 = __ldg(&feat[s0 * L + c]);
        acc4(a, t0);
    }
    __half2 r0 = __floats2half2_rn(a[0].x, a[0].y);
    __half2 r1 = __floats2half2_rn(a[1].x, a[1].y);
    __half2 r2 = __floats2half2_rn(a[2].x, a[2].y);
    __half2 r3 = __floats2half2_rn(a[3].x, a[3].y);
    uint4 o;
    o.x = *(uint32_t*)&r0; o.y = *(uint32_t*)&r1;
    o.z = *(uint32_t*)&r2; o.w = *(uint32_t*)&r3;
    aggr[i * L + c] = o;
}

// ---------------------------------------------------------------------------
// pools / copies / reductions
// ---------------------------------------------------------------------------
__global__ void seg_pool_h_kernel(const __half2* __restrict__ feat,
                                  const int* __restrict__ gstart,
                                  __half2* __restrict__ pool,
                                  int F2, int off2) {
    int g = blockIdx.x;
    int t = threadIdx.x;
    int beg = __ldg(gstart + g), end = __ldg(gstart + g + 1);
    float2 a0 = make_float2(0.f, 0.f), a1 = make_float2(0.f, 0.f);
    int r = beg;
    for (; r + 1 < end; r += 2) {
        float2 v0 = __half22float2(__ldg(feat + (long long)r * F2 + t));
        float2 v1 = __half22float2(__ldg(feat + (long long)(r + 1) * F2 + t));
        a0.x += v0.x; a0.y += v0.y; a1.x += v1.x; a1.y += v1.y;
    }
    if (r < end) {
        float2 v0 = __half22float2(__ldg(feat + (long long)r * F2 + t));
        a0.x += v0.x; a0.y += v0.y;
    }
    pool[(long long)g * (RDIM / 2) + off2 + t] = __floats2half2_rn(a0.x + a1.x, a0.y + a1.y);
}
__global__ void fp_copy_kernel(const float4* __restrict__ fp, uint2* __restrict__ pool) {
    int col = blockIdx.x * blockDim.x + threadIdx.x;
    int row = blockIdx.y;
    if (col >= 1536) return;
    float4 v = __ldg(fp + row * 1536 + col);
    __half2 h0 = __floats2half2_rn(v.x, v.y);
    __half2 h1 = __floats2half2_rn(v.z, v.w);
    uint2 o;
    o.x = *(uint32_t*)&h0; o.y = *(uint32_t*)&h1;
    pool[row * (RDIM / 4) + 128 + col] = o;
}
__global__ void final_reduce_kernel(const float* __restrict__ part,
                                    const float* __restrict__ bias,
                                    float* __restrict__ out) {
    int idx = blockIdx.x * blockDim.x + threadIdx.x;
    if (idx >= NGRAPH * 128) return;
    float s = 0.0f;
    #pragma unroll
    for (int z = 0; z < 8; z++) s += part[idx + z * NGRAPH * 128];
    out[idx] = s + __ldg(bias + (idx & 127));
}

// ---------------------------------------------------------------------------
// shared GEMM machinery
// ---------------------------------------------------------------------------
#define SKA2 40
#define SKB2 136
#define A_STG (128 * SKA2)
#define B_STG (32 * SKB2)
#define HG_SMEM (3 * (A_STG + B_STG) * 2)
#define H1_STG (128 * SKB2)
#define FU_SMEM ((3 * (A_STG + B_STG) + H1_STG) * 2)

__device__ __forceinline__ uint32_t smem_u32(const void* p) {
    uint32_t a;
    asm("{ .reg .u64 t; cvta.to.shared.u64 t, %1; cvt.u32.u64 %0, t; }" : "=r"(a) : "l"(p));
    return a;
}
__device__ __forceinline__ void cp16(uint32_t s, const void* g, int sz) {
    asm volatile("cp.async.cg.shared.global [%0], [%1], 16, %2;" :: "r"(s), "l"(g), "r"(sz));
}
#define CP_COMMIT() asm volatile("cp.async.commit_group;")
#define LDMATRIX_X4(r0, r1, r2, r3, addr) \
    asm volatile("ldmatrix.sync.aligned.m8n8.x4.shared.b16 {%0,%1,%2,%3}, [%4];" \
        : "=r"(r0), "=r"(r1), "=r"(r2), "=r"(r3) : "r"(addr))
#define LDMATRIX_X4_T(r0, r1, r2, r3, addr) \
    asm volatile("ldmatrix.sync.aligned.m8n8.x4.trans.shared.b16 {%0,%1,%2,%3}, [%4];" \
        : "=r"(r0), "=r"(r1), "=r"(r2), "=r"(r3) : "r"(addr))
#define HMMA16816(acc, a0, a1, a2, a3, b0, b1) \
    asm volatile("mma.sync.aligned.m16n8k16.row.col.f32.f16.f16.f32 " \
        "{%0,%1,%2,%3}, {%4,%5,%6,%7}, {%8,%9}, {%0,%1,%2,%3};" \
        : "+f"((acc)[0]), "+f"((acc)[1]), "+f"((acc)[2]), "+f"((acc)[3]) \
        : "r"(a0), "r"(a1), "r"(a2), "r"(a3), "r"(b0), "r"(b1))

// ---------------------------------------------------------------------------
// unfused GEMM.
// EPI: 0 +bias; 1 relu(+bias); 2 relu(bn(+bias));
//      3 relu(bn(acc + sum of 4 fp32 slots in red + bias)) -> fp16 C (readout fuse)
// SPLIT=1: grid.z splits K, fp32 partials at C + (bz+zoff)*M*Nn.
// ---------------------------------------------------------------------------
template<int EPI, int SPLIT, bool CH>
__global__ __launch_bounds__(256, 2) void hgemm16_kernel(
    int M, int Nn, int K, int ldA, int zoff,
    const __half* __restrict__ A, const __half* __restrict__ B,
    const float* __restrict__ bias,
    const float* __restrict__ bng, const float* __restrict__ bnb,
    const float* __restrict__ red,
    void* __restrict__ Cv)
{
    extern __shared__ __half dsm[];
    __half* AsBase = dsm;
    __half* BsBase = dsm + 3 * A_STG;

    const int tid = threadIdx.x, bx = blockIdx.x, by = blockIdx.y, bz = blockIdx.z;
    const int warp = tid >> 5, lane = tid & 31;
    const int wm = (warp >> 2) * 64;
    const int wn = (warp & 3) * 32;
    const int lr = lane >> 2;
    const int lc = lane & 3;

    const long long koff = (long long)bz * K;

    auto issueT = [&](int kk, int stg) {
        __half* As = AsBase + stg * A_STG;
        __half* Bs = BsBase + stg * B_STG;
        #pragma unroll
        for (int q = 0; q < 2; q++) {
            int c = tid + q * 256;
            int row = c >> 2, kc = (c & 3) * 8;
            int gr = by * 128 + row;
            uint32_t sa = smem_u32(&As[row * SKA2 + kc]);
            const __half* g = A + (long long)gr * ldA + koff + kk + kc;
            cp16(sa, g, gr < M ? 16 : 0);
        }
        #pragma unroll
        for (int q = 0; q < 2; q++) {
            int c = tid + q * 256;
            int row = c >> 4, nc = (c & 15) * 8;
            uint32_t sb = smem_u32(&Bs[row * SKB2 + nc]);
            const __half* g = B + (koff + kk + row) * (long long)Nn + (long long)bx * 128 + nc;
            cp16(sb, g, 16);
        }
        CP_COMMIT();
    };

    float acc[4][4][4];
    #pragma unroll
    for (int i = 0; i < 4; i++)
        #pragma unroll
        for (int j = 0; j < 4; j++)
            #pragma unroll
            for (int t = 0; t < 4; t++) acc[i][j][t] = 0.0f;

    const int a_r = lane & 15, a_s = lane >> 4;
    const int b_k = lane & 7,  b_s = lane >> 3;

    auto compute = [&](int stg) {
        const uint32_t aB = smem_u32(AsBase + stg * A_STG);
        const uint32_t bB = smem_u32(BsBase + stg * B_STG);
        #pragma unroll
        for (int ks = 0; ks < 32; ks += 16) {
            uint32_t af[4][4], bf[4][2];
            #pragma unroll
            for (int mt = 0; mt < 4; mt++) {
                uint32_t addr = aB + (uint32_t)(((wm + mt * 16 + a_r) * SKA2 + ks + a_s * 8) * 2);
                LDMATRIX_X4(af[mt][0], af[mt][1], af[mt][2], af[mt][3], addr);
            }
            #pragma unroll
            for (int np = 0; np < 2; np++) {
                uint32_t addr = bB + (uint32_t)(((ks + (b_s & 1) * 8 + b_k) * SKB2 + wn + np * 16 + (b_s >> 1) * 8) * 2);
                uint32_t r0, r1, r2, r3;
                LDMATRIX_X4_T(r0, r1, r2, r3, addr);
                bf[2*np][0] = r0; bf[2*np][1] = r1;
                bf[2*np+1][0] = r2; bf[2*np+1][1] = r3;
            }
            #pragma unroll
            for (int mt = 0; mt < 4; mt++)
                #pragma unroll
                for (int nt = 0; nt < 4; nt++)
                    HMMA16816(acc[mt][nt], af[mt][0], af[mt][1], af[mt][2], af[mt][3], bf[nt][0], bf[nt][1]);
        }
    };

    const int nIter = K / 32;
    issueT(0, 0);
    issueT(32, 1);
    int stg = 0;
    for (int it = 0; it < nIter; it++) {
        if (it < nIter - 1) {
            asm volatile("cp.async.wait_group 1;");
        } else {
            asm volatile("cp.async.wait_group 0;");
        }
        __syncthreads();
        compute(stg);
        if (it + 2 < nIter) {
            int ns = stg + 2; if (ns >= 3) ns -= 3;
            issueT((it + 2) * 32, ns);
        }
        if (++stg == 3) stg = 0;
    }

    if (SPLIT) {
        float* Cz = (float*)Cv + (long long)(bz + zoff) * M * Nn;
        #pragma unroll
        for (int mt = 0; mt < 4; mt++) {
            int r0 = by * 128 + wm + mt * 16 + lr;
            int r1 = r0 + 8;
            #pragma unroll
            for (int nt = 0; nt < 4; nt++) {
                int col = bx * 128 + wn + nt * 8 + 2 * lc;
                if (r0 < M) *(float2*)&Cz[(long long)r0 * Nn + col] = make_float2(acc[mt][nt][0], acc[mt][nt][1]);
                if (r1 < M) *(float2*)&Cz[(long long)r1 * Nn + col] = make_float2(acc[mt][nt][2], acc[mt][nt][3]);
            }
        }
        return;
    }

    const float bninv = rsqrtf(1.0f + 1e-5f);
    const long long SZr = (long long)NGRAPH * 3328;
    #pragma unroll
    for (int mt = 0; mt < 4; mt++) {
        int r0 = by * 128 + wm + mt * 16 + lr;
        int r1 = r0 + 8;
        #pragma unroll
        for (int nt = 0; nt < 4; nt++) {
            int col = bx * 128 + wn + nt * 8 + 2 * lc;
            float b0 = __ldg(bias + col);
            float b1 = __ldg(bias + col + 1);
            float g0 = 1.f, g1 = 1.f, be0 = 0.f, be1 = 0.f;
            if (EPI >= 2) {
                g0 = __ldg(bng + col) * bninv;  g1 = __ldg(bng + col + 1) * bninv;
                be0 = __ldg(bnb + col);         be1 = __ldg(bnb + col + 1);
            }
            float v00 = acc[mt][nt][0], v01 = acc[mt][nt][1];
            float v10 = acc[mt][nt][2], v11 = acc[mt][nt][3];
            if (EPI == 3) {
                // add the 4 fp32 split-K slots (fixed order) before bias
                float2 s0 = make_float2(0.f, 0.f), s1 = make_float2(0.f, 0.f);
                #pragma unroll
                for (int z = 0; z < 4; z++) {
                    float2 t0 = *(const float2*)&red[z * SZr + (long long)r0 * Nn + col];
                    float2 t1 = *(const float2*)&red[z * SZr + (long long)r1 * Nn + col];
                    s0.x += t0.x; s0.y += t0.y;
                    s1.x += t1.x; s1.y += t1.y;
                }
                v00 += s0.x; v01 += s0.y;
                v10 += s1.x; v11 += s1.y;
            }
            v00 += b0; v01 += b1; v10 += b0; v11 += b1;
            if (EPI >= 2) {
                v00 = v00 * g0 + be0; v01 = v01 * g1 + be1;
                v10 = v10 * g0 + be0; v11 = v11 * g1 + be1;
            }
            if (EPI >= 1) {
                v00 = fmaxf(v00, 0.f); v01 = fmaxf(v01, 0.f);
                v10 = fmaxf(v10, 0.f); v11 = fmaxf(v11, 0.f);
            }
            if (CH) {
                __half* Ch = (__half*)Cv;
                if (r0 < M) *(__half2*)&Ch[(long long)r0 * Nn + col] = __floats2half2_rn(v00, v01);
                if (r1 < M) *(__half2*)&Ch[(long long)r1 * Nn + col] = __floats2half2_rn(v10, v11);
            } else {
                float* Cf = (float*)Cv;
                if (r0 < M) *(float2*)&Cf[(long long)r0 * Nn + col] = make_float2(v00, v01);
                if (r1 < M) *(float2*)&Cf[(long long)r1 * Nn + col] = make_float2(v10, v11);
            }
        }
    }
}

// ---------------------------------------------------------------------------
// FUSED conv MLP (unchanged)
// ---------------------------------------------------------------------------
template<int K1>
__global__ __launch_bounds__(256, 2) void hgemm_fused_kernel(
    int M,
    const __half* __restrict__ A, const __half* __restrict__ W1,
    const float* __restrict__ b1,
    const __half* __restrict__ W2, const float* __restrict__ b2,
    const float* __restrict__ bng, const float* __restrict__ bnb,
    __half* __restrict__ C)
{
    extern __shared__ __half dsm[];
    __half* AsBase = dsm;
    __half* BsBase = dsm + 3 * A_STG;
    __half* H1     = dsm + 3 * A_STG + 3 * B_STG;

    const int tid = threadIdx.x, by = blockIdx.y;
    const int warp = tid >> 5, lane = tid & 31;
    const int wm = (warp >> 2) * 64;
    const int wn = (warp & 3) * 32;
    const int lr = lane >> 2;
    const int lc = lane & 3;
    const int a_r = lane & 15, a_s = lane >> 4;
    const int b_k = lane & 7,  b_s = lane >> 3;

    auto issueA = [&](int kk, int stg, int ld) {
        __half* As = AsBase + stg * A_STG;
        #pragma unroll
        for (int q = 0; q < 2; q++) {
            int c = tid + q * 256;
            int row = c >> 2, kc = (c & 3) * 8;
            int gr = by * 128 + row;
            uint32_t sa = smem_u32(&As[row * SKA2 + kc]);
            cp16(sa, A + (long long)gr * ld + kk + kc, gr < M ? 16 : 0);
        }
    };
    auto issueB = [&](const __half* B, int kk, int stg) {
        __half* Bs = BsBase + stg * B_STG;
        #pragma unroll
        for (int q = 0; q < 2; q++) {
            int c = tid + q * 256;
            int row = c >> 4, nc = (c & 15) * 8;
            uint32_t sb = smem_u32(&Bs[row * SKB2 + nc]);
            cp16(sb, B + (long long)(kk + row) * 128 + nc, 16);
        }
    };

    float acc[4][4][4];
    #pragma unroll
    for (int i = 0; i < 4; i++)
        #pragma unroll
        for (int j = 0; j < 4; j++)
            #pragma unroll
            for (int t = 0; t < 4; t++) acc[i][j][t] = 0.0f;

    auto computeAB = [&](uint32_t aB, int aStride, uint32_t bB) {
        #pragma unroll
        for (int ks = 0; ks < 32; ks += 16) {
            uint32_t af[4][4], bf[4][2];
            #pragma unroll
            for (int mt = 0; mt < 4; mt++) {
                uint32_t addr = aB + (uint32_t)(((wm + mt * 16 + a_r) * aStride + ks + a_s * 8) * 2);
                LDMATRIX_X4(af[mt][0], af[mt][1], af[mt][2], af[mt][3], addr);
            }
            #pragma unroll
            for (int np = 0; np < 2; np++) {
                uint32_t addr = bB + (uint32_t)(((ks + (b_s & 1) * 8 + b_k) * SKB2 + wn + np * 16 + (b_s >> 1) * 8) * 2);
                uint32_t r0, r1, r2, r3;
                LDMATRIX_X4_T(r0, r1, r2, r3, addr);
                bf[2*np][0] = r0; bf[2*np][1] = r1;
                bf[2*np+1][0] = r2; bf[2*np+1][1] = r3;
            }
            #pragma unroll
            for (int mt = 0; mt < 4; mt++)
                #pragma unroll
                for (int nt = 0; nt < 4; nt++)
                    HMMA16816(acc[mt][nt], af[mt][0], af[mt][1], af[mt][2], af[mt][3], bf[nt][0], bf[nt][1]);
        }
    };

    {
        const int nIter = K1 / 32;
        issueA(0, 0, K1); issueB(W1, 0, 0); CP_COMMIT();
        issueA(32, 1, K1); issueB(W1, 32, 1); CP_COMMIT();
        int stg = 0;
        for (int it = 0; it < nIter; it++) {
            if (it < nIter - 1) asm volatile("cp.async.wait_group 1;");
            else                asm volatile("cp.async.wait_group 0;");
            __syncthreads();
            computeAB(smem_u32(AsBase + stg * A_STG), SKA2, smem_u32(BsBase + stg * B_STG));
            if (it + 2 < nIter) {
                int ns = stg + 2; if (ns >= 3) ns -= 3;
                issueA((it + 2) * 32, ns, K1); issueB(W1, (it + 2) * 32, ns); CP_COMMIT();
            }
            if (++stg == 3) stg = 0;
        }
    }
    __syncthreads();

    #pragma unroll
    for (int mt = 0; mt < 4; mt++) {
        int r0 = wm + mt * 16 + lr;
        int r1 = r0 + 8;
        #pragma unroll
        for (int nt = 0; nt < 4; nt++) {
            int col = wn + nt * 8 + 2 * lc;
            float bb0 = __ldg(b1 + col);
            float bb1 = __ldg(b1 + col + 1);
            float v00 = fmaxf(acc[mt][nt][0] + bb0, 0.f);
            float v01 = fmaxf(acc[mt][nt][1] + bb1, 0.f);
            float v10 = fmaxf(acc[mt][nt][2] + bb0, 0.f);
            float v11 = fmaxf(acc[mt][nt][3] + bb1, 0.f);
            *(__half2*)&H1[r0 * SKB2 + col] = __floats2half2_rn(v00, v01);
            *(__half2*)&H1[r1 * SKB2 + col] = __floats2half2_rn(v10, v11);
            acc[mt][nt][0] = 0.f; acc[mt][nt][1] = 0.f;
            acc[mt][nt][2] = 0.f; acc[mt][nt][3] = 0.f;
        }
    }
    __syncthreads();

    {
        issueB(W2, 0, 0); CP_COMMIT();
        issueB(W2, 32, 1); CP_COMMIT();
        const uint32_t h1B = smem_u32(H1);
        int stg = 0;
        for (int it = 0; it < 4; it++) {
            if (it < 3) asm volatile("cp.async.wait_group 1;");
            else        asm volatile("cp.async.wait_group 0;");
            __syncthreads();
            {
                const uint32_t aB = h1B + (uint32_t)(it * 32 * 2);
                computeAB(aB, SKB2, smem_u32(BsBase + stg * B_STG));
            }
            if (it + 2 < 4) {
                int ns = stg + 2; if (ns >= 3) ns -= 3;
                issueB(W2, (it + 2) * 32, ns); CP_COMMIT();
            }
            if (++stg == 3) stg = 0;
        }
    }

    const float bninv = rsqrtf(1.0f + 1e-5f);
    #pragma unroll
    for (int mt = 0; mt < 4; mt++) {
        int r0 = by * 128 + wm + mt * 16 + lr;
        int r1 = r0 + 8;
        #pragma unroll
        for (int nt = 0; nt < 4; nt++) {
            int col = wn + nt * 8 + 2 * lc;
            float bb0 = __ldg(b2 + col), bb1 = __ldg(b2 + col + 1);
            float g0 = __ldg(bng + col) * bninv, g1 = __ldg(bng + col + 1) * bninv;
            float be0 = __ldg(bnb + col), be1 = __ldg(bnb + col + 1);
            float v00 = fmaxf((acc[mt][nt][0] + bb0) * g0 + be0, 0.f);
            float v01 = fmaxf((acc[mt][nt][1] + bb1) * g1 + be1, 0.f);
            float v10 = fmaxf((acc[mt][nt][2] + bb0) * g0 + be0, 0.f);
            float v11 = fmaxf((acc[mt][nt][3] + bb1) * g1 + be1, 0.f);
            if (r0 < M) *(__half2*)&C[(long long)r0 * 128 + col] = __floats2half2_rn(v00, v01);
            if (r1 < M) *(__half2*)&C[(long long)r1 * 128 + col] = __floats2half2_rn(v10, v11);
        }
    }
}

// ---------------------------------------------------------------------------
extern "C" void kernel_launch(void* const* d_in, const int* in_sizes, int n_in,
                              void* d_out, int out_size) {
    const float* x     = (const float*)d_in[0];
    const int*   ei    = (const int*)  d_in[1];
    const int*   src   = ei;
    const int*   dst   = ei + NEDGES;
    const int*   batch = (const int*)  d_in[2];
    const float* fp    = (const float*)d_in[3];
    const float* c1w1 = (const float*)d_in[4],  *c1b1 = (const float*)d_in[5];
    const float* c1w2 = (const float*)d_in[6],  *c1b2 = (const float*)d_in[7];
    const float* c2w1 = (const float*)d_in[8],  *c2b1 = (const float*)d_in[9];
    const float* c2w2 = (const float*)d_in[10], *c2b2 = (const float*)d_in[11];
    const float* c3w1 = (const float*)d_in[12], *c3b1 = (const float*)d_in[13];
    const float* c3w2 = (const float*)d_in[14], *c3b2 = (const float*)d_in[15];
    const float* bn1g = (const float*)d_in[16], *bn1b = (const float*)d_in[17];
    const float* bn2g = (const float*)d_in[18], *bn2b = (const float*)d_in[19];
    const float* bn3g = (const float*)d_in[20], *bn3b = (const float*)d_in[21];
    const float* o1w  = (const float*)d_in[22], *o1b  = (const float*)d_in[23];
    const float* obng = (const float*)d_in[24], *obnb = (const float*)d_in[25];
    const float* o3w  = (const float*)d_in[26], *o3b  = (const float*)d_in[27];
    float* out = (float*)d_out;

    __half *xh, *aggrh, *tmph, *hh, *wh, *poolh;
    float *scr;
    int *deg, *cursor, *rowptr, *srclist, *gstart, *bsum;
    cudaGetSymbolAddress((void**)&xh,      g_xh);
    cudaGetSymbolAddress((void**)&aggrh,   g_aggrh);
    cudaGetSymbolAddress((void**)&tmph,    g_tmph);
    cudaGetSymbolAddress((void**)&hh,      g_hh);
    cudaGetSymbolAddress((void**)&wh,      g_wh);
    cudaGetSymbolAddress((void**)&poolh,   g_poolh);
    cudaGetSymbolAddress((void**)&scr,     g_scr);
    cudaGetSymbolAddress((void**)&deg,     g_deg);
    cudaGetSymbolAddress((void**)&cursor,  g_cursor);
    cudaGetSymbolAddress((void**)&rowptr,  g_rowptr);
    cudaGetSymbolAddress((void**)&srclist, g_srclist);
    cudaGetSymbolAddress((void**)&gstart,  g_gstart);
    cudaGetSymbolAddress((void**)&bsum,    g_bsum);

    cudaFuncSetAttribute(hgemm16_kernel<1,0,true>,  cudaFuncAttributeMaxDynamicSharedMemorySize, HG_SMEM);
    cudaFuncSetAttribute(hgemm16_kernel<2,0,true>,  cudaFuncAttributeMaxDynamicSharedMemorySize, HG_SMEM);
    cudaFuncSetAttribute(hgemm16_kernel<0,1,false>, cudaFuncAttributeMaxDynamicSharedMemorySize, HG_SMEM);
    cudaFuncSetAttribute(hgemm16_kernel<3,0,true>,  cudaFuncAttributeMaxDynamicSharedMemorySize, HG_SMEM);
    cudaFuncSetAttribute(hgemm_fused_kernel<64>,  cudaFuncAttributeMaxDynamicSharedMemorySize, FU_SMEM);
    cudaFuncSetAttribute(hgemm_fused_kernel<128>, cudaFuncAttributeMaxDynamicSharedMemorySize, FU_SMEM);

    const int T = 256;
    const int gy = (NNODES + 127) / 128;
    const long long SZ = (long long)NGRAPH * 3328;

    // ---- fork/join infrastructure ----
    cudaStream_t sB, sC, sP;
    cudaStreamCreateWithFlags(&sB, cudaStreamNonBlocking);
    cudaStreamCreateWithFlags(&sC, cudaStreamNonBlocking);
    cudaStreamCreateWithFlags(&sP, cudaStreamNonBlocking);
    cudaEvent_t evRoot, evB, evC, evH[3], evP[3];
    cudaEventCreateWithFlags(&evRoot, cudaEventDisableTiming);
    cudaEventCreateWithFlags(&evB,    cudaEventDisableTiming);
    cudaEventCreateWithFlags(&evC,    cudaEventDisableTiming);
    for (int i = 0; i < 3; i++) {
        cudaEventCreateWithFlags(&evH[i], cudaEventDisableTiming);
        cudaEventCreateWithFlags(&evP[i], cudaEventDisableTiming);
    }

    cudaEventRecord(evRoot, 0);
    cudaStreamWaitEvent(sB, evRoot, 0);
    cudaStreamWaitEvent(sC, evRoot, 0);

    // ---- sC: x convert + fingerprint + conv weights ----
    {
        f2h_kernel<<<(NNODES * 32 + T - 1) / T, T, 0, sC>>>((const float2*)x, (__half2*)xh, NNODES * 32);
        fp_copy_kernel<<<dim3((1536 + T - 1) / T, NGRAPH), T, 0, sC>>>((const float4*)fp, (uint2*)poolh);
        WConvArgs wc = {};
        wc.seg[0] = { (const float2*)c1w1, (__half2*)(wh + W_C1W1), 4096 };
        wc.seg[1] = { (const float2*)c1w2, (__half2*)(wh + W_C1W2), 8192 };
        wc.seg[2] = { (const float2*)c2w1, (__half2*)(wh + W_C2W1), 8192 };
        wc.seg[3] = { (const float2*)c2w2, (__half2*)(wh + W_C2W2), 8192 };
        wc.seg[4] = { (const float2*)c3w1, (__half2*)(wh + W_C3W1), 16384 };
        wc.seg[5] = { (const float2*)c3w2, (__half2*)(wh + W_C3W2), 32768 };
        wc.total = 4096 + 8192 + 8192 + 8192 + 16384 + 32768;
        wconv_kernel<<<256, T, 0, sC>>>(wc);
        cudaEventRecord(evC, sC);
    }
    // ---- sB: big weight converts, then fingerprint-part of readout GEMM1 ----
    {
        WConvArgs wb = {};
        wb.seg[0] = { (const float2*)o3w, (__half2*)(wh + W_O3W), 212992 };
        wb.seg[1] = { (const float2*)o1w, (__half2*)(wh + W_O1W), 11075584 };
        wb.total = 212992 + 11075584;
        wconv_kernel<<<2048, T, 0, sB>>>(wb);
        cudaStreamWaitEvent(sB, evC, 0);
        // GEMM1 part-B: K = 6144 (pool cols 512..6655), split-K 4 -> slots 0..3
        hgemm16_kernel<0,1,false><<<dim3(3328 / 128, 4, 4), T, HG_SMEM, sB>>>(
            NGRAPH, 3328, 1536, RDIM, 0, poolh + 512, wh + W_O1W + (long long)512 * 3328,
            nullptr, nullptr, nullptr, nullptr, scr);
        cudaEventRecord(evB, sB);
    }
    // ---- main: CSR build (multi-block scan) ----
    cudaMemsetAsync(deg, 0, NNODES * sizeof(int), 0);
    hist_kernel<<<(NEDGES / 4 + T - 1) / T, T>>>(dst, deg);
    bsum_kernel<<<NSCANB, 1024>>>(deg, bsum);
    boff_kernel<<<1, 1>>>(bsum, rowptr);
    rowptr_kernel<<<NSCANB, 1024>>>(deg, bsum, rowptr, cursor);
    fill_kernel<<<(NEDGES / 4 + T - 1) / T, T>>>(src, dst, cursor, srclist);
    gstart_kernel<<<3, 256>>>(batch, gstart);
    cudaStreamWaitEvent(0, evC, 0);

    // ---- conv1 (64 -> 128 -> 128), fused MLP ----
    gather_aggr_h_kernel<64><<<(NNODES * 8 + T - 1) / T, T>>>((const uint4*)xh, rowptr, srclist, (uint4*)aggrh);
    hgemm_fused_kernel<64><<<dim3(1, gy), T, FU_SMEM>>>(NNODES, aggrh, wh + W_C1W1, c1b1, wh + W_C1W2, c1b2, bn1g, bn1b, hh);
    cudaEventRecord(evH[0], 0);
    cudaStreamWaitEvent(sP, evH[0], 0);
    seg_pool_h_kernel<<<NGRAPH, 64, 0, sP>>>((const __half2*)hh, gstart, (__half2*)poolh, 64, 0);
    cudaEventRecord(evP[0], sP);

    // ---- conv2 (128 -> 128 -> 128), fused MLP ----
    gather_aggr_h_kernel<128><<<(NNODES * 16 + T - 1) / T, T>>>((const uint4*)hh, rowptr, srclist, (uint4*)aggrh);
    cudaStreamWaitEvent(0, evP[0], 0);
    hgemm_fused_kernel<128><<<dim3(1, gy), T, FU_SMEM>>>(NNODES, aggrh, wh + W_C2W1, c2b1, wh + W_C2W2, c2b2, bn2g, bn2b, hh);
    cudaEventRecord(evH[1], 0);
    cudaStreamWaitEvent(sP, evH[1], 0);
    seg_pool_h_kernel<<<NGRAPH, 64, 0, sP>>>((const __half2*)hh, gstart, (__half2*)poolh, 64, 64);
    cudaEventRecord(evP[1], sP);

    // ---- conv3 (128 -> 256 -> 256), unfused ----
    gather_aggr_h_kernel<128><<<(NNODES * 16 + T - 1) / T, T>>>((const uint4*)hh, rowptr, srclist, (uint4*)aggrh);
    hgemm16_kernel<1,0,true><<<dim3(2, gy), T, HG_SMEM>>>(NNODES, 256, 128, 128, 0, aggrh, wh + W_C3W1, c3b1, nullptr, nullptr, nullptr, tmph);
    cudaStreamWaitEvent(0, evP[1], 0);
    hgemm16_kernel<2,0,true><<<dim3(2, gy), T, HG_SMEM>>>(NNODES, 256, 256, 256, 0, tmph, wh + W_C3W2, c3b2, bn3g, bn3b, nullptr, hh);
    cudaEventRecord(evH[2], 0);
    cudaStreamWaitEvent(sP, evH[2], 0);
    seg_pool_h_kernel<<<NGRAPH, 128, 0, sP>>>((const __half2*)hh, gstart, (__half2*)poolh, 128, 128);
    cudaEventRecord(evP[2], sP);

    // ---- GEMM1 part-A (K=512) with FUSED 4-slot reduce + bias/bn/relu -> tmph fp16 ----
    cudaStreamWaitEvent(0, evP[2], 0);
    cudaStreamWaitEvent(0, evB, 0);
    hgemm16_kernel<3,0,true><<<dim3(3328 / 128, 4, 1), T, HG_SMEM>>>(
        NGRAPH, 3328, 512, RDIM, 0, poolh, wh + W_O1W, o1b, obng, obnb, scr, tmph);

    // ---- readout GEMM2: split-K=8 ----
    float* scr2 = scr + 5 * SZ;
    hgemm16_kernel<0,1,false><<<dim3(1, 4, 8), T, HG_SMEM>>>(NGRAPH, 128, 416, 3328, 0, tmph, wh + W_O3W, nullptr, nullptr, nullptr, nullptr, scr2);
    final_reduce_kernel<<<(NGRAPH * 128 + T - 1) / T, T>>>(scr2, o3b, out);

    // ---- cleanup ----
    cudaEventDestroy(evRoot); cudaEventDestroy(evB); cudaEventDestroy(evC);
    for (int i = 0; i < 3; i++) { cudaEventDestroy(evH[i]); cudaEventDestroy(evP[i]); }
    cudaStreamDestroy(sB); cudaStreamDestroy(sC); cudaStreamDestroy(sP);
}